// round 2
// baseline (speedup 1.0000x reference)
#include <cuda_runtime.h>
#include <cuda_bf16.h>

#define T_DIM 2048
#define C_DIM 1024
#define NHEAD 16
#define HSIZE 64
#define KSP   64

// Scratch (no allocations allowed)
__device__ float g_q[T_DIM * C_DIM];
__device__ float g_k[T_DIM * C_DIM];
__device__ float g_v[T_DIM * C_DIM];
__device__ float g_att[T_DIM * C_DIM];
__device__ float g_scores[T_DIM];
__device__ int   g_sorted[T_DIM];
__device__ int   g_topk[T_DIM * KSP];

// ---------------------------------------------------------------------------
// GEMM: out[M,N] = A[M,K] @ W[N,K]^T + bias[N]
// BM=BN=128, BK=16, 256 threads, 8x8 micro-tile
// ---------------------------------------------------------------------------
__global__ __launch_bounds__(256) void gemm_bias_kernel(
    const float* __restrict__ A, const float* __restrict__ W,
    const float* __restrict__ bias, float* __restrict__ out,
    int M, int N, int K)
{
    __shared__ float As[16][128];
    __shared__ float Bs[16][128];

    const int tid = threadIdx.x;
    const int tx = tid & 15;
    const int ty = tid >> 4;
    const int bm = blockIdx.y << 7;
    const int bn = blockIdx.x << 7;

    float acc[8][8];
#pragma unroll
    for (int i = 0; i < 8; i++)
#pragma unroll
        for (int j = 0; j < 8; j++) acc[i][j] = 0.f;

    const int row0 = tid >> 2;          // 0..63
    const int c4   = (tid & 3) << 2;    // 0,4,8,12

    for (int k0 = 0; k0 < K; k0 += 16) {
#pragma unroll
        for (int i = 0; i < 2; i++) {
            int row = row0 + i * 64;
            float4 a = *(const float4*)(A + (size_t)(bm + row) * K + k0 + c4);
            As[c4 + 0][row] = a.x; As[c4 + 1][row] = a.y;
            As[c4 + 2][row] = a.z; As[c4 + 3][row] = a.w;
            float4 b = *(const float4*)(W + (size_t)(bn + row) * K + k0 + c4);
            Bs[c4 + 0][row] = b.x; Bs[c4 + 1][row] = b.y;
            Bs[c4 + 2][row] = b.z; Bs[c4 + 3][row] = b.w;
        }
        __syncthreads();

#pragma unroll
        for (int kk = 0; kk < 16; kk++) {
            float4 a0 = *(const float4*)&As[kk][ty * 8];
            float4 a1 = *(const float4*)&As[kk][ty * 8 + 4];
            float4 b0 = *(const float4*)&Bs[kk][tx * 8];
            float4 b1 = *(const float4*)&Bs[kk][tx * 8 + 4];
            float av[8] = {a0.x, a0.y, a0.z, a0.w, a1.x, a1.y, a1.z, a1.w};
            float bv[8] = {b0.x, b0.y, b0.z, b0.w, b1.x, b1.y, b1.z, b1.w};
#pragma unroll
            for (int i = 0; i < 8; i++)
#pragma unroll
                for (int j = 0; j < 8; j++)
                    acc[i][j] += av[i] * bv[j];
        }
        __syncthreads();
    }

#pragma unroll
    for (int i = 0; i < 8; i++) {
        int r = bm + ty * 8 + i;
#pragma unroll
        for (int j = 0; j < 8; j += 4) {
            int c = bn + tx * 8 + j;
            float4 o;
            o.x = acc[i][j + 0] + bias[c + 0];
            o.y = acc[i][j + 1] + bias[c + 1];
            o.z = acc[i][j + 2] + bias[c + 2];
            o.w = acc[i][j + 3] + bias[c + 3];
            *(float4*)(out + (size_t)r * N + c) = o;
        }
    }
}

// ---------------------------------------------------------------------------
// key_scores[t] = x[t,:] . Wks + bks     (one warp per row)
// ---------------------------------------------------------------------------
__global__ void score_kernel(const float* __restrict__ x,
                             const float* __restrict__ Wks,
                             const float* __restrict__ bks)
{
    int t = (blockIdx.x << 2) + (threadIdx.x >> 5);
    int lane = threadIdx.x & 31;
    const float* xr = x + (size_t)t * C_DIM;
    float s = 0.f;
#pragma unroll 4
    for (int i = lane; i < C_DIM; i += 32) s += xr[i] * Wks[i];
#pragma unroll
    for (int o = 16; o; o >>= 1) s += __shfl_down_sync(0xffffffffu, s, o);
    if (lane == 0) g_scores[t] = s + bks[0];
}

// ---------------------------------------------------------------------------
// Bitonic sort of 2048 scores, descending, tie-break by ascending index
// (matches jax.lax.top_k ordering). Single block, 1024 threads.
// ---------------------------------------------------------------------------
__global__ __launch_bounds__(1024) void sort_kernel()
{
    __shared__ float sv[T_DIM];
    __shared__ int   si[T_DIM];
    int tid = threadIdx.x;
    for (int i = tid; i < T_DIM; i += 1024) { sv[i] = g_scores[i]; si[i] = i; }
    __syncthreads();

    for (int k = 2; k <= T_DIM; k <<= 1) {
        for (int j = k >> 1; j > 0; j >>= 1) {
            for (int i = tid; i < T_DIM; i += 1024) {
                int ixj = i ^ j;
                if (ixj > i) {
                    float v1 = sv[i], v2 = sv[ixj];
                    int   i1 = si[i], i2 = si[ixj];
                    // "i before ixj" in descending order?
                    bool ok = (v1 > v2) || (v1 == v2 && i1 < i2);
                    bool desc = ((i & k) == 0);
                    if (desc ? !ok : ok) {
                        sv[i] = v2; sv[ixj] = v1;
                        si[i] = i2; si[ixj] = i1;
                    }
                }
            }
            __syncthreads();
        }
    }
    for (int i = tid; i < T_DIM; i += 1024) g_sorted[i] = si[i];
}

// ---------------------------------------------------------------------------
// Per-query top-64 selection: one warp per query t.
// t < 64: exact reference multiset = {min(i,t)}.
// t >= 64: first 64 entries of the sorted order with index <= t.
// ---------------------------------------------------------------------------
__global__ void select_kernel()
{
    int t = (blockIdx.x << 2) + (threadIdx.x >> 5);
    int lane = threadIdx.x & 31;

    if (t < KSP) {
        g_topk[t * KSP + lane]      = min(lane, t);
        g_topk[t * KSP + 32 + lane] = min(32 + lane, t);
        return;
    }

    int count = 0, pos = 0;
    while (count < 64) {
        int p = pos + lane;
        int sidx = (p < T_DIM) ? g_sorted[p] : (1 << 30);
        bool f = (sidx <= t);
        unsigned m = __ballot_sync(0xffffffffu, f);
        int before = __popc(m & ((1u << lane) - 1));
        if (f && (count + before) < 64)
            g_topk[t * KSP + count + before] = sidx;
        count += __popc(m);
        pos += 32;
        if (pos >= T_DIM) break;  // safety (cannot trigger: t+1 >= 65 qualify)
    }
}

// ---------------------------------------------------------------------------
// Sparse attention: one block (128 thr) per (t, h).
// ---------------------------------------------------------------------------
__global__ __launch_bounds__(128) void attn_kernel()
{
    const int bid = blockIdx.x;
    const int h = bid & (NHEAD - 1);
    const int t = bid >> 4;
    const int tid = threadIdx.x;
    const int lane = tid & 31;
    const int w = tid >> 5;
    const int base = h * HSIZE;

    __shared__ float qs[HSIZE];
    __shared__ int   idxs[KSP];
    __shared__ float lg[KSP];
    __shared__ float part[2][HSIZE];

    if (tid < 64) {
        qs[tid]   = g_q[(size_t)t * C_DIM + base + tid];
        idxs[tid] = g_topk[t * KSP + tid];
    }
    __syncthreads();

    // logits: warp w computes j in [w*16, w*16+16)
#pragma unroll 1
    for (int j = w * 16; j < w * 16 + 16; j++) {
        int kidx = idxs[j];
        const float* kr = g_k + (size_t)kidx * C_DIM + base;
        float p = kr[lane] * qs[lane] + kr[lane + 32] * qs[lane + 32];
#pragma unroll
        for (int o = 16; o; o >>= 1) p += __shfl_down_sync(0xffffffffu, p, o);
        if (lane == 0) lg[j] = p * 0.125f;  // 1/sqrt(64)
    }
    __syncthreads();

    // softmax over 64 logits (warp 0)
    if (w == 0) {
        float a = lg[lane], b = lg[lane + 32];
        float m = fmaxf(a, b);
#pragma unroll
        for (int o = 16; o; o >>= 1) m = fmaxf(m, __shfl_xor_sync(0xffffffffu, m, o));
        float e0 = expf(a - m), e1 = expf(b - m);
        float s = e0 + e1;
#pragma unroll
        for (int o = 16; o; o >>= 1) s += __shfl_xor_sync(0xffffffffu, s, o);
        float inv = 1.f / s;
        lg[lane] = e0 * inv;
        lg[lane + 32] = e1 * inv;
    }
    __syncthreads();

    // P @ V: threads split into two halves over j; dim d = tid & 63
    const int half = tid >> 6;
    const int d = tid & 63;
    float acc = 0.f;
#pragma unroll 1
    for (int j = half * 32; j < half * 32 + 32; j++)
        acc += lg[j] * g_v[(size_t)idxs[j] * C_DIM + base + d];
    part[half][d] = acc;
    __syncthreads();

    if (tid < 64)
        g_att[(size_t)t * C_DIM + base + tid] = part[0][tid] + part[1][tid];
}

// ---------------------------------------------------------------------------
extern "C" void kernel_launch(void* const* d_in, const int* in_sizes, int n_in,
                              void* d_out, int out_size)
{
    const float* x   = (const float*)d_in[0];
    const float* Wq  = (const float*)d_in[1];
    const float* bq  = (const float*)d_in[2];
    const float* Wk  = (const float*)d_in[3];
    const float* bk  = (const float*)d_in[4];
    const float* Wv  = (const float*)d_in[5];
    const float* bv  = (const float*)d_in[6];
    const float* Wo  = (const float*)d_in[7];
    const float* bo  = (const float*)d_in[8];
    const float* Wks = (const float*)d_in[9];
    const float* bks = (const float*)d_in[10];
    float* out = (float*)d_out;

    float *q, *k, *v, *att;
    cudaGetSymbolAddress((void**)&q,   g_q);
    cudaGetSymbolAddress((void**)&k,   g_k);
    cudaGetSymbolAddress((void**)&v,   g_v);
    cudaGetSymbolAddress((void**)&att, g_att);

    dim3 gg(C_DIM / 128, T_DIM / 128);  // (8, 16)

    gemm_bias_kernel<<<gg, 256>>>(x, Wq, bq, q, T_DIM, C_DIM, C_DIM);
    gemm_bias_kernel<<<gg, 256>>>(x, Wk, bk, k, T_DIM, C_DIM, C_DIM);
    gemm_bias_kernel<<<gg, 256>>>(x, Wv, bv, v, T_DIM, C_DIM, C_DIM);

    score_kernel<<<T_DIM / 4, 128>>>(x, Wks, bks);
    sort_kernel<<<1, 1024>>>();
    select_kernel<<<T_DIM / 4, 128>>>();

    attn_kernel<<<T_DIM * NHEAD, 128>>>();

    gemm_bias_kernel<<<gg, 256>>>(att, Wo, bo, out, T_DIM, C_DIM, C_DIM);
}

// round 4
// speedup vs baseline: 1.9733x; 1.9733x over previous
#include <cuda_runtime.h>
#include <cuda_bf16.h>
#include <cstdint>

#define T_DIM 2048
#define C_DIM 1024
#define NHEAD 16
#define HSIZE 64
#define KSP   64

// ---------------- scratch (no allocations allowed) ----------------
__device__ float g_q[T_DIM * C_DIM];
__device__ float g_k[T_DIM * C_DIM];
__device__ float g_v[T_DIM * C_DIM];
__device__ float g_att[T_DIM * C_DIM];
__device__ float g_scores[T_DIM];
__device__ int   g_sorted[T_DIM];
__device__ int   g_topk[T_DIM * KSP];

// bf16 hi/lo splits
__device__ __nv_bfloat16 g_xh[T_DIM * C_DIM];
__device__ __nv_bfloat16 g_xl[T_DIM * C_DIM];
__device__ __nv_bfloat16 g_wqh[C_DIM * C_DIM];
__device__ __nv_bfloat16 g_wql[C_DIM * C_DIM];
__device__ __nv_bfloat16 g_wkh[C_DIM * C_DIM];
__device__ __nv_bfloat16 g_wkl[C_DIM * C_DIM];
__device__ __nv_bfloat16 g_wvh[C_DIM * C_DIM];
__device__ __nv_bfloat16 g_wvl[C_DIM * C_DIM];
__device__ __nv_bfloat16 g_woh[C_DIM * C_DIM];
__device__ __nv_bfloat16 g_wol[C_DIM * C_DIM];
__device__ __nv_bfloat16 g_ath[T_DIM * C_DIM];
__device__ __nv_bfloat16 g_atl[T_DIM * C_DIM];

// ---------------- helpers ----------------
__device__ __forceinline__ uint32_t smem_to_u32(const void* p) {
    uint32_t a;
    asm("{ .reg .u64 t; cvta.to.shared.u64 t, %1; cvt.u32.u64 %0, t; }" : "=r"(a) : "l"(p));
    return a;
}
#define SW128(off) ((off) ^ (((off) >> 3) & 0x70))

__device__ __forceinline__ void cp16(uint32_t dst, const void* src) {
    asm volatile("cp.async.cg.shared.global [%0], [%1], 16;" :: "r"(dst), "l"(src));
}
#define CP_COMMIT() asm volatile("cp.async.commit_group;" ::: "memory")
#define CP_WAIT(n)  asm volatile("cp.async.wait_group %0;" :: "n"(n) : "memory")

#define LDSM4(r, addr) \
    asm volatile("ldmatrix.sync.aligned.m8n8.x4.shared.b16 {%0,%1,%2,%3}, [%4];" \
        : "=r"((r)[0]), "=r"((r)[1]), "=r"((r)[2]), "=r"((r)[3]) : "r"(addr))

__device__ __forceinline__ void mma16816(float* d, const uint32_t* a, const uint32_t* b) {
    asm volatile("mma.sync.aligned.m16n8k16.row.col.f32.bf16.bf16.f32 "
        "{%0,%1,%2,%3}, {%4,%5,%6,%7}, {%8,%9}, {%0,%1,%2,%3};"
        : "+f"(d[0]), "+f"(d[1]), "+f"(d[2]), "+f"(d[3])
        : "r"(a[0]), "r"(a[1]), "r"(a[2]), "r"(a[3]), "r"(b[0]), "r"(b[1]));
}

// ---------------------------------------------------------------------------
// fp32 -> bf16 hi/lo split (vectorized by 4)
// ---------------------------------------------------------------------------
__device__ __forceinline__ uint32_t pack_bf2(float a, float b) {
    __nv_bfloat162 t = __floats2bfloat162_rn(a, b);
    return *reinterpret_cast<uint32_t*>(&t);
}
__global__ __launch_bounds__(256) void split_kernel(
    const float4* __restrict__ src, uint2* __restrict__ hi, uint2* __restrict__ lo, int n4)
{
    int i = blockIdx.x * 256 + threadIdx.x;
    if (i >= n4) return;
    float4 v = src[i];
    float h0 = __bfloat162float(__float2bfloat16_rn(v.x));
    float h1 = __bfloat162float(__float2bfloat16_rn(v.y));
    float h2 = __bfloat162float(__float2bfloat16_rn(v.z));
    float h3 = __bfloat162float(__float2bfloat16_rn(v.w));
    hi[i] = make_uint2(pack_bf2(h0, h1), pack_bf2(h2, h3));
    lo[i] = make_uint2(pack_bf2(v.x - h0, v.y - h1), pack_bf2(v.z - h2, v.w - h3));
}

// ---------------------------------------------------------------------------
// HMMA GEMM: out[2048,1024] = A @ W^T + bias, bf16x3 (Ah*Bh + Ah*Bl + Al*Bh)
// CTA tile 128x128, BK=64, 8 warps (4m x 2n), warp tile 32x64.
// SW128-swizzled SMEM, ldmatrix fragments, cp.async 2-stage pipeline.
// ---------------------------------------------------------------------------
#define NCHUNK  (C_DIM / 64)   // 16
#define TILE_B  16384          // 128 rows x 128 bytes
#define STAGE_B 65536          // 4 tiles: Ah, Al, Bh, Bl
#define RU      (C_DIM / 8)    // uint4 per row = 128

__global__ __launch_bounds__(256) void gemm_tc(
    const __nv_bfloat16* __restrict__ Ah, const __nv_bfloat16* __restrict__ Al,
    const __nv_bfloat16* __restrict__ Bh, const __nv_bfloat16* __restrict__ Bl,
    const float* __restrict__ bias, float* __restrict__ out)
{
    extern __shared__ char smem[];
    const uint32_t sb = smem_to_u32(smem);
    const int tid = threadIdx.x;
    const int wid = tid >> 5;
    const int lane = tid & 31;
    const int warp_m = wid & 3;   // 4 warps over M (32 rows each)
    const int warp_n = wid >> 2;  // 2 warps over N (64 cols each)
    const int bm = blockIdx.y << 7;
    const int bn = blockIdx.x << 7;

    float acc[2][8][4];
#pragma unroll
    for (int i = 0; i < 2; i++)
#pragma unroll
        for (int j = 0; j < 8; j++)
#pragma unroll
            for (int q = 0; q < 4; q++) acc[i][j][q] = 0.f;

    const uint4* srcs[4] = {
        reinterpret_cast<const uint4*>(Ah) + (size_t)bm * RU,
        reinterpret_cast<const uint4*>(Al) + (size_t)bm * RU,
        reinterpret_cast<const uint4*>(Bh) + (size_t)bn * RU,
        reinterpret_cast<const uint4*>(Bl) + (size_t)bn * RU };

    // per-thread load coords (16B x 16 per stage)
    const int lrow = tid >> 3;        // 0..31 (stepped by 32 over 4 passes)
    const int lch  = tid & 7;         // 16B chunk in row

    auto issue = [&](int s, int c) {
        const int kq = c * 8;
        const uint32_t sbase = sb + s * STAGE_B;
#pragma unroll
        for (int t4 = 0; t4 < 4; t4++) {
            const uint4* srow = srcs[t4] + kq;
            const uint32_t dbase = sbase + t4 * TILE_B;
#pragma unroll
            for (int p = 0; p < 4; p++) {
                int row = lrow + p * 32;
                cp16(dbase + SW128(row * 128 + lch * 16),
                     srow + (size_t)row * RU + lch);
            }
        }
        CP_COMMIT();
    };

    issue(0, 0);
    issue(1, 1);

    // fragment address components
    const int a_row  = warp_m * 32 + (lane & 15);
    const int a_koff = (lane >> 4) * 16;
    const int b_row  = warp_n * 64 + (lane & 7) + ((lane >> 4) & 1) * 8;
    const int b_koff = ((lane >> 3) & 1) * 16;

    for (int c = 0; c < NCHUNK; c++) {
        const int s = c & 1;
        if (c == NCHUNK - 1) { CP_WAIT(0); } else { CP_WAIT(1); }
        __syncthreads();

        const uint32_t aH = sb + s * STAGE_B;
        const uint32_t aL = aH + TILE_B;
        const uint32_t bH = aH + 2 * TILE_B;
        const uint32_t bL = aH + 3 * TILE_B;

#pragma unroll
        for (int ks = 0; ks < 4; ks++) {
            const int akb = ks * 32 + a_koff;
            const int bkb = ks * 32 + b_koff;
            uint32_t ah[2][4], al[2][4], bh[4][4], bl[4][4];
#pragma unroll
            for (int mi = 0; mi < 2; mi++) {
                int off = (a_row + mi * 16) * 128 + akb;
                LDSM4(ah[mi], aH + SW128(off));
                LDSM4(al[mi], aL + SW128(off));
            }
#pragma unroll
            for (int ni2 = 0; ni2 < 4; ni2++) {
                int off = (b_row + ni2 * 16) * 128 + bkb;
                LDSM4(bh[ni2], bH + SW128(off));
                LDSM4(bl[ni2], bL + SW128(off));
            }
#pragma unroll
            for (int mi = 0; mi < 2; mi++)
#pragma unroll
                for (int ni = 0; ni < 8; ni++) {
                    const uint32_t* ph = &bh[ni >> 1][(ni & 1) * 2];
                    const uint32_t* pl = &bl[ni >> 1][(ni & 1) * 2];
                    mma16816(acc[mi][ni], ah[mi], ph);
                    mma16816(acc[mi][ni], ah[mi], pl);
                    mma16816(acc[mi][ni], al[mi], ph);
                }
        }
        __syncthreads();
        if (c + 2 < NCHUNK) issue(s, c + 2);
    }

    // epilogue: d0,d1 -> (row g, col 2tg,+1); d2,d3 -> row g+8
    const int g  = lane >> 2;
    const int tg = lane & 3;
#pragma unroll
    for (int mi = 0; mi < 2; mi++) {
        const int row = bm + warp_m * 32 + mi * 16 + g;
#pragma unroll
        for (int ni = 0; ni < 8; ni++) {
            const int col = bn + warp_n * 64 + ni * 8 + tg * 2;
            float2 bb = *reinterpret_cast<const float2*>(bias + col);
            float2 o0 = { acc[mi][ni][0] + bb.x, acc[mi][ni][1] + bb.y };
            float2 o1 = { acc[mi][ni][2] + bb.x, acc[mi][ni][3] + bb.y };
            *reinterpret_cast<float2*>(out + (size_t)row * C_DIM + col) = o0;
            *reinterpret_cast<float2*>(out + (size_t)(row + 8) * C_DIM + col) = o1;
        }
    }
}

// ---------------------------------------------------------------------------
// key_scores[t] = x[t,:] . Wks + bks     (one warp per row)
// ---------------------------------------------------------------------------
__global__ void score_kernel(const float* __restrict__ x,
                             const float* __restrict__ Wks,
                             const float* __restrict__ bks)
{
    int t = (blockIdx.x << 2) + (threadIdx.x >> 5);
    int lane = threadIdx.x & 31;
    const float* xr = x + (size_t)t * C_DIM;
    float s = 0.f;
#pragma unroll 4
    for (int i = lane; i < C_DIM; i += 32) s += xr[i] * Wks[i];
#pragma unroll
    for (int o = 16; o; o >>= 1) s += __shfl_down_sync(0xffffffffu, s, o);
    if (lane == 0) g_scores[t] = s + bks[0];
}

// ---------------------------------------------------------------------------
// Bitonic sort of 2048 scores, descending, index-ascending tie-break
// ---------------------------------------------------------------------------
__global__ __launch_bounds__(1024) void sort_kernel()
{
    __shared__ float sv[T_DIM];
    __shared__ int   si[T_DIM];
    int tid = threadIdx.x;
    for (int i = tid; i < T_DIM; i += 1024) { sv[i] = g_scores[i]; si[i] = i; }
    __syncthreads();

    for (int k = 2; k <= T_DIM; k <<= 1) {
        for (int j = k >> 1; j > 0; j >>= 1) {
            for (int i = tid; i < T_DIM; i += 1024) {
                int ixj = i ^ j;
                if (ixj > i) {
                    float v1 = sv[i], v2 = sv[ixj];
                    int   i1 = si[i], i2 = si[ixj];
                    bool ok = (v1 > v2) || (v1 == v2 && i1 < i2);
                    bool desc = ((i & k) == 0);
                    if (desc ? !ok : ok) {
                        sv[i] = v2; sv[ixj] = v1;
                        si[i] = i2; si[ixj] = i1;
                    }
                }
            }
            __syncthreads();
        }
    }
    for (int i = tid; i < T_DIM; i += 1024) g_sorted[i] = si[i];
}

// ---------------------------------------------------------------------------
// Per-query top-64 selection (one warp per query)
// ---------------------------------------------------------------------------
__global__ void select_kernel()
{
    int t = (blockIdx.x << 2) + (threadIdx.x >> 5);
    int lane = threadIdx.x & 31;

    if (t < KSP) {
        g_topk[t * KSP + lane]      = min(lane, t);
        g_topk[t * KSP + 32 + lane] = min(32 + lane, t);
        return;
    }

    int count = 0, pos = 0;
    while (count < 64) {
        int p = pos + lane;
        int sidx = (p < T_DIM) ? g_sorted[p] : (1 << 30);
        bool f = (sidx <= t);
        unsigned m = __ballot_sync(0xffffffffu, f);
        int before = __popc(m & ((1u << lane) - 1));
        if (f && (count + before) < 64)
            g_topk[t * KSP + count + before] = sidx;
        count += __popc(m);
        pos += 32;
        if (pos >= T_DIM) break;
    }
}

// ---------------------------------------------------------------------------
// Sparse attention: one block (128 thr) per (t, h).
// ---------------------------------------------------------------------------
__global__ __launch_bounds__(128) void attn_kernel()
{
    const int bid = blockIdx.x;
    const int h = bid & (NHEAD - 1);
    const int t = bid >> 4;
    const int tid = threadIdx.x;
    const int lane = tid & 31;
    const int w = tid >> 5;
    const int base = h * HSIZE;

    __shared__ float qs[HSIZE];
    __shared__ int   idxs[KSP];
    __shared__ float lg[KSP];
    __shared__ float part[2][HSIZE];

    if (tid < 64) {
        qs[tid]   = g_q[(size_t)t * C_DIM + base + tid];
        idxs[tid] = g_topk[t * KSP + tid];
    }
    __syncthreads();

#pragma unroll 1
    for (int j = w * 16; j < w * 16 + 16; j++) {
        int kidx = idxs[j];
        const float* kr = g_k + (size_t)kidx * C_DIM + base;
        float p = kr[lane] * qs[lane] + kr[lane + 32] * qs[lane + 32];
#pragma unroll
        for (int o = 16; o; o >>= 1) p += __shfl_down_sync(0xffffffffu, p, o);
        if (lane == 0) lg[j] = p * 0.125f;
    }
    __syncthreads();

    if (w == 0) {
        float a = lg[lane], b = lg[lane + 32];
        float m = fmaxf(a, b);
#pragma unroll
        for (int o = 16; o; o >>= 1) m = fmaxf(m, __shfl_xor_sync(0xffffffffu, m, o));
        float e0 = expf(a - m), e1 = expf(b - m);
        float s = e0 + e1;
#pragma unroll
        for (int o = 16; o; o >>= 1) s += __shfl_xor_sync(0xffffffffu, s, o);
        float inv = 1.f / s;
        lg[lane] = e0 * inv;
        lg[lane + 32] = e1 * inv;
    }
    __syncthreads();

    const int half = tid >> 6;
    const int d = tid & 63;
    float acc = 0.f;
#pragma unroll 1
    for (int j = half * 32; j < half * 32 + 32; j++)
        acc += lg[j] * g_v[(size_t)idxs[j] * C_DIM + base + d];
    part[half][d] = acc;
    __syncthreads();

    if (tid < 64)
        g_att[(size_t)t * C_DIM + base + tid] = part[0][tid] + part[1][tid];
}

// ---------------------------------------------------------------------------
extern "C" void kernel_launch(void* const* d_in, const int* in_sizes, int n_in,
                              void* d_out, int out_size)
{
    const float* x   = (const float*)d_in[0];
    const float* Wq  = (const float*)d_in[1];
    const float* bq  = (const float*)d_in[2];
    const float* Wk  = (const float*)d_in[3];
    const float* bk  = (const float*)d_in[4];
    const float* Wv  = (const float*)d_in[5];
    const float* bv  = (const float*)d_in[6];
    const float* Wo  = (const float*)d_in[7];
    const float* bo  = (const float*)d_in[8];
    const float* Wks = (const float*)d_in[9];
    const float* bks = (const float*)d_in[10];
    float* out = (float*)d_out;

    float *q, *k, *v, *att;
    cudaGetSymbolAddress((void**)&q,   g_q);
    cudaGetSymbolAddress((void**)&k,   g_k);
    cudaGetSymbolAddress((void**)&v,   g_v);
    cudaGetSymbolAddress((void**)&att, g_att);

    __nv_bfloat16 *xh, *xl, *wqh, *wql, *wkh, *wkl, *wvh, *wvl, *woh, *wol, *ath, *atl;
    cudaGetSymbolAddress((void**)&xh,  g_xh);
    cudaGetSymbolAddress((void**)&xl,  g_xl);
    cudaGetSymbolAddress((void**)&wqh, g_wqh);
    cudaGetSymbolAddress((void**)&wql, g_wql);
    cudaGetSymbolAddress((void**)&wkh, g_wkh);
    cudaGetSymbolAddress((void**)&wkl, g_wkl);
    cudaGetSymbolAddress((void**)&wvh, g_wvh);
    cudaGetSymbolAddress((void**)&wvl, g_wvl);
    cudaGetSymbolAddress((void**)&woh, g_woh);
    cudaGetSymbolAddress((void**)&wol, g_wol);
    cudaGetSymbolAddress((void**)&ath, g_ath);
    cudaGetSymbolAddress((void**)&atl, g_atl);

    const int smem_sz = 2 * STAGE_B;  // 131072
    static bool attr_done = false;
    if (!attr_done) {
        cudaFuncSetAttribute(gemm_tc, cudaFuncAttributeMaxDynamicSharedMemorySize, smem_sz);
        attr_done = true;
    }

    const int nx4 = T_DIM * C_DIM / 4;   // 524288
    const int nw4 = C_DIM * C_DIM / 4;   // 262144

    split_kernel<<<nx4 / 256, 256>>>((const float4*)x,  (uint2*)xh,  (uint2*)xl,  nx4);
    split_kernel<<<nw4 / 256, 256>>>((const float4*)Wq, (uint2*)wqh, (uint2*)wql, nw4);
    split_kernel<<<nw4 / 256, 256>>>((const float4*)Wk, (uint2*)wkh, (uint2*)wkl, nw4);
    split_kernel<<<nw4 / 256, 256>>>((const float4*)Wv, (uint2*)wvh, (uint2*)wvl, nw4);
    split_kernel<<<nw4 / 256, 256>>>((const float4*)Wo, (uint2*)woh, (uint2*)wol, nw4);

    dim3 gg(C_DIM / 128, T_DIM / 128);  // (8, 16)
    gemm_tc<<<gg, 256, smem_sz>>>(xh, xl, wqh, wql, bq, q);
    gemm_tc<<<gg, 256, smem_sz>>>(xh, xl, wkh, wkl, bk, k);
    gemm_tc<<<gg, 256, smem_sz>>>(xh, xl, wvh, wvl, bv, v);

    score_kernel<<<T_DIM / 4, 128>>>(x, Wks, bks);
    sort_kernel<<<1, 1024>>>();
    select_kernel<<<T_DIM / 4, 128>>>();

    attn_kernel<<<T_DIM * NHEAD, 128>>>();

    split_kernel<<<nx4 / 256, 256>>>((const float4*)att, (uint2*)ath, (uint2*)atl, nx4);
    gemm_tc<<<gg, 256, smem_sz>>>(ath, atl, woh, wol, bo, out);
}

// round 5
// speedup vs baseline: 2.5350x; 1.2846x over previous
#include <cuda_runtime.h>
#include <cuda_bf16.h>
#include <cstdint>

#define T_DIM 2048
#define C_DIM 1024
#define NHEAD 16
#define HSIZE 64
#define KSP   64
#define GQ    16
#define UMAX  128
#define NGRP  ((T_DIM - KSP) / GQ)   // 124

// ---------------- scratch (no allocations allowed) ----------------
__device__ float g_q[T_DIM * C_DIM];
__device__ float g_k[T_DIM * C_DIM];
__device__ float g_v[T_DIM * C_DIM];
__device__ float g_scores[T_DIM];
__device__ int   g_sorted[T_DIM];
__device__ int   g_uidx[NGRP * UMAX];
__device__ int   g_ucnt[NGRP];

// bf16 hi/lo splits
__device__ __nv_bfloat16 g_xh[T_DIM * C_DIM];
__device__ __nv_bfloat16 g_xl[T_DIM * C_DIM];
__device__ __nv_bfloat16 g_wqh[C_DIM * C_DIM];
__device__ __nv_bfloat16 g_wql[C_DIM * C_DIM];
__device__ __nv_bfloat16 g_wkh[C_DIM * C_DIM];
__device__ __nv_bfloat16 g_wkl[C_DIM * C_DIM];
__device__ __nv_bfloat16 g_wvh[C_DIM * C_DIM];
__device__ __nv_bfloat16 g_wvl[C_DIM * C_DIM];
__device__ __nv_bfloat16 g_woh[C_DIM * C_DIM];
__device__ __nv_bfloat16 g_wol[C_DIM * C_DIM];
__device__ __nv_bfloat16 g_ath[T_DIM * C_DIM];
__device__ __nv_bfloat16 g_atl[T_DIM * C_DIM];

// ---------------- helpers ----------------
__device__ __forceinline__ uint32_t smem_to_u32(const void* p) {
    uint32_t a;
    asm("{ .reg .u64 t; cvta.to.shared.u64 t, %1; cvt.u32.u64 %0, t; }" : "=r"(a) : "l"(p));
    return a;
}
#define SW128(off) ((off) ^ (((off) >> 3) & 0x70))

__device__ __forceinline__ void cp16(uint32_t dst, const void* src) {
    asm volatile("cp.async.cg.shared.global [%0], [%1], 16;" :: "r"(dst), "l"(src));
}
#define CP_COMMIT() asm volatile("cp.async.commit_group;" ::: "memory")
#define CP_WAIT(n)  asm volatile("cp.async.wait_group %0;" :: "n"(n) : "memory")

#define LDSM4(r, addr) \
    asm volatile("ldmatrix.sync.aligned.m8n8.x4.shared.b16 {%0,%1,%2,%3}, [%4];" \
        : "=r"((r)[0]), "=r"((r)[1]), "=r"((r)[2]), "=r"((r)[3]) : "r"(addr))

__device__ __forceinline__ void mma16816(float* d, const uint32_t* a, const uint32_t* b) {
    asm volatile("mma.sync.aligned.m16n8k16.row.col.f32.bf16.bf16.f32 "
        "{%0,%1,%2,%3}, {%4,%5,%6,%7}, {%8,%9}, {%0,%1,%2,%3};"
        : "+f"(d[0]), "+f"(d[1]), "+f"(d[2]), "+f"(d[3])
        : "r"(a[0]), "r"(a[1]), "r"(a[2]), "r"(a[3]), "r"(b[0]), "r"(b[1]));
}

// ---------------------------------------------------------------------------
// fp32 -> bf16 hi/lo split
// ---------------------------------------------------------------------------
__device__ __forceinline__ uint32_t pack_bf2(float a, float b) {
    __nv_bfloat162 t = __floats2bfloat162_rn(a, b);
    return *reinterpret_cast<uint32_t*>(&t);
}
__global__ __launch_bounds__(256) void split_kernel(
    const float4* __restrict__ src, uint2* __restrict__ hi, uint2* __restrict__ lo, int n4)
{
    int i = blockIdx.x * 256 + threadIdx.x;
    if (i >= n4) return;
    float4 v = src[i];
    float h0 = __bfloat162float(__float2bfloat16_rn(v.x));
    float h1 = __bfloat162float(__float2bfloat16_rn(v.y));
    float h2 = __bfloat162float(__float2bfloat16_rn(v.z));
    float h3 = __bfloat162float(__float2bfloat16_rn(v.w));
    hi[i] = make_uint2(pack_bf2(h0, h1), pack_bf2(h2, h3));
    lo[i] = make_uint2(pack_bf2(v.x - h0, v.y - h1), pack_bf2(v.z - h2, v.w - h3));
}

// ---------------------------------------------------------------------------
// HMMA GEMM core (bf16x3): CTA tile 128x128, BK=64, 8 warps (4m x 2n).
// ---------------------------------------------------------------------------
#define NCHUNK  (C_DIM / 64)   // 16
#define TILE_B  16384          // 128 rows x 128 bytes
#define STAGE_B 65536          // 4 tiles: Ah, Al, Bh, Bl
#define RU      (C_DIM / 8)    // uint4 per row = 128

__device__ __forceinline__ void gemm_core(
    const __nv_bfloat16* Ah, const __nv_bfloat16* Al,
    const __nv_bfloat16* Bh, const __nv_bfloat16* Bl,
    const float* bias, float* out, int bm, int bn, char* smem)
{
    const uint32_t sb = smem_to_u32(smem);
    const int tid = threadIdx.x;
    const int wid = tid >> 5;
    const int lane = tid & 31;
    const int warp_m = wid & 3;
    const int warp_n = wid >> 2;

    float acc[2][8][4];
#pragma unroll
    for (int i = 0; i < 2; i++)
#pragma unroll
        for (int j = 0; j < 8; j++)
#pragma unroll
            for (int q = 0; q < 4; q++) acc[i][j][q] = 0.f;

    const uint4* srcs[4] = {
        reinterpret_cast<const uint4*>(Ah) + (size_t)bm * RU,
        reinterpret_cast<const uint4*>(Al) + (size_t)bm * RU,
        reinterpret_cast<const uint4*>(Bh) + (size_t)bn * RU,
        reinterpret_cast<const uint4*>(Bl) + (size_t)bn * RU };

    const int lrow = tid >> 3;
    const int lch  = tid & 7;

    auto issue = [&](int s, int c) {
        const int kq = c * 8;
        const uint32_t sbase = sb + s * STAGE_B;
#pragma unroll
        for (int t4 = 0; t4 < 4; t4++) {
            const uint4* srow = srcs[t4] + kq;
            const uint32_t dbase = sbase + t4 * TILE_B;
#pragma unroll
            for (int p = 0; p < 4; p++) {
                int row = lrow + p * 32;
                cp16(dbase + SW128(row * 128 + lch * 16),
                     srow + (size_t)row * RU + lch);
            }
        }
        CP_COMMIT();
    };

    issue(0, 0);
    issue(1, 1);

    const int a_row  = warp_m * 32 + (lane & 15);
    const int a_koff = (lane >> 4) * 16;
    const int b_row  = warp_n * 64 + (lane & 7) + ((lane >> 4) & 1) * 8;
    const int b_koff = ((lane >> 3) & 1) * 16;

    for (int c = 0; c < NCHUNK; c++) {
        const int s = c & 1;
        if (c == NCHUNK - 1) { CP_WAIT(0); } else { CP_WAIT(1); }
        __syncthreads();

        const uint32_t aH = sb + s * STAGE_B;
        const uint32_t aL = aH + TILE_B;
        const uint32_t bH = aH + 2 * TILE_B;
        const uint32_t bL = aH + 3 * TILE_B;

#pragma unroll
        for (int ks = 0; ks < 4; ks++) {
            const int akb = ks * 32 + a_koff;
            const int bkb = ks * 32 + b_koff;
            uint32_t ah[2][4], al[2][4], bh[4][4], bl[4][4];
#pragma unroll
            for (int mi = 0; mi < 2; mi++) {
                int off = (a_row + mi * 16) * 128 + akb;
                LDSM4(ah[mi], aH + SW128(off));
                LDSM4(al[mi], aL + SW128(off));
            }
#pragma unroll
            for (int ni2 = 0; ni2 < 4; ni2++) {
                int off = (b_row + ni2 * 16) * 128 + bkb;
                LDSM4(bh[ni2], bH + SW128(off));
                LDSM4(bl[ni2], bL + SW128(off));
            }
#pragma unroll
            for (int mi = 0; mi < 2; mi++)
#pragma unroll
                for (int ni = 0; ni < 8; ni++) {
                    const uint32_t* ph = &bh[ni >> 1][(ni & 1) * 2];
                    const uint32_t* pl = &bl[ni >> 1][(ni & 1) * 2];
                    mma16816(acc[mi][ni], ah[mi], ph);
                    mma16816(acc[mi][ni], ah[mi], pl);
                    mma16816(acc[mi][ni], al[mi], ph);
                }
        }
        __syncthreads();
        if (c + 2 < NCHUNK) issue(s, c + 2);
    }

    const int g  = lane >> 2;
    const int tg = lane & 3;
#pragma unroll
    for (int mi = 0; mi < 2; mi++) {
        const int row = bm + warp_m * 32 + mi * 16 + g;
#pragma unroll
        for (int ni = 0; ni < 8; ni++) {
            const int col = bn + warp_n * 64 + ni * 8 + tg * 2;
            float2 bb = *reinterpret_cast<const float2*>(bias + col);
            float2 o0 = { acc[mi][ni][0] + bb.x, acc[mi][ni][1] + bb.y };
            float2 o1 = { acc[mi][ni][2] + bb.x, acc[mi][ni][3] + bb.y };
            *reinterpret_cast<float2*>(out + (size_t)row * C_DIM + col) = o0;
            *reinterpret_cast<float2*>(out + (size_t)(row + 8) * C_DIM + col) = o1;
        }
    }
}

// Fused QKV: grid (24, 16); blockIdx.x selects (which, bn)
__global__ __launch_bounds__(256) void gemm_qkv(
    const __nv_bfloat16* Ah, const __nv_bfloat16* Al,
    const __nv_bfloat16* Bh0, const __nv_bfloat16* Bl0, const float* bias0, float* out0,
    const __nv_bfloat16* Bh1, const __nv_bfloat16* Bl1, const float* bias1, float* out1,
    const __nv_bfloat16* Bh2, const __nv_bfloat16* Bl2, const float* bias2, float* out2)
{
    extern __shared__ char smem[];
    const int nb = blockIdx.x;
    const int which = nb >> 3;
    const int bn = (nb & 7) << 7;
    const int bm = blockIdx.y << 7;
    const __nv_bfloat16* Bh = (which == 0) ? Bh0 : (which == 1) ? Bh1 : Bh2;
    const __nv_bfloat16* Bl = (which == 0) ? Bl0 : (which == 1) ? Bl1 : Bl2;
    const float* bias = (which == 0) ? bias0 : (which == 1) ? bias1 : bias2;
    float* out = (which == 0) ? out0 : (which == 1) ? out1 : out2;
    gemm_core(Ah, Al, Bh, Bl, bias, out, bm, bn, smem);
}

__global__ __launch_bounds__(256) void gemm_tc(
    const __nv_bfloat16* Ah, const __nv_bfloat16* Al,
    const __nv_bfloat16* Bh, const __nv_bfloat16* Bl,
    const float* bias, float* out)
{
    extern __shared__ char smem[];
    gemm_core(Ah, Al, Bh, Bl, bias, out, blockIdx.y << 7, blockIdx.x << 7, smem);
}

// ---------------------------------------------------------------------------
// key_scores[t] = x[t,:] . Wks + bks
// ---------------------------------------------------------------------------
__global__ void score_kernel(const float* __restrict__ x,
                             const float* __restrict__ Wks,
                             const float* __restrict__ bks)
{
    int t = (blockIdx.x << 2) + (threadIdx.x >> 5);
    int lane = threadIdx.x & 31;
    const float* xr = x + (size_t)t * C_DIM;
    float s = 0.f;
#pragma unroll 4
    for (int i = lane; i < C_DIM; i += 32) s += xr[i] * Wks[i];
#pragma unroll
    for (int o = 16; o; o >>= 1) s += __shfl_down_sync(0xffffffffu, s, o);
    if (lane == 0) g_scores[t] = s + bks[0];
}

// ---------------------------------------------------------------------------
// Bitonic sort, descending, index-ascending tie-break
// ---------------------------------------------------------------------------
__global__ __launch_bounds__(1024) void sort_kernel()
{
    __shared__ float sv[T_DIM];
    __shared__ int   si[T_DIM];
    int tid = threadIdx.x;
    for (int i = tid; i < T_DIM; i += 1024) { sv[i] = g_scores[i]; si[i] = i; }
    __syncthreads();

    for (int k = 2; k <= T_DIM; k <<= 1) {
        for (int j = k >> 1; j > 0; j >>= 1) {
            for (int i = tid; i < T_DIM; i += 1024) {
                int ixj = i ^ j;
                if (ixj > i) {
                    float v1 = sv[i], v2 = sv[ixj];
                    int   i1 = si[i], i2 = si[ixj];
                    bool ok = (v1 > v2) || (v1 == v2 && i1 < i2);
                    bool desc = ((i & k) == 0);
                    if (desc ? !ok : ok) {
                        sv[i] = v2; sv[ixj] = v1;
                        si[i] = i2; si[ixj] = i1;
                    }
                }
            }
            __syncthreads();
        }
    }
    for (int i = tid; i < T_DIM; i += 1024) g_sorted[i] = si[i];
}

// ---------------------------------------------------------------------------
// Per-group candidate union: one warp per group g; queries t in
// [64+g*GQ, 64+g*GQ+GQ). Walk sorted list, keep entries with idx <= t_max
// until t_min has 64 valid. Union size <= 110 < UMAX.
// ---------------------------------------------------------------------------
__global__ void prep_kernel()
{
    int g = blockIdx.x;
    int lane = threadIdx.x;
    int tmin = KSP + g * GQ;
    int tmax = tmin + GQ - 1;
    unsigned lt = (1u << lane) - 1;

    int cmin = 0, kept = 0;
    for (int base = 0; base < T_DIM && cmin < 64; base += 32) {
        int sidx = g_sorted[base + lane];
        bool vmax = (sidx <= tmax);
        unsigned m = __ballot_sync(0xffffffffu, vmax);
        int before = __popc(m & lt);
        if (vmax) g_uidx[g * UMAX + kept + before] = sidx;
        kept += __popc(m);
        cmin += __popc(__ballot_sync(0xffffffffu, sidx <= tmin));
    }
    if (lane == 0) g_ucnt[g] = kept;
}

// ---------------------------------------------------------------------------
// Grouped sparse attention: block = (group g, head h), 512 threads
// (16 warps, one per query). Union K/V rows staged in SMEM.
// Writes bf16 hi/lo of the attention output directly.
// ---------------------------------------------------------------------------
struct AttnSmem {
    float Kc[UMAX][65];   // padded for conflict-free row-gather
    float Vc[UMAX][64];
    float qs[GQ][64];
    float lg[GQ][64];
    int   uidx[UMAX];
    short sel[GQ][64];
    int   ucnt;
};

__global__ __launch_bounds__(512) void attn_group_kernel()
{
    extern __shared__ char sm_raw[];
    AttnSmem& S = *reinterpret_cast<AttnSmem*>(sm_raw);

    const int grp = blockIdx.x;
    const int h   = blockIdx.y;
    const int t0  = KSP + grp * GQ;
    const int base = h * HSIZE;
    const int tid = threadIdx.x;

    if (tid == 0) S.ucnt = g_ucnt[grp];
    if (tid < UMAX) S.uidx[tid] = g_uidx[grp * UMAX + tid];
    __syncthreads();
    const int ucnt = S.ucnt;

    // stage union rows: 16 threads per row, 32 rows per pass
    for (int r = tid >> 4; r < ucnt; r += 32) {
        int tok = S.uidx[r];
        int dc = (tid & 15) << 2;
        const float* kp = g_k + (size_t)tok * C_DIM + base + dc;
        const float* vp = g_v + (size_t)tok * C_DIM + base + dc;
        float4 kv = *reinterpret_cast<const float4*>(kp);
        S.Kc[r][dc + 0] = kv.x; S.Kc[r][dc + 1] = kv.y;
        S.Kc[r][dc + 2] = kv.z; S.Kc[r][dc + 3] = kv.w;
        *reinterpret_cast<float4*>(&S.Vc[r][dc]) = *reinterpret_cast<const float4*>(vp);
    }
    // stage queries
    for (int i = tid; i < GQ * 64; i += 512)
        S.qs[i >> 6][i & 63] = g_q[(size_t)(t0 + (i >> 6)) * C_DIM + base + (i & 63)];
    __syncthreads();

    const int w = tid >> 5;
    const int lane = tid & 31;
    const int t = t0 + w;
    const unsigned ltm = (1u << lane) - 1;

    // per-query: first 64 union entries with idx <= t
    int count = 0;
    for (int b2 = 0; b2 < ucnt && count < 64; b2 += 32) {
        int i = b2 + lane;
        bool f = (i < ucnt) && (S.uidx[i] <= t);
        unsigned m = __ballot_sync(0xffffffffu, f);
        int before = __popc(m & ltm);
        if (f && count + before < 64) S.sel[w][count + before] = (short)i;
        count += __popc(m);
    }
    __syncwarp();

    // logits (j = lane, lane+32)
    const int s0 = S.sel[w][lane];
    const int s1 = S.sel[w][lane + 32];
    float lo0 = 0.f, lo1 = 0.f;
#pragma unroll 8
    for (int d = 0; d < 64; d++) {
        float qq = S.qs[w][d];
        lo0 += qq * S.Kc[s0][d];
        lo1 += qq * S.Kc[s1][d];
    }
    lo0 *= 0.125f; lo1 *= 0.125f;

    float m = fmaxf(lo0, lo1);
#pragma unroll
    for (int o = 16; o; o >>= 1) m = fmaxf(m, __shfl_xor_sync(0xffffffffu, m, o));
    float e0 = expf(lo0 - m), e1 = expf(lo1 - m);
    float sum = e0 + e1;
#pragma unroll
    for (int o = 16; o; o >>= 1) sum += __shfl_xor_sync(0xffffffffu, sum, o);
    float inv = 1.f / sum;
    S.lg[w][lane] = e0 * inv;
    S.lg[w][lane + 32] = e1 * inv;
    __syncwarp();

    // PV (d = lane, lane+32)
    float a0 = 0.f, a1 = 0.f;
#pragma unroll 8
    for (int j = 0; j < 64; j++) {
        float p = S.lg[w][j];
        int s = S.sel[w][j];
        a0 += p * S.Vc[s][lane];
        a1 += p * S.Vc[s][lane + 32];
    }

    size_t off = (size_t)t * C_DIM + base;
    __nv_bfloat16 h0 = __float2bfloat16_rn(a0);
    __nv_bfloat16 h1 = __float2bfloat16_rn(a1);
    g_ath[off + lane]      = h0;
    g_ath[off + lane + 32] = h1;
    g_atl[off + lane]      = __float2bfloat16_rn(a0 - __bfloat162float(h0));
    g_atl[off + lane + 32] = __float2bfloat16_rn(a1 - __bfloat162float(h1));
}

// ---------------------------------------------------------------------------
// Small-t attention (t < 64): one block (128 thr) per (t, h).
// Candidate multiset = { min(j, t) : j in 0..63 } (matches reference).
// ---------------------------------------------------------------------------
__global__ __launch_bounds__(128) void attn_small_kernel()
{
    const int bid = blockIdx.x;
    const int h = bid & (NHEAD - 1);
    const int t = bid >> 4;
    const int tid = threadIdx.x;
    const int lane = tid & 31;
    const int w = tid >> 5;
    const int base = h * HSIZE;

    __shared__ float qs[HSIZE];
    __shared__ float lg[KSP];
    __shared__ float part[2][HSIZE];

    if (tid < 64) qs[tid] = g_q[(size_t)t * C_DIM + base + tid];
    __syncthreads();

#pragma unroll 1
    for (int j = w * 16; j < w * 16 + 16; j++) {
        int kidx = min(j, t);
        const float* kr = g_k + (size_t)kidx * C_DIM + base;
        float p = kr[lane] * qs[lane] + kr[lane + 32] * qs[lane + 32];
#pragma unroll
        for (int o = 16; o; o >>= 1) p += __shfl_down_sync(0xffffffffu, p, o);
        if (lane == 0) lg[j] = p * 0.125f;
    }
    __syncthreads();

    if (w == 0) {
        float a = lg[lane], b = lg[lane + 32];
        float m = fmaxf(a, b);
#pragma unroll
        for (int o = 16; o; o >>= 1) m = fmaxf(m, __shfl_xor_sync(0xffffffffu, m, o));
        float e0 = expf(a - m), e1 = expf(b - m);
        float s = e0 + e1;
#pragma unroll
        for (int o = 16; o; o >>= 1) s += __shfl_xor_sync(0xffffffffu, s, o);
        float inv = 1.f / s;
        lg[lane] = e0 * inv;
        lg[lane + 32] = e1 * inv;
    }
    __syncthreads();

    const int half = tid >> 6;
    const int d = tid & 63;
    float acc = 0.f;
#pragma unroll 1
    for (int j = half * 32; j < half * 32 + 32; j++)
        acc += lg[j] * g_v[(size_t)min(j, t) * C_DIM + base + d];
    part[half][d] = acc;
    __syncthreads();

    if (tid < 64) {
        float o = part[0][tid] + part[1][tid];
        __nv_bfloat16 hh = __float2bfloat16_rn(o);
        size_t off = (size_t)t * C_DIM + base + tid;
        g_ath[off] = hh;
        g_atl[off] = __float2bfloat16_rn(o - __bfloat162float(hh));
    }
}

// ---------------------------------------------------------------------------
extern "C" void kernel_launch(void* const* d_in, const int* in_sizes, int n_in,
                              void* d_out, int out_size)
{
    const float* x   = (const float*)d_in[0];
    const float* Wq  = (const float*)d_in[1];
    const float* bq  = (const float*)d_in[2];
    const float* Wk  = (const float*)d_in[3];
    const float* bk  = (const float*)d_in[4];
    const float* Wv  = (const float*)d_in[5];
    const float* bv  = (const float*)d_in[6];
    const float* Wo  = (const float*)d_in[7];
    const float* bo  = (const float*)d_in[8];
    const float* Wks = (const float*)d_in[9];
    const float* bks = (const float*)d_in[10];
    float* out = (float*)d_out;

    float *q, *k, *v;
    cudaGetSymbolAddress((void**)&q, g_q);
    cudaGetSymbolAddress((void**)&k, g_k);
    cudaGetSymbolAddress((void**)&v, g_v);

    __nv_bfloat16 *xh, *xl, *wqh, *wql, *wkh, *wkl, *wvh, *wvl, *woh, *wol, *ath, *atl;
    cudaGetSymbolAddress((void**)&xh,  g_xh);
    cudaGetSymbolAddress((void**)&xl,  g_xl);
    cudaGetSymbolAddress((void**)&wqh, g_wqh);
    cudaGetSymbolAddress((void**)&wql, g_wql);
    cudaGetSymbolAddress((void**)&wkh, g_wkh);
    cudaGetSymbolAddress((void**)&wkl, g_wkl);
    cudaGetSymbolAddress((void**)&wvh, g_wvh);
    cudaGetSymbolAddress((void**)&wvl, g_wvl);
    cudaGetSymbolAddress((void**)&woh, g_woh);
    cudaGetSymbolAddress((void**)&wol, g_wol);
    cudaGetSymbolAddress((void**)&ath, g_ath);
    cudaGetSymbolAddress((void**)&atl, g_atl);

    const int gemm_smem = 2 * STAGE_B;                 // 131072
    const int attn_smem = (int)sizeof(AttnSmem);       // ~77KB
    static bool attr_done = false;
    if (!attr_done) {
        cudaFuncSetAttribute(gemm_qkv, cudaFuncAttributeMaxDynamicSharedMemorySize, gemm_smem);
        cudaFuncSetAttribute(gemm_tc,  cudaFuncAttributeMaxDynamicSharedMemorySize, gemm_smem);
        cudaFuncSetAttribute(attn_group_kernel, cudaFuncAttributeMaxDynamicSharedMemorySize, attn_smem);
        attr_done = true;
    }

    const int nx4 = T_DIM * C_DIM / 4;
    const int nw4 = C_DIM * C_DIM / 4;

    split_kernel<<<nx4 / 256, 256>>>((const float4*)x,  (uint2*)xh,  (uint2*)xl,  nx4);
    split_kernel<<<nw4 / 256, 256>>>((const float4*)Wq, (uint2*)wqh, (uint2*)wql, nw4);
    split_kernel<<<nw4 / 256, 256>>>((const float4*)Wk, (uint2*)wkh, (uint2*)wkl, nw4);
    split_kernel<<<nw4 / 256, 256>>>((const float4*)Wv, (uint2*)wvh, (uint2*)wvl, nw4);
    split_kernel<<<nw4 / 256, 256>>>((const float4*)Wo, (uint2*)woh, (uint2*)wol, nw4);

    // fused QKV projection
    gemm_qkv<<<dim3(24, 16), 256, gemm_smem>>>(
        xh, xl,
        wqh, wql, bq, q,
        wkh, wkl, bk, k,
        wvh, wvl, bv, v);

    score_kernel<<<T_DIM / 4, 128>>>(x, Wks, bks);
    sort_kernel<<<1, 1024>>>();
    prep_kernel<<<NGRP, 32>>>();

    attn_small_kernel<<<KSP * NHEAD, 128>>>();
    attn_group_kernel<<<dim3(NGRP, NHEAD), 512, attn_smem>>>();

    gemm_tc<<<dim3(8, 16), 256, gemm_smem>>>(ath, atl, woh, wol, bo, out);
}

// round 6
// speedup vs baseline: 3.1184x; 1.2302x over previous
#include <cuda_runtime.h>
#include <cuda_fp16.h>
#include <cstdint>

#define T_DIM 2048
#define C_DIM 1024
#define NHEAD 16
#define HSIZE 64
#define KSP   64
#define GQ    16
#define UMAX  128
#define NGRP  ((T_DIM - KSP) / GQ)   // 124

// ---------------- scratch (no allocations allowed) ----------------
__device__ float g_q[T_DIM * C_DIM];
__device__ float g_k[T_DIM * C_DIM];
__device__ float g_v[T_DIM * C_DIM];
__device__ float g_scores[T_DIM];
__device__ int   g_sorted[T_DIM];
__device__ int   g_uidx[NGRP * UMAX];
__device__ int   g_ucnt[NGRP];

// fp16 operands
__device__ __half g_xq[T_DIM * C_DIM];      // x in fp16
__device__ __half g_wqh[C_DIM * C_DIM];
__device__ __half g_wql[C_DIM * C_DIM];
__device__ __half g_wkh[C_DIM * C_DIM];
__device__ __half g_wkl[C_DIM * C_DIM];
__device__ __half g_wvh[C_DIM * C_DIM];
__device__ __half g_wvl[C_DIM * C_DIM];
__device__ __half g_woh[C_DIM * C_DIM];
__device__ __half g_wol[C_DIM * C_DIM];
__device__ __half g_atq[T_DIM * C_DIM];     // attention output in fp16

// ---------------- helpers ----------------
__device__ __forceinline__ uint32_t smem_to_u32(const void* p) {
    uint32_t a;
    asm("{ .reg .u64 t; cvta.to.shared.u64 t, %1; cvt.u32.u64 %0, t; }" : "=r"(a) : "l"(p));
    return a;
}
#define SW128(off) ((off) ^ (((off) >> 3) & 0x70))

__device__ __forceinline__ void cp16(uint32_t dst, const void* src) {
    asm volatile("cp.async.cg.shared.global [%0], [%1], 16;" :: "r"(dst), "l"(src));
}
#define CP_COMMIT() asm volatile("cp.async.commit_group;" ::: "memory")
#define CP_WAIT(n)  asm volatile("cp.async.wait_group %0;" :: "n"(n) : "memory")

#define LDSM4(r, addr) \
    asm volatile("ldmatrix.sync.aligned.m8n8.x4.shared.b16 {%0,%1,%2,%3}, [%4];" \
        : "=r"((r)[0]), "=r"((r)[1]), "=r"((r)[2]), "=r"((r)[3]) : "r"(addr))

__device__ __forceinline__ void mma16816(float* d, const uint32_t* a, const uint32_t* b) {
    asm volatile("mma.sync.aligned.m16n8k16.row.col.f32.f16.f16.f32 "
        "{%0,%1,%2,%3}, {%4,%5,%6,%7}, {%8,%9}, {%0,%1,%2,%3};"
        : "+f"(d[0]), "+f"(d[1]), "+f"(d[2]), "+f"(d[3])
        : "r"(a[0]), "r"(a[1]), "r"(a[2]), "r"(a[3]), "r"(b[0]), "r"(b[1]));
}

// ---------------------------------------------------------------------------
// Fused: x -> fp16 convert + key_scores = x . Wks + bks.
// One block per row (grid 2048, 256 thr; thread t covers cols [4t, 4t+4)).
// ---------------------------------------------------------------------------
__global__ __launch_bounds__(256) void splitx_score_kernel(
    const float4* __restrict__ x4, uint2* __restrict__ xq,
    const float4* __restrict__ wks4, const float* __restrict__ bks)
{
    const int tid = threadIdx.x;
    const int i = blockIdx.x * 256 + tid;
    float4 v = x4[i];
    __half2 p0 = __floats2half2_rn(v.x, v.y);
    __half2 p1 = __floats2half2_rn(v.z, v.w);
    xq[i] = make_uint2(*reinterpret_cast<uint32_t*>(&p0), *reinterpret_cast<uint32_t*>(&p1));

    float4 wk = wks4[tid];
    float s = v.x * wk.x + v.y * wk.y + v.z * wk.z + v.w * wk.w;
#pragma unroll
    for (int o = 16; o; o >>= 1) s += __shfl_down_sync(0xffffffffu, s, o);
    __shared__ float red[8];
    if ((tid & 31) == 0) red[tid >> 5] = s;
    __syncthreads();
    if (tid == 0) {
        float tot = 0.f;
#pragma unroll
        for (int j = 0; j < 8; j++) tot += red[j];
        g_scores[blockIdx.x] = tot + bks[0];
    }
}

// ---------------------------------------------------------------------------
// Weight fp32 -> fp16 hi/lo split
// ---------------------------------------------------------------------------
__global__ __launch_bounds__(256) void splitw_kernel(
    const float4* __restrict__ src, uint2* __restrict__ hi, uint2* __restrict__ lo, int n4)
{
    int i = blockIdx.x * 256 + threadIdx.x;
    if (i >= n4) return;
    float4 v = src[i];
    __half h0 = __float2half_rn(v.x);
    __half h1 = __float2half_rn(v.y);
    __half h2 = __float2half_rn(v.z);
    __half h3 = __float2half_rn(v.w);
    __half2 a = __halves2half2(h0, h1), b = __halves2half2(h2, h3);
    hi[i] = make_uint2(*reinterpret_cast<uint32_t*>(&a), *reinterpret_cast<uint32_t*>(&b));
    __half l0 = __float2half_rn(v.x - __half2float(h0));
    __half l1 = __float2half_rn(v.y - __half2float(h1));
    __half l2 = __float2half_rn(v.z - __half2float(h2));
    __half l3 = __float2half_rn(v.w - __half2float(h3));
    __half2 c = __halves2half2(l0, l1), d = __halves2half2(l2, l3);
    lo[i] = make_uint2(*reinterpret_cast<uint32_t*>(&c), *reinterpret_cast<uint32_t*>(&d));
}

// ---------------------------------------------------------------------------
// HMMA GEMM core, fp16 2-product: D = Ax*(Bh + Bl).
// CTA tile 128x128, BK=64, 8 warps (4m x 2n), 3-stage cp.async pipeline.
// ---------------------------------------------------------------------------
#define NCHUNK  (C_DIM / 64)   // 16
#define TILE_B  16384          // 128 rows x 128 bytes
#define STAGE_B 49152          // 3 tiles: Ax, Bh, Bl
#define NSTAGE  3
#define RU      (C_DIM / 8)    // uint4 per row = 128

__device__ __forceinline__ void gemm_core(
    const __half* Ax, const __half* Bh, const __half* Bl,
    const float* bias, float* out, int bm, int bn, char* smem)
{
    const uint32_t sb = smem_to_u32(smem);
    const int tid = threadIdx.x;
    const int wid = tid >> 5;
    const int lane = tid & 31;
    const int warp_m = wid & 3;
    const int warp_n = wid >> 2;

    float acc[2][8][4];
#pragma unroll
    for (int i = 0; i < 2; i++)
#pragma unroll
        for (int j = 0; j < 8; j++)
#pragma unroll
            for (int q = 0; q < 4; q++) acc[i][j][q] = 0.f;

    const uint4* srcs[3] = {
        reinterpret_cast<const uint4*>(Ax) + (size_t)bm * RU,
        reinterpret_cast<const uint4*>(Bh) + (size_t)bn * RU,
        reinterpret_cast<const uint4*>(Bl) + (size_t)bn * RU };

    const int lrow = tid >> 3;
    const int lch  = tid & 7;

    auto issue = [&](int s, int c) {
        const int kq = c * 8;
        const uint32_t sbase = sb + s * STAGE_B;
#pragma unroll
        for (int t3 = 0; t3 < 3; t3++) {
            const uint4* srow = srcs[t3] + kq;
            const uint32_t dbase = sbase + t3 * TILE_B;
#pragma unroll
            for (int p = 0; p < 4; p++) {
                int row = lrow + p * 32;
                cp16(dbase + SW128(row * 128 + lch * 16),
                     srow + (size_t)row * RU + lch);
            }
        }
        CP_COMMIT();
    };

    issue(0, 0);
    issue(1, 1);
    issue(2, 2);

    const int a_row  = warp_m * 32 + (lane & 15);
    const int a_koff = (lane >> 4) * 16;
    const int b_row  = warp_n * 64 + (lane & 7) + ((lane >> 4) & 1) * 8;
    const int b_koff = ((lane >> 3) & 1) * 16;

    for (int c = 0; c < NCHUNK; c++) {
        const int s = c % NSTAGE;
        if (c >= NCHUNK - 1)      { CP_WAIT(0); }
        else if (c == NCHUNK - 2) { CP_WAIT(1); }
        else                      { CP_WAIT(2); }
        __syncthreads();

        const uint32_t aX = sb + s * STAGE_B;
        const uint32_t bH = aX + TILE_B;
        const uint32_t bL = aX + 2 * TILE_B;

#pragma unroll
        for (int ks = 0; ks < 4; ks++) {
            const int akb = ks * 32 + a_koff;
            const int bkb = ks * 32 + b_koff;
            uint32_t ax[2][4], bh[4][4], bl[4][4];
#pragma unroll
            for (int mi = 0; mi < 2; mi++) {
                int off = (a_row + mi * 16) * 128 + akb;
                LDSM4(ax[mi], aX + SW128(off));
            }
#pragma unroll
            for (int ni2 = 0; ni2 < 4; ni2++) {
                int off = (b_row + ni2 * 16) * 128 + bkb;
                LDSM4(bh[ni2], bH + SW128(off));
                LDSM4(bl[ni2], bL + SW128(off));
            }
#pragma unroll
            for (int mi = 0; mi < 2; mi++)
#pragma unroll
                for (int ni = 0; ni < 8; ni++) {
                    const uint32_t* ph = &bh[ni >> 1][(ni & 1) * 2];
                    const uint32_t* pl = &bl[ni >> 1][(ni & 1) * 2];
                    mma16816(acc[mi][ni], ax[mi], ph);
                    mma16816(acc[mi][ni], ax[mi], pl);
                }
        }
        __syncthreads();
        if (c + NSTAGE < NCHUNK) issue(s, c + NSTAGE);
    }

    const int g  = lane >> 2;
    const int tg = lane & 3;
#pragma unroll
    for (int mi = 0; mi < 2; mi++) {
        const int row = bm + warp_m * 32 + mi * 16 + g;
#pragma unroll
        for (int ni = 0; ni < 8; ni++) {
            const int col = bn + warp_n * 64 + ni * 8 + tg * 2;
            float2 bb = *reinterpret_cast<const float2*>(bias + col);
            float2 o0 = { acc[mi][ni][0] + bb.x, acc[mi][ni][1] + bb.y };
            float2 o1 = { acc[mi][ni][2] + bb.x, acc[mi][ni][3] + bb.y };
            *reinterpret_cast<float2*>(out + (size_t)row * C_DIM + col) = o0;
            *reinterpret_cast<float2*>(out + (size_t)(row + 8) * C_DIM + col) = o1;
        }
    }
}

// Fused QKV: grid (24, 16); blockIdx.x selects (which, bn)
__global__ __launch_bounds__(256) void gemm_qkv(
    const __half* Ax,
    const __half* Bh0, const __half* Bl0, const float* bias0, float* out0,
    const __half* Bh1, const __half* Bl1, const float* bias1, float* out1,
    const __half* Bh2, const __half* Bl2, const float* bias2, float* out2)
{
    extern __shared__ char smem[];
    const int nb = blockIdx.x;
    const int which = nb >> 3;
    const int bn = (nb & 7) << 7;
    const int bm = blockIdx.y << 7;
    const __half* Bh = (which == 0) ? Bh0 : (which == 1) ? Bh1 : Bh2;
    const __half* Bl = (which == 0) ? Bl0 : (which == 1) ? Bl1 : Bl2;
    const float* bias = (which == 0) ? bias0 : (which == 1) ? bias1 : bias2;
    float* out = (which == 0) ? out0 : (which == 1) ? out1 : out2;
    gemm_core(Ax, Bh, Bl, bias, out, bm, bn, smem);
}

__global__ __launch_bounds__(256) void gemm_tc(
    const __half* Ax, const __half* Bh, const __half* Bl,
    const float* bias, float* out)
{
    extern __shared__ char smem[];
    gemm_core(Ax, Bh, Bl, bias, out, blockIdx.y << 7, blockIdx.x << 7, smem);
}

// ---------------------------------------------------------------------------
// Bitonic sort, descending, index-ascending tie-break
// ---------------------------------------------------------------------------
__global__ __launch_bounds__(1024) void sort_kernel()
{
    __shared__ float sv[T_DIM];
    __shared__ int   si[T_DIM];
    int tid = threadIdx.x;
    for (int i = tid; i < T_DIM; i += 1024) { sv[i] = g_scores[i]; si[i] = i; }
    __syncthreads();

    for (int k = 2; k <= T_DIM; k <<= 1) {
        for (int j = k >> 1; j > 0; j >>= 1) {
            for (int i = tid; i < T_DIM; i += 1024) {
                int ixj = i ^ j;
                if (ixj > i) {
                    float v1 = sv[i], v2 = sv[ixj];
                    int   i1 = si[i], i2 = si[ixj];
                    bool ok = (v1 > v2) || (v1 == v2 && i1 < i2);
                    bool desc = ((i & k) == 0);
                    if (desc ? !ok : ok) {
                        sv[i] = v2; sv[ixj] = v1;
                        si[i] = i2; si[ixj] = i1;
                    }
                }
            }
            __syncthreads();
        }
    }
    for (int i = tid; i < T_DIM; i += 1024) g_sorted[i] = si[i];
}

// ---------------------------------------------------------------------------
// Per-group candidate union (one warp per group)
// ---------------------------------------------------------------------------
__global__ void prep_kernel()
{
    int g = blockIdx.x;
    int lane = threadIdx.x;
    int tmin = KSP + g * GQ;
    int tmax = tmin + GQ - 1;
    unsigned lt = (1u << lane) - 1;

    int cmin = 0, kept = 0;
    for (int base = 0; base < T_DIM && cmin < 64; base += 32) {
        int sidx = g_sorted[base + lane];
        bool vmax = (sidx <= tmax);
        unsigned m = __ballot_sync(0xffffffffu, vmax);
        int before = __popc(m & lt);
        if (vmax) g_uidx[g * UMAX + kept + before] = sidx;
        kept += __popc(m);
        cmin += __popc(__ballot_sync(0xffffffffu, sidx <= tmin));
    }
    if (lane == 0) g_ucnt[g] = kept;
}

// ---------------------------------------------------------------------------
// Grouped sparse attention (writes fp16 att directly)
// ---------------------------------------------------------------------------
struct AttnSmem {
    float Kc[UMAX][65];
    float Vc[UMAX][64];
    float qs[GQ][64];
    float lg[GQ][64];
    int   uidx[UMAX];
    short sel[GQ][64];
    int   ucnt;
};

__global__ __launch_bounds__(512) void attn_group_kernel()
{
    extern __shared__ char sm_raw[];
    AttnSmem& S = *reinterpret_cast<AttnSmem*>(sm_raw);

    const int grp = blockIdx.x;
    const int h   = blockIdx.y;
    const int t0  = KSP + grp * GQ;
    const int base = h * HSIZE;
    const int tid = threadIdx.x;

    if (tid == 0) S.ucnt = g_ucnt[grp];
    if (tid < UMAX) S.uidx[tid] = g_uidx[grp * UMAX + tid];
    __syncthreads();
    const int ucnt = S.ucnt;

    for (int r = tid >> 4; r < ucnt; r += 32) {
        int tok = S.uidx[r];
        int dc = (tid & 15) << 2;
        const float* kp = g_k + (size_t)tok * C_DIM + base + dc;
        const float* vp = g_v + (size_t)tok * C_DIM + base + dc;
        float4 kv = *reinterpret_cast<const float4*>(kp);
        S.Kc[r][dc + 0] = kv.x; S.Kc[r][dc + 1] = kv.y;
        S.Kc[r][dc + 2] = kv.z; S.Kc[r][dc + 3] = kv.w;
        *reinterpret_cast<float4*>(&S.Vc[r][dc]) = *reinterpret_cast<const float4*>(vp);
    }
    for (int i = tid; i < GQ * 64; i += 512)
        S.qs[i >> 6][i & 63] = g_q[(size_t)(t0 + (i >> 6)) * C_DIM + base + (i & 63)];
    __syncthreads();

    const int w = tid >> 5;
    const int lane = tid & 31;
    const int t = t0 + w;
    const unsigned ltm = (1u << lane) - 1;

    int count = 0;
    for (int b2 = 0; b2 < ucnt && count < 64; b2 += 32) {
        int i = b2 + lane;
        bool f = (i < ucnt) && (S.uidx[i] <= t);
        unsigned m = __ballot_sync(0xffffffffu, f);
        int before = __popc(m & ltm);
        if (f && count + before < 64) S.sel[w][count + before] = (short)i;
        count += __popc(m);
    }
    __syncwarp();

    const int s0 = S.sel[w][lane];
    const int s1 = S.sel[w][lane + 32];
    float lo0 = 0.f, lo1 = 0.f;
#pragma unroll 8
    for (int d = 0; d < 64; d++) {
        float qq = S.qs[w][d];
        lo0 += qq * S.Kc[s0][d];
        lo1 += qq * S.Kc[s1][d];
    }
    lo0 *= 0.125f; lo1 *= 0.125f;

    float m = fmaxf(lo0, lo1);
#pragma unroll
    for (int o = 16; o; o >>= 1) m = fmaxf(m, __shfl_xor_sync(0xffffffffu, m, o));
    float e0 = expf(lo0 - m), e1 = expf(lo1 - m);
    float sum = e0 + e1;
#pragma unroll
    for (int o = 16; o; o >>= 1) sum += __shfl_xor_sync(0xffffffffu, sum, o);
    float inv = 1.f / sum;
    S.lg[w][lane] = e0 * inv;
    S.lg[w][lane + 32] = e1 * inv;
    __syncwarp();

    float a0 = 0.f, a1 = 0.f;
#pragma unroll 8
    for (int j = 0; j < 64; j++) {
        float p = S.lg[w][j];
        int s = S.sel[w][j];
        a0 += p * S.Vc[s][lane];
        a1 += p * S.Vc[s][lane + 32];
    }

    size_t off = (size_t)t * C_DIM + base;
    g_atq[off + lane]      = __float2half_rn(a0);
    g_atq[off + lane + 32] = __float2half_rn(a1);
}

// ---------------------------------------------------------------------------
// Small-t attention (t < 64)
// ---------------------------------------------------------------------------
__global__ __launch_bounds__(128) void attn_small_kernel()
{
    const int bid = blockIdx.x;
    const int h = bid & (NHEAD - 1);
    const int t = bid >> 4;
    const int tid = threadIdx.x;
    const int lane = tid & 31;
    const int w = tid >> 5;
    const int base = h * HSIZE;

    __shared__ float qs[HSIZE];
    __shared__ float lg[KSP];
    __shared__ float part[2][HSIZE];

    if (tid < 64) qs[tid] = g_q[(size_t)t * C_DIM + base + tid];
    __syncthreads();

#pragma unroll 1
    for (int j = w * 16; j < w * 16 + 16; j++) {
        int kidx = min(j, t);
        const float* kr = g_k + (size_t)kidx * C_DIM + base;
        float p = kr[lane] * qs[lane] + kr[lane + 32] * qs[lane + 32];
#pragma unroll
        for (int o = 16; o; o >>= 1) p += __shfl_down_sync(0xffffffffu, p, o);
        if (lane == 0) lg[j] = p * 0.125f;
    }
    __syncthreads();

    if (w == 0) {
        float a = lg[lane], b = lg[lane + 32];
        float m = fmaxf(a, b);
#pragma unroll
        for (int o = 16; o; o >>= 1) m = fmaxf(m, __shfl_xor_sync(0xffffffffu, m, o));
        float e0 = expf(a - m), e1 = expf(b - m);
        float s = e0 + e1;
#pragma unroll
        for (int o = 16; o; o >>= 1) s += __shfl_xor_sync(0xffffffffu, s, o);
        float inv = 1.f / s;
        lg[lane] = e0 * inv;
        lg[lane + 32] = e1 * inv;
    }
    __syncthreads();

    const int half = tid >> 6;
    const int d = tid & 63;
    float acc = 0.f;
#pragma unroll 1
    for (int j = half * 32; j < half * 32 + 32; j++)
        acc += lg[j] * g_v[(size_t)min(j, t) * C_DIM + base + d];
    part[half][d] = acc;
    __syncthreads();

    if (tid < 64)
        g_atq[(size_t)t * C_DIM + base + tid] =
            __float2half_rn(part[0][tid] + part[1][tid]);
}

// ---------------------------------------------------------------------------
extern "C" void kernel_launch(void* const* d_in, const int* in_sizes, int n_in,
                              void* d_out, int out_size)
{
    const float* x   = (const float*)d_in[0];
    const float* Wq  = (const float*)d_in[1];
    const float* bq  = (const float*)d_in[2];
    const float* Wk  = (const float*)d_in[3];
    const float* bk  = (const float*)d_in[4];
    const float* Wv  = (const float*)d_in[5];
    const float* bv  = (const float*)d_in[6];
    const float* Wo  = (const float*)d_in[7];
    const float* bo  = (const float*)d_in[8];
    const float* Wks = (const float*)d_in[9];
    const float* bks = (const float*)d_in[10];
    float* out = (float*)d_out;

    float *q, *k, *v;
    cudaGetSymbolAddress((void**)&q, g_q);
    cudaGetSymbolAddress((void**)&k, g_k);
    cudaGetSymbolAddress((void**)&v, g_v);

    __half *xq, *wqh, *wql, *wkh, *wkl, *wvh, *wvl, *woh, *wol, *atq;
    cudaGetSymbolAddress((void**)&xq,  g_xq);
    cudaGetSymbolAddress((void**)&wqh, g_wqh);
    cudaGetSymbolAddress((void**)&wql, g_wql);
    cudaGetSymbolAddress((void**)&wkh, g_wkh);
    cudaGetSymbolAddress((void**)&wkl, g_wkl);
    cudaGetSymbolAddress((void**)&wvh, g_wvh);
    cudaGetSymbolAddress((void**)&wvl, g_wvl);
    cudaGetSymbolAddress((void**)&woh, g_woh);
    cudaGetSymbolAddress((void**)&wol, g_wol);
    cudaGetSymbolAddress((void**)&atq, g_atq);

    const int gemm_smem = NSTAGE * STAGE_B;            // 147456
    const int attn_smem = (int)sizeof(AttnSmem);
    static bool attr_done = false;
    if (!attr_done) {
        cudaFuncSetAttribute(gemm_qkv, cudaFuncAttributeMaxDynamicSharedMemorySize, gemm_smem);
        cudaFuncSetAttribute(gemm_tc,  cudaFuncAttributeMaxDynamicSharedMemorySize, gemm_smem);
        cudaFuncSetAttribute(attn_group_kernel, cudaFuncAttributeMaxDynamicSharedMemorySize, attn_smem);
        attr_done = true;
    }

    const int nw4 = C_DIM * C_DIM / 4;

    // x convert + key scores (one block per row)
    splitx_score_kernel<<<T_DIM, 256>>>((const float4*)x, (uint2*)xq,
                                        (const float4*)Wks, bks);
    splitw_kernel<<<nw4 / 256, 256>>>((const float4*)Wq, (uint2*)wqh, (uint2*)wql, nw4);
    splitw_kernel<<<nw4 / 256, 256>>>((const float4*)Wk, (uint2*)wkh, (uint2*)wkl, nw4);
    splitw_kernel<<<nw4 / 256, 256>>>((const float4*)Wv, (uint2*)wvh, (uint2*)wvl, nw4);
    splitw_kernel<<<nw4 / 256, 256>>>((const float4*)Wo, (uint2*)woh, (uint2*)wol, nw4);

    gemm_qkv<<<dim3(24, 16), 256, gemm_smem>>>(
        xq,
        wqh, wql, bq, q,
        wkh, wkl, bk, k,
        wvh, wvl, bv, v);

    sort_kernel<<<1, 1024>>>();
    prep_kernel<<<NGRP, 32>>>();

    attn_small_kernel<<<KSP * NHEAD, 128>>>();
    attn_group_kernel<<<dim3(NGRP, NHEAD), 512, attn_smem>>>();

    gemm_tc<<<dim3(8, 16), 256, gemm_smem>>>(atq, woh, wol, bo, out);
}

// round 7
// speedup vs baseline: 3.9332x; 1.2613x over previous
#include <cuda_runtime.h>
#include <cuda_fp16.h>
#include <cstdint>

#define T_DIM 2048
#define C_DIM 1024
#define NHEAD 16
#define HSIZE 64
#define KSP   64
#define GQ    16
#define UMAX  128
#define NGRP  ((T_DIM - KSP) / GQ)   // 124

// ---------------- scratch (no allocations allowed) ----------------
__device__ float g_q[T_DIM * C_DIM];
__device__ float g_k[T_DIM * C_DIM];
__device__ float g_v[T_DIM * C_DIM];
__device__ float g_scores[T_DIM];
__device__ int   g_sorted[T_DIM];
__device__ int   g_uidx[NGRP * UMAX];
__device__ int   g_ucnt[NGRP];

// fp16 operands
__device__ __half g_xq[T_DIM * C_DIM];      // x in fp16
__device__ __half g_wq[C_DIM * C_DIM];
__device__ __half g_wk[C_DIM * C_DIM];
__device__ __half g_wv[C_DIM * C_DIM];
__device__ __half g_wo[C_DIM * C_DIM];
__device__ __half g_atq[T_DIM * C_DIM];     // attention output in fp16

// ---------------- helpers ----------------
__device__ __forceinline__ uint32_t smem_to_u32(const void* p) {
    uint32_t a;
    asm("{ .reg .u64 t; cvta.to.shared.u64 t, %1; cvt.u32.u64 %0, t; }" : "=r"(a) : "l"(p));
    return a;
}
#define SW128(off) ((off) ^ (((off) >> 3) & 0x70))

__device__ __forceinline__ void cp16(uint32_t dst, const void* src) {
    asm volatile("cp.async.cg.shared.global [%0], [%1], 16;" :: "r"(dst), "l"(src));
}
#define CP_COMMIT() asm volatile("cp.async.commit_group;" ::: "memory")
#define CP_WAIT(n)  asm volatile("cp.async.wait_group %0;" :: "n"(n) : "memory")

#define LDSM4(r, addr) \
    asm volatile("ldmatrix.sync.aligned.m8n8.x4.shared.b16 {%0,%1,%2,%3}, [%4];" \
        : "=r"((r)[0]), "=r"((r)[1]), "=r"((r)[2]), "=r"((r)[3]) : "r"(addr))

__device__ __forceinline__ void mma16816(float* d, const uint32_t* a, const uint32_t* b) {
    asm volatile("mma.sync.aligned.m16n8k16.row.col.f32.f16.f16.f32 "
        "{%0,%1,%2,%3}, {%4,%5,%6,%7}, {%8,%9}, {%0,%1,%2,%3};"
        : "+f"(d[0]), "+f"(d[1]), "+f"(d[2]), "+f"(d[3])
        : "r"(a[0]), "r"(a[1]), "r"(a[2]), "r"(a[3]), "r"(b[0]), "r"(b[1]));
}

// ---------------------------------------------------------------------------
// Fused: x -> fp16 convert + key_scores = x . Wks + bks.
// One block per row (grid 2048, 256 thr; thread t covers cols [4t, 4t+4)).
// ---------------------------------------------------------------------------
__global__ __launch_bounds__(256) void splitx_score_kernel(
    const float4* __restrict__ x4, uint2* __restrict__ xq,
    const float4* __restrict__ wks4, const float* __restrict__ bks)
{
    const int tid = threadIdx.x;
    const int i = blockIdx.x * 256 + tid;
    float4 v = x4[i];
    __half2 p0 = __floats2half2_rn(v.x, v.y);
    __half2 p1 = __floats2half2_rn(v.z, v.w);
    xq[i] = make_uint2(*reinterpret_cast<uint32_t*>(&p0), *reinterpret_cast<uint32_t*>(&p1));

    float4 wk = wks4[tid];
    float s = v.x * wk.x + v.y * wk.y + v.z * wk.z + v.w * wk.w;
#pragma unroll
    for (int o = 16; o; o >>= 1) s += __shfl_down_sync(0xffffffffu, s, o);
    __shared__ float red[8];
    if ((tid & 31) == 0) red[tid >> 5] = s;
    __syncthreads();
    if (tid == 0) {
        float tot = 0.f;
#pragma unroll
        for (int j = 0; j < 8; j++) tot += red[j];
        g_scores[blockIdx.x] = tot + bks[0];
    }
}

// ---------------------------------------------------------------------------
// All-4-weights fp32 -> fp16 convert in one launch.
// grid.x = 4 * 1024 blocks; block 1024*w .. covers weight w.
// ---------------------------------------------------------------------------
#define NW4 (C_DIM * C_DIM / 4)   // 262144 float4 per weight

__global__ __launch_bounds__(256) void convw_kernel(
    const float4* __restrict__ w0, uint2* __restrict__ d0,
    const float4* __restrict__ w1, uint2* __restrict__ d1,
    const float4* __restrict__ w2, uint2* __restrict__ d2,
    const float4* __restrict__ w3, uint2* __restrict__ d3)
{
    const int nblk = NW4 / 256;   // 1024
    int which = blockIdx.x / nblk;
    int i = (blockIdx.x % nblk) * 256 + threadIdx.x;
    const float4* src = (which == 0) ? w0 : (which == 1) ? w1 : (which == 2) ? w2 : w3;
    uint2* dst = (which == 0) ? d0 : (which == 1) ? d1 : (which == 2) ? d2 : d3;
    float4 v = src[i];
    __half2 a = __floats2half2_rn(v.x, v.y);
    __half2 b = __floats2half2_rn(v.z, v.w);
    dst[i] = make_uint2(*reinterpret_cast<uint32_t*>(&a), *reinterpret_cast<uint32_t*>(&b));
}

// ---------------------------------------------------------------------------
// HMMA GEMM core, single fp16 product: D = Ax*B + bias.
// CTA tile 128x128, BK=64, 8 warps (4m x 2n), 4-stage cp.async pipeline.
// ---------------------------------------------------------------------------
#define NCHUNK  (C_DIM / 64)   // 16
#define TILE_B  16384          // 128 rows x 128 bytes
#define STAGE_B 32768          // 2 tiles: Ax, B
#define NSTAGE  4
#define RU      (C_DIM / 8)    // uint4 per row = 128

__device__ __forceinline__ void gemm_core(
    const __half* Ax, const __half* B,
    const float* bias, float* out, int bm, int bn, char* smem)
{
    const uint32_t sb = smem_to_u32(smem);
    const int tid = threadIdx.x;
    const int wid = tid >> 5;
    const int lane = tid & 31;
    const int warp_m = wid & 3;
    const int warp_n = wid >> 2;

    float acc[2][8][4];
#pragma unroll
    for (int i = 0; i < 2; i++)
#pragma unroll
        for (int j = 0; j < 8; j++)
#pragma unroll
            for (int q = 0; q < 4; q++) acc[i][j][q] = 0.f;

    const uint4* srcs[2] = {
        reinterpret_cast<const uint4*>(Ax) + (size_t)bm * RU,
        reinterpret_cast<const uint4*>(B)  + (size_t)bn * RU };

    const int lrow = tid >> 3;
    const int lch  = tid & 7;

    auto issue = [&](int s, int c) {
        const int kq = c * 8;
        const uint32_t sbase = sb + s * STAGE_B;
#pragma unroll
        for (int t2 = 0; t2 < 2; t2++) {
            const uint4* srow = srcs[t2] + kq;
            const uint32_t dbase = sbase + t2 * TILE_B;
#pragma unroll
            for (int p = 0; p < 4; p++) {
                int row = lrow + p * 32;
                cp16(dbase + SW128(row * 128 + lch * 16),
                     srow + (size_t)row * RU + lch);
            }
        }
        CP_COMMIT();
    };

    issue(0, 0);
    issue(1, 1);
    issue(2, 2);

    const int a_row  = warp_m * 32 + (lane & 15);
    const int a_koff = (lane >> 4) * 16;
    const int b_row  = warp_n * 64 + (lane & 7) + ((lane >> 4) & 1) * 8;
    const int b_koff = ((lane >> 3) & 1) * 16;

    for (int c = 0; c < NCHUNK; c++) {
        const int s = c % NSTAGE;
        if (c >= NCHUNK - 1)      { CP_WAIT(0); }
        else if (c == NCHUNK - 2) { CP_WAIT(1); }
        else                      { CP_WAIT(2); }
        __syncthreads();

        const uint32_t aX = sb + s * STAGE_B;
        const uint32_t bB = aX + TILE_B;

#pragma unroll
        for (int ks = 0; ks < 4; ks++) {
            const int akb = ks * 32 + a_koff;
            const int bkb = ks * 32 + b_koff;
            uint32_t ax[2][4], bb[4][4];
#pragma unroll
            for (int mi = 0; mi < 2; mi++) {
                int off = (a_row + mi * 16) * 128 + akb;
                LDSM4(ax[mi], aX + SW128(off));
            }
#pragma unroll
            for (int ni2 = 0; ni2 < 4; ni2++) {
                int off = (b_row + ni2 * 16) * 128 + bkb;
                LDSM4(bb[ni2], bB + SW128(off));
            }
#pragma unroll
            for (int mi = 0; mi < 2; mi++)
#pragma unroll
                for (int ni = 0; ni < 8; ni++)
                    mma16816(acc[mi][ni], ax[mi], &bb[ni >> 1][(ni & 1) * 2]);
        }
        __syncthreads();
        if (c + NSTAGE - 1 < NCHUNK) issue((c + NSTAGE - 1) % NSTAGE, c + NSTAGE - 1);
    }

    const int g  = lane >> 2;
    const int tg = lane & 3;
#pragma unroll
    for (int mi = 0; mi < 2; mi++) {
        const int row = bm + warp_m * 32 + mi * 16 + g;
#pragma unroll
        for (int ni = 0; ni < 8; ni++) {
            const int col = bn + warp_n * 64 + ni * 8 + tg * 2;
            float2 bv = *reinterpret_cast<const float2*>(bias + col);
            float2 o0 = { acc[mi][ni][0] + bv.x, acc[mi][ni][1] + bv.y };
            float2 o1 = { acc[mi][ni][2] + bv.x, acc[mi][ni][3] + bv.y };
            *reinterpret_cast<float2*>(out + (size_t)row * C_DIM + col) = o0;
            *reinterpret_cast<float2*>(out + (size_t)(row + 8) * C_DIM + col) = o1;
        }
    }
}

// Fused QKV: grid (24, 16); blockIdx.x selects (which, bn)
__global__ __launch_bounds__(256) void gemm_qkv(
    const __half* Ax,
    const __half* B0, const float* bias0, float* out0,
    const __half* B1, const float* bias1, float* out1,
    const __half* B2, const float* bias2, float* out2)
{
    extern __shared__ char smem[];
    const int nb = blockIdx.x;
    const int which = nb >> 3;
    const int bn = (nb & 7) << 7;
    const int bm = blockIdx.y << 7;
    const __half* B = (which == 0) ? B0 : (which == 1) ? B1 : B2;
    const float* bias = (which == 0) ? bias0 : (which == 1) ? bias1 : bias2;
    float* out = (which == 0) ? out0 : (which == 1) ? out1 : out2;
    gemm_core(Ax, B, bias, out, bm, bn, smem);
}

__global__ __launch_bounds__(256) void gemm_tc(
    const __half* Ax, const __half* B, const float* bias, float* out)
{
    extern __shared__ char smem[];
    gemm_core(Ax, B, bias, out, blockIdx.y << 7, blockIdx.x << 7, smem);
}

// ---------------------------------------------------------------------------
// Bitonic sort, descending, index-ascending tie-break
// ---------------------------------------------------------------------------
__global__ __launch_bounds__(1024) void sort_kernel()
{
    __shared__ float sv[T_DIM];
    __shared__ int   si[T_DIM];
    int tid = threadIdx.x;
    for (int i = tid; i < T_DIM; i += 1024) { sv[i] = g_scores[i]; si[i] = i; }
    __syncthreads();

    for (int k = 2; k <= T_DIM; k <<= 1) {
        for (int j = k >> 1; j > 0; j >>= 1) {
            for (int i = tid; i < T_DIM; i += 1024) {
                int ixj = i ^ j;
                if (ixj > i) {
                    float v1 = sv[i], v2 = sv[ixj];
                    int   i1 = si[i], i2 = si[ixj];
                    bool ok = (v1 > v2) || (v1 == v2 && i1 < i2);
                    bool desc = ((i & k) == 0);
                    if (desc ? !ok : ok) {
                        sv[i] = v2; sv[ixj] = v1;
                        si[i] = i2; si[ixj] = i1;
                    }
                }
            }
            __syncthreads();
        }
    }
    for (int i = tid; i < T_DIM; i += 1024) g_sorted[i] = si[i];
}

// ---------------------------------------------------------------------------
// Per-group candidate union (one warp per group)
// ---------------------------------------------------------------------------
__global__ void prep_kernel()
{
    int g = blockIdx.x;
    int lane = threadIdx.x;
    int tmin = KSP + g * GQ;
    int tmax = tmin + GQ - 1;
    unsigned lt = (1u << lane) - 1;

    int cmin = 0, kept = 0;
    for (int base = 0; base < T_DIM && cmin < 64; base += 32) {
        int sidx = g_sorted[base + lane];
        bool vmax = (sidx <= tmax);
        unsigned m = __ballot_sync(0xffffffffu, vmax);
        int before = __popc(m & lt);
        if (vmax) g_uidx[g * UMAX + kept + before] = sidx;
        kept += __popc(m);
        cmin += __popc(__ballot_sync(0xffffffffu, sidx <= tmin));
    }
    if (lane == 0) g_ucnt[g] = kept;
}

// ---------------------------------------------------------------------------
// Grouped sparse attention (writes fp16 att directly)
// ---------------------------------------------------------------------------
struct AttnSmem {
    float Kc[UMAX][65];
    float Vc[UMAX][64];
    float qs[GQ][64];
    float lg[GQ][64];
    int   uidx[UMAX];
    short sel[GQ][64];
    int   ucnt;
};

__global__ __launch_bounds__(512) void attn_group_kernel()
{
    extern __shared__ char sm_raw[];
    AttnSmem& S = *reinterpret_cast<AttnSmem*>(sm_raw);

    const int grp = blockIdx.x;
    const int h   = blockIdx.y;
    const int t0  = KSP + grp * GQ;
    const int base = h * HSIZE;
    const int tid = threadIdx.x;

    if (tid == 0) S.ucnt = g_ucnt[grp];
    if (tid < UMAX) S.uidx[tid] = g_uidx[grp * UMAX + tid];
    __syncthreads();
    const int ucnt = S.ucnt;

    for (int r = tid >> 4; r < ucnt; r += 32) {
        int tok = S.uidx[r];
        int dc = (tid & 15) << 2;
        const float* kp = g_k + (size_t)tok * C_DIM + base + dc;
        const float* vp = g_v + (size_t)tok * C_DIM + base + dc;
        float4 kv = *reinterpret_cast<const float4*>(kp);
        S.Kc[r][dc + 0] = kv.x; S.Kc[r][dc + 1] = kv.y;
        S.Kc[r][dc + 2] = kv.z; S.Kc[r][dc + 3] = kv.w;
        *reinterpret_cast<float4*>(&S.Vc[r][dc]) = *reinterpret_cast<const float4*>(vp);
    }
    for (int i = tid; i < GQ * 64; i += 512)
        S.qs[i >> 6][i & 63] = g_q[(size_t)(t0 + (i >> 6)) * C_DIM + base + (i & 63)];
    __syncthreads();

    const int w = tid >> 5;
    const int lane = tid & 31;
    const int t = t0 + w;
    const unsigned ltm = (1u << lane) - 1;

    int count = 0;
    for (int b2 = 0; b2 < ucnt && count < 64; b2 += 32) {
        int i = b2 + lane;
        bool f = (i < ucnt) && (S.uidx[i] <= t);
        unsigned m = __ballot_sync(0xffffffffu, f);
        int before = __popc(m & ltm);
        if (f && count + before < 64) S.sel[w][count + before] = (short)i;
        count += __popc(m);
    }
    __syncwarp();

    const int s0 = S.sel[w][lane];
    const int s1 = S.sel[w][lane + 32];
    float lo0 = 0.f, lo1 = 0.f;
#pragma unroll 8
    for (int d = 0; d < 64; d++) {
        float qq = S.qs[w][d];
        lo0 += qq * S.Kc[s0][d];
        lo1 += qq * S.Kc[s1][d];
    }
    lo0 *= 0.125f; lo1 *= 0.125f;

    float m = fmaxf(lo0, lo1);
#pragma unroll
    for (int o = 16; o; o >>= 1) m = fmaxf(m, __shfl_xor_sync(0xffffffffu, m, o));
    float e0 = expf(lo0 - m), e1 = expf(lo1 - m);
    float sum = e0 + e1;
#pragma unroll
    for (int o = 16; o; o >>= 1) sum += __shfl_xor_sync(0xffffffffu, sum, o);
    float inv = 1.f / sum;
    S.lg[w][lane] = e0 * inv;
    S.lg[w][lane + 32] = e1 * inv;
    __syncwarp();

    float a0 = 0.f, a1 = 0.f;
#pragma unroll 8
    for (int j = 0; j < 64; j++) {
        float p = S.lg[w][j];
        int s = S.sel[w][j];
        a0 += p * S.Vc[s][lane];
        a1 += p * S.Vc[s][lane + 32];
    }

    size_t off = (size_t)t * C_DIM + base;
    g_atq[off + lane]      = __float2half_rn(a0);
    g_atq[off + lane + 32] = __float2half_rn(a1);
}

// ---------------------------------------------------------------------------
// Small-t attention (t < 64)
// ---------------------------------------------------------------------------
__global__ __launch_bounds__(128) void attn_small_kernel()
{
    const int bid = blockIdx.x;
    const int h = bid & (NHEAD - 1);
    const int t = bid >> 4;
    const int tid = threadIdx.x;
    const int lane = tid & 31;
    const int w = tid >> 5;
    const int base = h * HSIZE;

    __shared__ float qs[HSIZE];
    __shared__ float lg[KSP];
    __shared__ float part[2][HSIZE];

    if (tid < 64) qs[tid] = g_q[(size_t)t * C_DIM + base + tid];
    __syncthreads();

#pragma unroll 1
    for (int j = w * 16; j < w * 16 + 16; j++) {
        int kidx = min(j, t);
        const float* kr = g_k + (size_t)kidx * C_DIM + base;
        float p = kr[lane] * qs[lane] + kr[lane + 32] * qs[lane + 32];
#pragma unroll
        for (int o = 16; o; o >>= 1) p += __shfl_down_sync(0xffffffffu, p, o);
        if (lane == 0) lg[j] = p * 0.125f;
    }
    __syncthreads();

    if (w == 0) {
        float a = lg[lane], b = lg[lane + 32];
        float m = fmaxf(a, b);
#pragma unroll
        for (int o = 16; o; o >>= 1) m = fmaxf(m, __shfl_xor_sync(0xffffffffu, m, o));
        float e0 = expf(a - m), e1 = expf(b - m);
        float s = e0 + e1;
#pragma unroll
        for (int o = 16; o; o >>= 1) s += __shfl_xor_sync(0xffffffffu, s, o);
        float inv = 1.f / s;
        lg[lane] = e0 * inv;
        lg[lane + 32] = e1 * inv;
    }
    __syncthreads();

    const int half = tid >> 6;
    const int d = tid & 63;
    float acc = 0.f;
#pragma unroll 1
    for (int j = half * 32; j < half * 32 + 32; j++)
        acc += lg[j] * g_v[(size_t)min(j, t) * C_DIM + base + d];
    part[half][d] = acc;
    __syncthreads();

    if (tid < 64)
        g_atq[(size_t)t * C_DIM + base + tid] =
            __float2half_rn(part[0][tid] + part[1][tid]);
}

// ---------------------------------------------------------------------------
extern "C" void kernel_launch(void* const* d_in, const int* in_sizes, int n_in,
                              void* d_out, int out_size)
{
    const float* x   = (const float*)d_in[0];
    const float* Wq  = (const float*)d_in[1];
    const float* bq  = (const float*)d_in[2];
    const float* Wk  = (const float*)d_in[3];
    const float* bk  = (const float*)d_in[4];
    const float* Wv  = (const float*)d_in[5];
    const float* bv  = (const float*)d_in[6];
    const float* Wo  = (const float*)d_in[7];
    const float* bo  = (const float*)d_in[8];
    const float* Wks = (const float*)d_in[9];
    const float* bks = (const float*)d_in[10];
    float* out = (float*)d_out;

    float *q, *k, *v;
    cudaGetSymbolAddress((void**)&q, g_q);
    cudaGetSymbolAddress((void**)&k, g_k);
    cudaGetSymbolAddress((void**)&v, g_v);

    __half *xq, *wq, *wk, *wv, *wo, *atq;
    cudaGetSymbolAddress((void**)&xq,  g_xq);
    cudaGetSymbolAddress((void**)&wq,  g_wq);
    cudaGetSymbolAddress((void**)&wk,  g_wk);
    cudaGetSymbolAddress((void**)&wv,  g_wv);
    cudaGetSymbolAddress((void**)&wo,  g_wo);
    cudaGetSymbolAddress((void**)&atq, g_atq);

    const int gemm_smem = NSTAGE * STAGE_B;            // 131072
    const int attn_smem = (int)sizeof(AttnSmem);
    static bool attr_done = false;
    if (!attr_done) {
        cudaFuncSetAttribute(gemm_qkv, cudaFuncAttributeMaxDynamicSharedMemorySize, gemm_smem);
        cudaFuncSetAttribute(gemm_tc,  cudaFuncAttributeMaxDynamicSharedMemorySize, gemm_smem);
        cudaFuncSetAttribute(attn_group_kernel, cudaFuncAttributeMaxDynamicSharedMemorySize, attn_smem);
        attr_done = true;
    }

    // x convert + key scores (one block per row)
    splitx_score_kernel<<<T_DIM, 256>>>((const float4*)x, (uint2*)xq,
                                        (const float4*)Wks, bks);
    // all weight converts in one launch
    convw_kernel<<<4 * (NW4 / 256), 256>>>(
        (const float4*)Wq, (uint2*)wq,
        (const float4*)Wk, (uint2*)wk,
        (const float4*)Wv, (uint2*)wv,
        (const float4*)Wo, (uint2*)wo);

    gemm_qkv<<<dim3(24, 16), 256, gemm_smem>>>(
        xq,
        wq, bq, q,
        wk, bk, k,
        wv, bv, v);

    sort_kernel<<<1, 1024>>>();
    prep_kernel<<<NGRP, 32>>>();

    attn_small_kernel<<<KSP * NHEAD, 128>>>();
    attn_group_kernel<<<dim3(NGRP, NHEAD), 512, attn_smem>>>();

    gemm_tc<<<dim3(8, 16), 256, gemm_smem>>>(atq, wo, bo, out);
}

// round 8
// speedup vs baseline: 4.0755x; 1.0362x over previous
#include <cuda_runtime.h>
#include <cuda_fp16.h>
#include <cstdint>

#define T_DIM 2048
#define C_DIM 1024
#define NHEAD 16
#define HSIZE 64
#define KSP   64
#define GQ    16
#define UMAX  128
#define NGRP  ((T_DIM - KSP) / GQ)   // 124

// ---------------- scratch (no allocations allowed) ----------------
__device__ float  g_q[T_DIM * C_DIM];
__device__ __half g_kh[T_DIM * C_DIM];
__device__ __half g_vh[T_DIM * C_DIM];
__device__ float  g_scores[T_DIM];
__device__ int    g_sorted[T_DIM];
__device__ int    g_uidx[NGRP * UMAX];
__device__ int    g_ucnt[NGRP];

// fp16 operands
__device__ __half g_xq[T_DIM * C_DIM];
__device__ __half g_wq[C_DIM * C_DIM];
__device__ __half g_wk[C_DIM * C_DIM];
__device__ __half g_wv[C_DIM * C_DIM];
__device__ __half g_wo[C_DIM * C_DIM];
__device__ __half g_atq[T_DIM * C_DIM];

// ---------------- helpers ----------------
__device__ __forceinline__ uint32_t smem_to_u32(const void* p) {
    uint32_t a;
    asm("{ .reg .u64 t; cvta.to.shared.u64 t, %1; cvt.u32.u64 %0, t; }" : "=r"(a) : "l"(p));
    return a;
}
#define SW128(off) ((off) ^ (((off) >> 3) & 0x70))

__device__ __forceinline__ void cp16(uint32_t dst, const void* src) {
    asm volatile("cp.async.cg.shared.global [%0], [%1], 16;" :: "r"(dst), "l"(src));
}
#define CP_COMMIT() asm volatile("cp.async.commit_group;" ::: "memory")
#define CP_WAIT(n)  asm volatile("cp.async.wait_group %0;" :: "n"(n) : "memory")

#define LDSM4(r, addr) \
    asm volatile("ldmatrix.sync.aligned.m8n8.x4.shared.b16 {%0,%1,%2,%3}, [%4];" \
        : "=r"((r)[0]), "=r"((r)[1]), "=r"((r)[2]), "=r"((r)[3]) : "r"(addr))

__device__ __forceinline__ void mma16816(float* d, const uint32_t* a, const uint32_t* b) {
    asm volatile("mma.sync.aligned.m16n8k16.row.col.f32.f16.f16.f32 "
        "{%0,%1,%2,%3}, {%4,%5,%6,%7}, {%8,%9}, {%0,%1,%2,%3};"
        : "+f"(d[0]), "+f"(d[1]), "+f"(d[2]), "+f"(d[3])
        : "r"(a[0]), "r"(a[1]), "r"(a[2]), "r"(a[3]), "r"(b[0]), "r"(b[1]));
}

// ---------------------------------------------------------------------------
// Fused: x -> fp16 convert + key_scores = x . Wks + bks
// ---------------------------------------------------------------------------
__global__ __launch_bounds__(256) void splitx_score_kernel(
    const float4* __restrict__ x4, uint2* __restrict__ xq,
    const float4* __restrict__ wks4, const float* __restrict__ bks)
{
    const int tid = threadIdx.x;
    const int i = blockIdx.x * 256 + tid;
    float4 v = x4[i];
    __half2 p0 = __floats2half2_rn(v.x, v.y);
    __half2 p1 = __floats2half2_rn(v.z, v.w);
    xq[i] = make_uint2(*reinterpret_cast<uint32_t*>(&p0), *reinterpret_cast<uint32_t*>(&p1));

    float4 wk = wks4[tid];
    float s = v.x * wk.x + v.y * wk.y + v.z * wk.z + v.w * wk.w;
#pragma unroll
    for (int o = 16; o; o >>= 1) s += __shfl_down_sync(0xffffffffu, s, o);
    __shared__ float red[8];
    if ((tid & 31) == 0) red[tid >> 5] = s;
    __syncthreads();
    if (tid == 0) {
        float tot = 0.f;
#pragma unroll
        for (int j = 0; j < 8; j++) tot += red[j];
        g_scores[blockIdx.x] = tot + bks[0];
    }
}

// ---------------------------------------------------------------------------
// All-4-weights fp32 -> fp16 convert in one launch
// ---------------------------------------------------------------------------
#define NW4 (C_DIM * C_DIM / 4)   // 262144 float4 per weight

__global__ __launch_bounds__(256) void convw_kernel(
    const float4* __restrict__ w0, uint2* __restrict__ d0,
    const float4* __restrict__ w1, uint2* __restrict__ d1,
    const float4* __restrict__ w2, uint2* __restrict__ d2,
    const float4* __restrict__ w3, uint2* __restrict__ d3)
{
    const int nblk = NW4 / 256;   // 1024
    int which = blockIdx.x / nblk;
    int i = (blockIdx.x % nblk) * 256 + threadIdx.x;
    const float4* src = (which == 0) ? w0 : (which == 1) ? w1 : (which == 2) ? w2 : w3;
    uint2* dst = (which == 0) ? d0 : (which == 1) ? d1 : (which == 2) ? d2 : d3;
    float4 v = src[i];
    __half2 a = __floats2half2_rn(v.x, v.y);
    __half2 b = __floats2half2_rn(v.z, v.w);
    dst[i] = make_uint2(*reinterpret_cast<uint32_t*>(&a), *reinterpret_cast<uint32_t*>(&b));
}

// ---------------------------------------------------------------------------
// HMMA GEMM core, fp16: D = Ax*B + bias. Templated output type.
// CTA tile 128x128, BK=64, 8 warps (4m x 2n), 4-stage cp.async pipeline.
// ---------------------------------------------------------------------------
#define NCHUNK  (C_DIM / 64)   // 16
#define TILE_B  16384
#define STAGE_B 32768          // 2 tiles: Ax, B
#define NSTAGE  4
#define RU      (C_DIM / 8)

template <bool HALF_OUT>
__device__ __forceinline__ void gemm_core(
    const __half* Ax, const __half* B,
    const float* bias, void* outp, int bm, int bn, char* smem)
{
    const uint32_t sb = smem_to_u32(smem);
    const int tid = threadIdx.x;
    const int wid = tid >> 5;
    const int lane = tid & 31;
    const int warp_m = wid & 3;
    const int warp_n = wid >> 2;

    float acc[2][8][4];
#pragma unroll
    for (int i = 0; i < 2; i++)
#pragma unroll
        for (int j = 0; j < 8; j++)
#pragma unroll
            for (int q = 0; q < 4; q++) acc[i][j][q] = 0.f;

    const uint4* srcs[2] = {
        reinterpret_cast<const uint4*>(Ax) + (size_t)bm * RU,
        reinterpret_cast<const uint4*>(B)  + (size_t)bn * RU };

    const int lrow = tid >> 3;
    const int lch  = tid & 7;

    auto issue = [&](int s, int c) {
        const int kq = c * 8;
        const uint32_t sbase = sb + s * STAGE_B;
#pragma unroll
        for (int t2 = 0; t2 < 2; t2++) {
            const uint4* srow = srcs[t2] + kq;
            const uint32_t dbase = sbase + t2 * TILE_B;
#pragma unroll
            for (int p = 0; p < 4; p++) {
                int row = lrow + p * 32;
                cp16(dbase + SW128(row * 128 + lch * 16),
                     srow + (size_t)row * RU + lch);
            }
        }
        CP_COMMIT();
    };

    issue(0, 0);
    issue(1, 1);
    issue(2, 2);

    const int a_row  = warp_m * 32 + (lane & 15);
    const int a_koff = (lane >> 4) * 16;
    const int b_row  = warp_n * 64 + (lane & 7) + ((lane >> 4) & 1) * 8;
    const int b_koff = ((lane >> 3) & 1) * 16;

    for (int c = 0; c < NCHUNK; c++) {
        const int s = c % NSTAGE;
        if (c >= NCHUNK - 1)      { CP_WAIT(0); }
        else if (c == NCHUNK - 2) { CP_WAIT(1); }
        else                      { CP_WAIT(2); }
        __syncthreads();

        const uint32_t aX = sb + s * STAGE_B;
        const uint32_t bB = aX + TILE_B;

#pragma unroll
        for (int ks = 0; ks < 4; ks++) {
            const int akb = ks * 32 + a_koff;
            const int bkb = ks * 32 + b_koff;
            uint32_t ax[2][4], bb[4][4];
#pragma unroll
            for (int mi = 0; mi < 2; mi++) {
                int off = (a_row + mi * 16) * 128 + akb;
                LDSM4(ax[mi], aX + SW128(off));
            }
#pragma unroll
            for (int ni2 = 0; ni2 < 4; ni2++) {
                int off = (b_row + ni2 * 16) * 128 + bkb;
                LDSM4(bb[ni2], bB + SW128(off));
            }
#pragma unroll
            for (int mi = 0; mi < 2; mi++)
#pragma unroll
                for (int ni = 0; ni < 8; ni++)
                    mma16816(acc[mi][ni], ax[mi], &bb[ni >> 1][(ni & 1) * 2]);
        }
        __syncthreads();
        if (c + NSTAGE - 1 < NCHUNK) issue((c + NSTAGE - 1) % NSTAGE, c + NSTAGE - 1);
    }

    const int g  = lane >> 2;
    const int tg = lane & 3;
#pragma unroll
    for (int mi = 0; mi < 2; mi++) {
        const int row = bm + warp_m * 32 + mi * 16 + g;
#pragma unroll
        for (int ni = 0; ni < 8; ni++) {
            const int col = bn + warp_n * 64 + ni * 8 + tg * 2;
            float2 bv = *reinterpret_cast<const float2*>(bias + col);
            float o00 = acc[mi][ni][0] + bv.x, o01 = acc[mi][ni][1] + bv.y;
            float o10 = acc[mi][ni][2] + bv.x, o11 = acc[mi][ni][3] + bv.y;
            if (HALF_OUT) {
                __half* out = (__half*)outp;
                __half2 h0 = __floats2half2_rn(o00, o01);
                __half2 h1 = __floats2half2_rn(o10, o11);
                *reinterpret_cast<__half2*>(out + (size_t)row * C_DIM + col) = h0;
                *reinterpret_cast<__half2*>(out + (size_t)(row + 8) * C_DIM + col) = h1;
            } else {
                float* out = (float*)outp;
                *reinterpret_cast<float2*>(out + (size_t)row * C_DIM + col) = make_float2(o00, o01);
                *reinterpret_cast<float2*>(out + (size_t)(row + 8) * C_DIM + col) = make_float2(o10, o11);
            }
        }
    }
}

// Fused QKV: grid (24, 16). which 0 -> Q (fp32), 1/2 -> K/V (fp16)
__global__ __launch_bounds__(256) void gemm_qkv(
    const __half* Ax,
    const __half* B0, const float* bias0, float* out0,
    const __half* B1, const float* bias1, __half* out1,
    const __half* B2, const float* bias2, __half* out2)
{
    extern __shared__ char smem[];
    const int nb = blockIdx.x;
    const int which = nb >> 3;
    const int bn = (nb & 7) << 7;
    const int bm = blockIdx.y << 7;
    if (which == 0) {
        gemm_core<false>(Ax, B0, bias0, out0, bm, bn, smem);
    } else if (which == 1) {
        gemm_core<true>(Ax, B1, bias1, out1, bm, bn, smem);
    } else {
        gemm_core<true>(Ax, B2, bias2, out2, bm, bn, smem);
    }
}

__global__ __launch_bounds__(256) void gemm_tc(
    const __half* Ax, const __half* B, const float* bias, float* out)
{
    extern __shared__ char smem[];
    gemm_core<false>(Ax, B, bias, out, blockIdx.y << 7, blockIdx.x << 7, smem);
}

// ---------------------------------------------------------------------------
// Hybrid bitonic sort: 2048 u64 keys, 2/thread in registers.
// key = (~monotone(score) << 11) | idx  -> ascending u64 = jax top_k order.
// Stages j<=32 via shfl, j=1 intra-thread, j>=64 via SMEM.
// ---------------------------------------------------------------------------
__device__ __forceinline__ unsigned long long sort_key(float f, int idx) {
    uint32_t u = __float_as_uint(f);
    u = (u & 0x80000000u) ? ~u : (u | 0x80000000u);   // monotone ascending
    u = ~u;                                            // descending score
    return ((unsigned long long)u << 11) | (unsigned)idx;
}

__global__ __launch_bounds__(1024) void sort_kernel()
{
    __shared__ unsigned long long sk[T_DIM];
    const int tid = threadIdx.x;
    const int lane = tid & 31;
    const int i0 = 2 * tid;

    unsigned long long e0 = sort_key(g_scores[i0], i0);
    unsigned long long e1 = sort_key(g_scores[i0 + 1], i0 + 1);

#pragma unroll
    for (int k = 2; k <= T_DIM; k <<= 1) {
        const bool dirAsc = ((i0 & k) == 0);
        // cross-warp stages
        for (int j = k >> 1; j >= 64; j >>= 1) {
            sk[i0] = e0; sk[i0 + 1] = e1;
            __syncthreads();
            unsigned long long p0 = sk[i0 ^ j];
            unsigned long long p1 = sk[(i0 + 1) ^ j];
            const bool low = ((i0 & j) == 0);
            if (dirAsc == low) {
                e0 = (p0 < e0) ? p0 : e0;
                e1 = (p1 < e1) ? p1 : e1;
            } else {
                e0 = (p0 > e0) ? p0 : e0;
                e1 = (p1 > e1) ? p1 : e1;
            }
            __syncthreads();
        }
        // intra-warp stages (j = min(k/2,32) .. 2)
        for (int j = (k >> 1) < 32 ? (k >> 1) : 32; j >= 2; j >>= 1) {
            const int h = j >> 1;
            unsigned long long p0 = __shfl_xor_sync(0xffffffffu, e0, h);
            unsigned long long p1 = __shfl_xor_sync(0xffffffffu, e1, h);
            const bool low = ((lane & h) == 0);
            if (dirAsc == low) {
                e0 = (p0 < e0) ? p0 : e0;
                e1 = (p1 < e1) ? p1 : e1;
            } else {
                e0 = (p0 > e0) ? p0 : e0;
                e1 = (p1 > e1) ? p1 : e1;
            }
        }
        // j == 1: intra-thread
        {
            unsigned long long lo = (e0 < e1) ? e0 : e1;
            unsigned long long hi = (e0 < e1) ? e1 : e0;
            e0 = dirAsc ? lo : hi;
            e1 = dirAsc ? hi : lo;
        }
    }
    g_sorted[i0]     = (int)(e0 & 0x7FF);
    g_sorted[i0 + 1] = (int)(e1 & 0x7FF);
}

// ---------------------------------------------------------------------------
// Per-group candidate union (one warp per group)
// ---------------------------------------------------------------------------
__global__ void prep_kernel()
{
    int g = blockIdx.x;
    int lane = threadIdx.x;
    int tmin = KSP + g * GQ;
    int tmax = tmin + GQ - 1;
    unsigned lt = (1u << lane) - 1;

    int cmin = 0, kept = 0;
    for (int base = 0; base < T_DIM && cmin < 64; base += 32) {
        int sidx = g_sorted[base + lane];
        bool vmax = (sidx <= tmax);
        unsigned m = __ballot_sync(0xffffffffu, vmax);
        int before = __popc(m & lt);
        if (vmax) g_uidx[g * UMAX + kept + before] = sidx;
        kept += __popc(m);
        cmin += __popc(__ballot_sync(0xffffffffu, sidx <= tmin));
    }
    if (lane == 0) g_ucnt[g] = kept;
}

// ---------------------------------------------------------------------------
// Grouped sparse attention (fp16 K/V gather, fp32 SMEM compute)
// ---------------------------------------------------------------------------
struct AttnSmem {
    float Kc[UMAX][65];
    float Vc[UMAX][64];
    float qs[GQ][64];
    float lg[GQ][64];
    int   uidx[UMAX];
    short sel[GQ][64];
    int   ucnt;
};

__global__ __launch_bounds__(512) void attn_group_kernel()
{
    extern __shared__ char sm_raw[];
    AttnSmem& S = *reinterpret_cast<AttnSmem*>(sm_raw);

    const int grp = blockIdx.x;
    const int h   = blockIdx.y;
    const int t0  = KSP + grp * GQ;
    const int base = h * HSIZE;
    const int tid = threadIdx.x;

    if (tid == 0) S.ucnt = g_ucnt[grp];
    if (tid < UMAX) S.uidx[tid] = g_uidx[grp * UMAX + tid];
    __syncthreads();
    const int ucnt = S.ucnt;

    // stage union rows: 8 threads/row (each loads 8 halves = uint4), 64 rows/pass
    for (int r = tid >> 3; r < ucnt; r += 64) {
        int tok = S.uidx[r];
        int dc = (tid & 7) << 3;
        uint4 kk = *((const uint4*)(g_kh + (size_t)tok * C_DIM + base) + (tid & 7));
        uint4 vv = *((const uint4*)(g_vh + (size_t)tok * C_DIM + base) + (tid & 7));
        const __half2* kh = reinterpret_cast<const __half2*>(&kk);
        const __half2* vh = reinterpret_cast<const __half2*>(&vv);
#pragma unroll
        for (int q2 = 0; q2 < 4; q2++) {
            float2 kf = __half22float2(kh[q2]);
            float2 vf = __half22float2(vh[q2]);
            S.Kc[r][dc + 2 * q2]     = kf.x;
            S.Kc[r][dc + 2 * q2 + 1] = kf.y;
            S.Vc[r][dc + 2 * q2]     = vf.x;
            S.Vc[r][dc + 2 * q2 + 1] = vf.y;
        }
    }
    for (int i = tid; i < GQ * 64; i += 512)
        S.qs[i >> 6][i & 63] = g_q[(size_t)(t0 + (i >> 6)) * C_DIM + base + (i & 63)];
    __syncthreads();

    const int w = tid >> 5;
    const int lane = tid & 31;
    const int t = t0 + w;
    const unsigned ltm = (1u << lane) - 1;

    int count = 0;
    for (int b2 = 0; b2 < ucnt && count < 64; b2 += 32) {
        int i = b2 + lane;
        bool f = (i < ucnt) && (S.uidx[i] <= t);
        unsigned m = __ballot_sync(0xffffffffu, f);
        int before = __popc(m & ltm);
        if (f && count + before < 64) S.sel[w][count + before] = (short)i;
        count += __popc(m);
    }
    __syncwarp();

    const int s0 = S.sel[w][lane];
    const int s1 = S.sel[w][lane + 32];
    float lo0 = 0.f, lo1 = 0.f;
#pragma unroll 8
    for (int d = 0; d < 64; d++) {
        float qq = S.qs[w][d];
        lo0 += qq * S.Kc[s0][d];
        lo1 += qq * S.Kc[s1][d];
    }
    lo0 *= 0.125f; lo1 *= 0.125f;

    float m = fmaxf(lo0, lo1);
#pragma unroll
    for (int o = 16; o; o >>= 1) m = fmaxf(m, __shfl_xor_sync(0xffffffffu, m, o));
    float e0 = expf(lo0 - m), e1 = expf(lo1 - m);
    float sum = e0 + e1;
#pragma unroll
    for (int o = 16; o; o >>= 1) sum += __shfl_xor_sync(0xffffffffu, sum, o);
    float inv = 1.f / sum;
    S.lg[w][lane] = e0 * inv;
    S.lg[w][lane + 32] = e1 * inv;
    __syncwarp();

    float a0 = 0.f, a1 = 0.f;
#pragma unroll 8
    for (int j = 0; j < 64; j++) {
        float p = S.lg[w][j];
        int s = S.sel[w][j];
        a0 += p * S.Vc[s][lane];
        a1 += p * S.Vc[s][lane + 32];
    }

    size_t off = (size_t)t * C_DIM + base;
    g_atq[off + lane]      = __float2half_rn(a0);
    g_atq[off + lane + 32] = __float2half_rn(a1);
}

// ---------------------------------------------------------------------------
// Small-t attention (t < 64)
// ---------------------------------------------------------------------------
__global__ __launch_bounds__(128) void attn_small_kernel()
{
    const int bid = blockIdx.x;
    const int h = bid & (NHEAD - 1);
    const int t = bid >> 4;
    const int tid = threadIdx.x;
    const int lane = tid & 31;
    const int w = tid >> 5;
    const int base = h * HSIZE;

    __shared__ float qs[HSIZE];
    __shared__ float lg[KSP];
    __shared__ float part[2][HSIZE];

    if (tid < 64) qs[tid] = g_q[(size_t)t * C_DIM + base + tid];
    __syncthreads();

#pragma unroll 1
    for (int j = w * 16; j < w * 16 + 16; j++) {
        int kidx = min(j, t);
        const __half* kr = g_kh + (size_t)kidx * C_DIM + base;
        float p = __half2float(kr[lane]) * qs[lane]
                + __half2float(kr[lane + 32]) * qs[lane + 32];
#pragma unroll
        for (int o = 16; o; o >>= 1) p += __shfl_down_sync(0xffffffffu, p, o);
        if (lane == 0) lg[j] = p * 0.125f;
    }
    __syncthreads();

    if (w == 0) {
        float a = lg[lane], b = lg[lane + 32];
        float m = fmaxf(a, b);
#pragma unroll
        for (int o = 16; o; o >>= 1) m = fmaxf(m, __shfl_xor_sync(0xffffffffu, m, o));
        float e0 = expf(a - m), e1 = expf(b - m);
        float s = e0 + e1;
#pragma unroll
        for (int o = 16; o; o >>= 1) s += __shfl_xor_sync(0xffffffffu, s, o);
        float inv = 1.f / s;
        lg[lane] = e0 * inv;
        lg[lane + 32] = e1 * inv;
    }
    __syncthreads();

    const int half = tid >> 6;
    const int d = tid & 63;
    float acc = 0.f;
#pragma unroll 1
    for (int j = half * 32; j < half * 32 + 32; j++)
        acc += lg[j] * __half2float(g_vh[(size_t)min(j, t) * C_DIM + base + d]);
    part[half][d] = acc;
    __syncthreads();

    if (tid < 64)
        g_atq[(size_t)t * C_DIM + base + tid] =
            __float2half_rn(part[0][tid] + part[1][tid]);
}

// ---------------------------------------------------------------------------
extern "C" void kernel_launch(void* const* d_in, const int* in_sizes, int n_in,
                              void* d_out, int out_size)
{
    const float* x   = (const float*)d_in[0];
    const float* Wq  = (const float*)d_in[1];
    const float* bq  = (const float*)d_in[2];
    const float* Wk  = (const float*)d_in[3];
    const float* bk  = (const float*)d_in[4];
    const float* Wv  = (const float*)d_in[5];
    const float* bv  = (const float*)d_in[6];
    const float* Wo  = (const float*)d_in[7];
    const float* bo  = (const float*)d_in[8];
    const float* Wks = (const float*)d_in[9];
    const float* bks = (const float*)d_in[10];
    float* out = (float*)d_out;

    float* q;
    __half *kh, *vh;
    cudaGetSymbolAddress((void**)&q,  g_q);
    cudaGetSymbolAddress((void**)&kh, g_kh);
    cudaGetSymbolAddress((void**)&vh, g_vh);

    __half *xq, *wq, *wk, *wv, *wo, *atq;
    cudaGetSymbolAddress((void**)&xq,  g_xq);
    cudaGetSymbolAddress((void**)&wq,  g_wq);
    cudaGetSymbolAddress((void**)&wk,  g_wk);
    cudaGetSymbolAddress((void**)&wv,  g_wv);
    cudaGetSymbolAddress((void**)&wo,  g_wo);
    cudaGetSymbolAddress((void**)&atq, g_atq);

    const int gemm_smem = NSTAGE * STAGE_B;            // 131072
    const int attn_smem = (int)sizeof(AttnSmem);
    static bool attr_done = false;
    if (!attr_done) {
        cudaFuncSetAttribute(gemm_qkv, cudaFuncAttributeMaxDynamicSharedMemorySize, gemm_smem);
        cudaFuncSetAttribute(gemm_tc,  cudaFuncAttributeMaxDynamicSharedMemorySize, gemm_smem);
        cudaFuncSetAttribute(attn_group_kernel, cudaFuncAttributeMaxDynamicSharedMemorySize, attn_smem);
        attr_done = true;
    }

    splitx_score_kernel<<<T_DIM, 256>>>((const float4*)x, (uint2*)xq,
                                        (const float4*)Wks, bks);
    convw_kernel<<<4 * (NW4 / 256), 256>>>(
        (const float4*)Wq, (uint2*)wq,
        (const float4*)Wk, (uint2*)wk,
        (const float4*)Wv, (uint2*)wv,
        (const float4*)Wo, (uint2*)wo);

    gemm_qkv<<<dim3(24, 16), 256, gemm_smem>>>(
        xq,
        wq, bq, q,
        wk, bk, kh,
        wv, bv, vh);

    sort_kernel<<<1, 1024>>>();
    prep_kernel<<<NGRP, 32>>>();

    attn_small_kernel<<<KSP * NHEAD, 128>>>();
    attn_group_kernel<<<dim3(NGRP, NHEAD), 512, attn_smem>>>();

    gemm_tc<<<dim3(8, 16), 256, gemm_smem>>>(atq, wo, bo, out);
}

// round 9
// speedup vs baseline: 4.2253x; 1.0367x over previous
#include <cuda_runtime.h>
#include <cuda_fp16.h>
#include <cstdint>

#define T_DIM 2048
#define C_DIM 1024
#define NHEAD 16
#define HSIZE 64
#define KSP   64
#define GQ    16
#define UMAX  128
#define NGRP  ((T_DIM - KSP) / GQ)   // 124

// ---------------- scratch (no allocations allowed) ----------------
__device__ float  g_q[T_DIM * C_DIM];
__device__ __half g_kh[T_DIM * C_DIM];
__device__ __half g_vh[T_DIM * C_DIM];
__device__ float  g_scores[T_DIM];
__device__ int    g_sorted[T_DIM];
__device__ int    g_uidx[NGRP * UMAX];
__device__ int    g_ucnt[NGRP];

// fp16 operands
__device__ __half g_xq[T_DIM * C_DIM];
__device__ __half g_wq[C_DIM * C_DIM];
__device__ __half g_wk[C_DIM * C_DIM];
__device__ __half g_wv[C_DIM * C_DIM];
__device__ __half g_wo[C_DIM * C_DIM];
__device__ __half g_atq[T_DIM * C_DIM];

// ---------------- helpers ----------------
__device__ __forceinline__ uint32_t smem_to_u32(const void* p) {
    uint32_t a;
    asm("{ .reg .u64 t; cvta.to.shared.u64 t, %1; cvt.u32.u64 %0, t; }" : "=r"(a) : "l"(p));
    return a;
}
#define SW128(off) ((off) ^ (((off) >> 3) & 0x70))

__device__ __forceinline__ void cp16(uint32_t dst, const void* src) {
    asm volatile("cp.async.cg.shared.global [%0], [%1], 16;" :: "r"(dst), "l"(src));
}
#define CP_COMMIT() asm volatile("cp.async.commit_group;" ::: "memory")
#define CP_WAIT(n)  asm volatile("cp.async.wait_group %0;" :: "n"(n) : "memory")

#define LDSM4(r, addr) \
    asm volatile("ldmatrix.sync.aligned.m8n8.x4.shared.b16 {%0,%1,%2,%3}, [%4];" \
        : "=r"((r)[0]), "=r"((r)[1]), "=r"((r)[2]), "=r"((r)[3]) : "r"(addr))

__device__ __forceinline__ void mma16816(float* d, const uint32_t* a, const uint32_t* b) {
    asm volatile("mma.sync.aligned.m16n8k16.row.col.f32.f16.f16.f32 "
        "{%0,%1,%2,%3}, {%4,%5,%6,%7}, {%8,%9}, {%0,%1,%2,%3};"
        : "+f"(d[0]), "+f"(d[1]), "+f"(d[2]), "+f"(d[3])
        : "r"(a[0]), "r"(a[1]), "r"(a[2]), "r"(a[3]), "r"(b[0]), "r"(b[1]));
}

// ---------------------------------------------------------------------------
// Fused: x -> fp16 convert + key_scores = x . Wks + bks
// ---------------------------------------------------------------------------
__global__ __launch_bounds__(256) void splitx_score_kernel(
    const float4* __restrict__ x4, uint2* __restrict__ xq,
    const float4* __restrict__ wks4, const float* __restrict__ bks)
{
    const int tid = threadIdx.x;
    const int i = blockIdx.x * 256 + tid;
    float4 v = x4[i];
    __half2 p0 = __floats2half2_rn(v.x, v.y);
    __half2 p1 = __floats2half2_rn(v.z, v.w);
    xq[i] = make_uint2(*reinterpret_cast<uint32_t*>(&p0), *reinterpret_cast<uint32_t*>(&p1));

    float4 wk = wks4[tid];
    float s = v.x * wk.x + v.y * wk.y + v.z * wk.z + v.w * wk.w;
#pragma unroll
    for (int o = 16; o; o >>= 1) s += __shfl_down_sync(0xffffffffu, s, o);
    __shared__ float red[8];
    if ((tid & 31) == 0) red[tid >> 5] = s;
    __syncthreads();
    if (tid == 0) {
        float tot = 0.f;
#pragma unroll
        for (int j = 0; j < 8; j++) tot += red[j];
        g_scores[blockIdx.x] = tot + bks[0];
    }
}

// ---------------------------------------------------------------------------
// All-4-weights fp32 -> fp16 convert in one launch
// ---------------------------------------------------------------------------
#define NW4 (C_DIM * C_DIM / 4)   // 262144 float4 per weight

__global__ __launch_bounds__(256) void convw_kernel(
    const float4* __restrict__ w0, uint2* __restrict__ d0,
    const float4* __restrict__ w1, uint2* __restrict__ d1,
    const float4* __restrict__ w2, uint2* __restrict__ d2,
    const float4* __restrict__ w3, uint2* __restrict__ d3)
{
    const int nblk = NW4 / 256;   // 1024
    int which = blockIdx.x / nblk;
    int i = (blockIdx.x % nblk) * 256 + threadIdx.x;
    const float4* src = (which == 0) ? w0 : (which == 1) ? w1 : (which == 2) ? w2 : w3;
    uint2* dst = (which == 0) ? d0 : (which == 1) ? d1 : (which == 2) ? d2 : d3;
    float4 v = src[i];
    __half2 a = __floats2half2_rn(v.x, v.y);
    __half2 b = __floats2half2_rn(v.z, v.w);
    dst[i] = make_uint2(*reinterpret_cast<uint32_t*>(&a), *reinterpret_cast<uint32_t*>(&b));
}

// ---------------------------------------------------------------------------
// HMMA GEMM core, fp16: D = Ax*B + bias. 3-stage pipeline, 2 CTAs/SM.
// CTA tile 128x128, BK=64, 8 warps (4m x 2n).
// ---------------------------------------------------------------------------
#define NCHUNK  (C_DIM / 64)   // 16
#define TILE_B  16384
#define STAGE_B 32768          // 2 tiles: Ax, B
#define NSTAGE  3
#define RU      (C_DIM / 8)

template <bool HALF_OUT>
__device__ __forceinline__ void gemm_core(
    const __half* Ax, const __half* B,
    const float* bias, void* outp, int bm, int bn, char* smem)
{
    const uint32_t sb = smem_to_u32(smem);
    const int tid = threadIdx.x;
    const int wid = tid >> 5;
    const int lane = tid & 31;
    const int warp_m = wid & 3;
    const int warp_n = wid >> 2;

    float acc[2][8][4];
#pragma unroll
    for (int i = 0; i < 2; i++)
#pragma unroll
        for (int j = 0; j < 8; j++)
#pragma unroll
            for (int q = 0; q < 4; q++) acc[i][j][q] = 0.f;

    const uint4* srcs[2] = {
        reinterpret_cast<const uint4*>(Ax) + (size_t)bm * RU,
        reinterpret_cast<const uint4*>(B)  + (size_t)bn * RU };

    const int lrow = tid >> 3;
    const int lch  = tid & 7;

    auto issue = [&](int s, int c) {
        const int kq = c * 8;
        const uint32_t sbase = sb + s * STAGE_B;
#pragma unroll
        for (int t2 = 0; t2 < 2; t2++) {
            const uint4* srow = srcs[t2] + kq;
            const uint32_t dbase = sbase + t2 * TILE_B;
#pragma unroll
            for (int p = 0; p < 4; p++) {
                int row = lrow + p * 32;
                cp16(dbase + SW128(row * 128 + lch * 16),
                     srow + (size_t)row * RU + lch);
            }
        }
        CP_COMMIT();
    };

    issue(0, 0);
    issue(1, 1);
    issue(2, 2);

    const int a_row  = warp_m * 32 + (lane & 15);
    const int a_koff = (lane >> 4) * 16;
    const int b_row  = warp_n * 64 + (lane & 7) + ((lane >> 4) & 1) * 8;
    const int b_koff = ((lane >> 3) & 1) * 16;

    for (int c = 0; c < NCHUNK; c++) {
        const int s = c % NSTAGE;
        if (c < NCHUNK - 2)       { CP_WAIT(2); }
        else if (c == NCHUNK - 2) { CP_WAIT(1); }
        else                      { CP_WAIT(0); }
        __syncthreads();

        const uint32_t aX = sb + s * STAGE_B;
        const uint32_t bB = aX + TILE_B;

#pragma unroll
        for (int ks = 0; ks < 4; ks++) {
            const int akb = ks * 32 + a_koff;
            const int bkb = ks * 32 + b_koff;
            uint32_t ax[2][4], bb[4][4];
#pragma unroll
            for (int mi = 0; mi < 2; mi++) {
                int off = (a_row + mi * 16) * 128 + akb;
                LDSM4(ax[mi], aX + SW128(off));
            }
#pragma unroll
            for (int ni2 = 0; ni2 < 4; ni2++) {
                int off = (b_row + ni2 * 16) * 128 + bkb;
                LDSM4(bb[ni2], bB + SW128(off));
            }
#pragma unroll
            for (int mi = 0; mi < 2; mi++)
#pragma unroll
                for (int ni = 0; ni < 8; ni++)
                    mma16816(acc[mi][ni], ax[mi], &bb[ni >> 1][(ni & 1) * 2]);
        }
        __syncthreads();
        if (c + NSTAGE < NCHUNK) issue(s, c + NSTAGE);
    }

    const int g  = lane >> 2;
    const int tg = lane & 3;
#pragma unroll
    for (int mi = 0; mi < 2; mi++) {
        const int row = bm + warp_m * 32 + mi * 16 + g;
#pragma unroll
        for (int ni = 0; ni < 8; ni++) {
            const int col = bn + warp_n * 64 + ni * 8 + tg * 2;
            float2 bv = *reinterpret_cast<const float2*>(bias + col);
            float o00 = acc[mi][ni][0] + bv.x, o01 = acc[mi][ni][1] + bv.y;
            float o10 = acc[mi][ni][2] + bv.x, o11 = acc[mi][ni][3] + bv.y;
            if (HALF_OUT) {
                __half* out = (__half*)outp;
                __half2 h0 = __floats2half2_rn(o00, o01);
                __half2 h1 = __floats2half2_rn(o10, o11);
                *reinterpret_cast<__half2*>(out + (size_t)row * C_DIM + col) = h0;
                *reinterpret_cast<__half2*>(out + (size_t)(row + 8) * C_DIM + col) = h1;
            } else {
                float* out = (float*)outp;
                *reinterpret_cast<float2*>(out + (size_t)row * C_DIM + col) = make_float2(o00, o01);
                *reinterpret_cast<float2*>(out + (size_t)(row + 8) * C_DIM + col) = make_float2(o10, o11);
            }
        }
    }
}

// Fused QKV: grid (24, 16). which 0 -> Q (fp32), 1/2 -> K/V (fp16)
__global__ __launch_bounds__(256, 2) void gemm_qkv(
    const __half* Ax,
    const __half* B0, const float* bias0, float* out0,
    const __half* B1, const float* bias1, __half* out1,
    const __half* B2, const float* bias2, __half* out2)
{
    extern __shared__ char smem[];
    const int nb = blockIdx.x;
    const int which = nb >> 3;
    const int bn = (nb & 7) << 7;
    const int bm = blockIdx.y << 7;
    if (which == 0) {
        gemm_core<false>(Ax, B0, bias0, out0, bm, bn, smem);
    } else if (which == 1) {
        gemm_core<true>(Ax, B1, bias1, out1, bm, bn, smem);
    } else {
        gemm_core<true>(Ax, B2, bias2, out2, bm, bn, smem);
    }
}

__global__ __launch_bounds__(256, 2) void gemm_tc(
    const __half* Ax, const __half* B, const float* bias, float* out)
{
    extern __shared__ char smem[];
    gemm_core<false>(Ax, B, bias, out, blockIdx.y << 7, blockIdx.x << 7, smem);
}

// ---------------------------------------------------------------------------
// Rank sort: g_sorted[rank(i)] = i where rank = #tokens with higher
// (score, -idx) priority. Exactly the jax.lax.top_k order.
// grid 16, block 256: 128 tokens/block, 2 threads per token (half each).
// ---------------------------------------------------------------------------
__global__ __launch_bounds__(256) void rank_kernel()
{
    __shared__ __align__(16) float ss[T_DIM];
    __shared__ int rpart[2][128];
    const int tid = threadIdx.x;
    for (int i = tid; i < T_DIM; i += 256) ss[i] = g_scores[i];
    __syncthreads();

    const int lt = tid & 127;
    const int half = tid >> 7;
    const int tok = blockIdx.x * 128 + lt;
    const float si = ss[tok];

    const float4* s4 = reinterpret_cast<const float4*>(ss);
    int cnt = 0;
    const int j0 = half * 256;
#pragma unroll 4
    for (int j4 = j0; j4 < j0 + 256; j4++) {
        float4 v = s4[j4];
        int j = j4 << 2;
        cnt += (v.x > si) || (v.x == si && (j + 0) < tok);
        cnt += (v.y > si) || (v.y == si && (j + 1) < tok);
        cnt += (v.z > si) || (v.z == si && (j + 2) < tok);
        cnt += (v.w > si) || (v.w == si && (j + 3) < tok);
    }
    rpart[half][lt] = cnt;
    __syncthreads();
    if (half == 0)
        g_sorted[cnt + rpart[1][lt]] = tok;
}

// ---------------------------------------------------------------------------
// Per-group candidate union (one warp per group)
// ---------------------------------------------------------------------------
__global__ void prep_kernel()
{
    int g = blockIdx.x;
    int lane = threadIdx.x;
    int tmin = KSP + g * GQ;
    int tmax = tmin + GQ - 1;
    unsigned lt = (1u << lane) - 1;

    int cmin = 0, kept = 0;
    for (int base = 0; base < T_DIM && cmin < 64; base += 32) {
        int sidx = g_sorted[base + lane];
        bool vmax = (sidx <= tmax);
        unsigned m = __ballot_sync(0xffffffffu, vmax);
        int before = __popc(m & lt);
        if (vmax) g_uidx[g * UMAX + kept + before] = sidx;
        kept += __popc(m);
        cmin += __popc(__ballot_sync(0xffffffffu, sidx <= tmin));
    }
    if (lane == 0) g_ucnt[g] = kept;
}

// ---------------------------------------------------------------------------
// Grouped sparse attention (fp16 K/V gather, fp32 SMEM compute)
// ---------------------------------------------------------------------------
struct AttnSmem {
    float Kc[UMAX][65];
    float Vc[UMAX][64];
    float qs[GQ][64];
    float lg[GQ][64];
    int   uidx[UMAX];
    short sel[GQ][64];
    int   ucnt;
};

__global__ __launch_bounds__(512) void attn_group_kernel()
{
    extern __shared__ char sm_raw[];
    AttnSmem& S = *reinterpret_cast<AttnSmem*>(sm_raw);

    const int grp = blockIdx.x;
    const int h   = blockIdx.y;
    const int t0  = KSP + grp * GQ;
    const int base = h * HSIZE;
    const int tid = threadIdx.x;

    if (tid == 0) S.ucnt = g_ucnt[grp];
    if (tid < UMAX) S.uidx[tid] = g_uidx[grp * UMAX + tid];
    __syncthreads();
    const int ucnt = S.ucnt;

    for (int r = tid >> 3; r < ucnt; r += 64) {
        int tok = S.uidx[r];
        int dc = (tid & 7) << 3;
        uint4 kk = *((const uint4*)(g_kh + (size_t)tok * C_DIM + base) + (tid & 7));
        uint4 vv = *((const uint4*)(g_vh + (size_t)tok * C_DIM + base) + (tid & 7));
        const __half2* kh = reinterpret_cast<const __half2*>(&kk);
        const __half2* vh = reinterpret_cast<const __half2*>(&vv);
#pragma unroll
        for (int q2 = 0; q2 < 4; q2++) {
            float2 kf = __half22float2(kh[q2]);
            float2 vf = __half22float2(vh[q2]);
            S.Kc[r][dc + 2 * q2]     = kf.x;
            S.Kc[r][dc + 2 * q2 + 1] = kf.y;
            S.Vc[r][dc + 2 * q2]     = vf.x;
            S.Vc[r][dc + 2 * q2 + 1] = vf.y;
        }
    }
    for (int i = tid; i < GQ * 64; i += 512)
        S.qs[i >> 6][i & 63] = g_q[(size_t)(t0 + (i >> 6)) * C_DIM + base + (i & 63)];
    __syncthreads();

    const int w = tid >> 5;
    const int lane = tid & 31;
    const int t = t0 + w;
    const unsigned ltm = (1u << lane) - 1;

    int count = 0;
    for (int b2 = 0; b2 < ucnt && count < 64; b2 += 32) {
        int i = b2 + lane;
        bool f = (i < ucnt) && (S.uidx[i] <= t);
        unsigned m = __ballot_sync(0xffffffffu, f);
        int before = __popc(m & ltm);
        if (f && count + before < 64) S.sel[w][count + before] = (short)i;
        count += __popc(m);
    }
    __syncwarp();

    const int s0 = S.sel[w][lane];
    const int s1 = S.sel[w][lane + 32];
    float lo0 = 0.f, lo1 = 0.f;
#pragma unroll 8
    for (int d = 0; d < 64; d++) {
        float qq = S.qs[w][d];
        lo0 += qq * S.Kc[s0][d];
        lo1 += qq * S.Kc[s1][d];
    }
    lo0 *= 0.125f; lo1 *= 0.125f;

    float m = fmaxf(lo0, lo1);
#pragma unroll
    for (int o = 16; o; o >>= 1) m = fmaxf(m, __shfl_xor_sync(0xffffffffu, m, o));
    float e0 = expf(lo0 - m), e1 = expf(lo1 - m);
    float sum = e0 + e1;
#pragma unroll
    for (int o = 16; o; o >>= 1) sum += __shfl_xor_sync(0xffffffffu, sum, o);
    float inv = 1.f / sum;
    S.lg[w][lane] = e0 * inv;
    S.lg[w][lane + 32] = e1 * inv;
    __syncwarp();

    float a0 = 0.f, a1 = 0.f;
#pragma unroll 8
    for (int j = 0; j < 64; j++) {
        float p = S.lg[w][j];
        int s = S.sel[w][j];
        a0 += p * S.Vc[s][lane];
        a1 += p * S.Vc[s][lane + 32];
    }

    size_t off = (size_t)t * C_DIM + base;
    g_atq[off + lane]      = __float2half_rn(a0);
    g_atq[off + lane + 32] = __float2half_rn(a1);
}

// ---------------------------------------------------------------------------
// Small-t attention (t < 64)
// ---------------------------------------------------------------------------
__global__ __launch_bounds__(128) void attn_small_kernel()
{
    const int bid = blockIdx.x;
    const int h = bid & (NHEAD - 1);
    const int t = bid >> 4;
    const int tid = threadIdx.x;
    const int lane = tid & 31;
    const int w = tid >> 5;
    const int base = h * HSIZE;

    __shared__ float qs[HSIZE];
    __shared__ float lg[KSP];
    __shared__ float part[2][HSIZE];

    if (tid < 64) qs[tid] = g_q[(size_t)t * C_DIM + base + tid];
    __syncthreads();

#pragma unroll 1
    for (int j = w * 16; j < w * 16 + 16; j++) {
        int kidx = min(j, t);
        const __half* kr = g_kh + (size_t)kidx * C_DIM + base;
        float p = __half2float(kr[lane]) * qs[lane]
                + __half2float(kr[lane + 32]) * qs[lane + 32];
#pragma unroll
        for (int o = 16; o; o >>= 1) p += __shfl_down_sync(0xffffffffu, p, o);
        if (lane == 0) lg[j] = p * 0.125f;
    }
    __syncthreads();

    if (w == 0) {
        float a = lg[lane], b = lg[lane + 32];
        float m = fmaxf(a, b);
#pragma unroll
        for (int o = 16; o; o >>= 1) m = fmaxf(m, __shfl_xor_sync(0xffffffffu, m, o));
        float e0 = expf(a - m), e1 = expf(b - m);
        float s = e0 + e1;
#pragma unroll
        for (int o = 16; o; o >>= 1) s += __shfl_xor_sync(0xffffffffu, s, o);
        float inv = 1.f / s;
        lg[lane] = e0 * inv;
        lg[lane + 32] = e1 * inv;
    }
    __syncthreads();

    const int half = tid >> 6;
    const int d = tid & 63;
    float acc = 0.f;
#pragma unroll 1
    for (int j = half * 32; j < half * 32 + 32; j++)
        acc += lg[j] * __half2float(g_vh[(size_t)min(j, t) * C_DIM + base + d]);
    part[half][d] = acc;
    __syncthreads();

    if (tid < 64)
        g_atq[(size_t)t * C_DIM + base + tid] =
            __float2half_rn(part[0][tid] + part[1][tid]);
}

// ---------------------------------------------------------------------------
extern "C" void kernel_launch(void* const* d_in, const int* in_sizes, int n_in,
                              void* d_out, int out_size)
{
    const float* x   = (const float*)d_in[0];
    const float* Wq  = (const float*)d_in[1];
    const float* bq  = (const float*)d_in[2];
    const float* Wk  = (const float*)d_in[3];
    const float* bk  = (const float*)d_in[4];
    const float* Wv  = (const float*)d_in[5];
    const float* bv  = (const float*)d_in[6];
    const float* Wo  = (const float*)d_in[7];
    const float* bo  = (const float*)d_in[8];
    const float* Wks = (const float*)d_in[9];
    const float* bks = (const float*)d_in[10];
    float* out = (float*)d_out;

    float* q;
    __half *kh, *vh;
    cudaGetSymbolAddress((void**)&q,  g_q);
    cudaGetSymbolAddress((void**)&kh, g_kh);
    cudaGetSymbolAddress((void**)&vh, g_vh);

    __half *xq, *wq, *wk, *wv, *wo, *atq;
    cudaGetSymbolAddress((void**)&xq,  g_xq);
    cudaGetSymbolAddress((void**)&wq,  g_wq);
    cudaGetSymbolAddress((void**)&wk,  g_wk);
    cudaGetSymbolAddress((void**)&wv,  g_wv);
    cudaGetSymbolAddress((void**)&wo,  g_wo);
    cudaGetSymbolAddress((void**)&atq, g_atq);

    const int gemm_smem = NSTAGE * STAGE_B;            // 98304
    const int attn_smem = (int)sizeof(AttnSmem);
    static bool attr_done = false;
    if (!attr_done) {
        cudaFuncSetAttribute(gemm_qkv, cudaFuncAttributeMaxDynamicSharedMemorySize, gemm_smem);
        cudaFuncSetAttribute(gemm_tc,  cudaFuncAttributeMaxDynamicSharedMemorySize, gemm_smem);
        cudaFuncSetAttribute(attn_group_kernel, cudaFuncAttributeMaxDynamicSharedMemorySize, attn_smem);
        attr_done = true;
    }

    splitx_score_kernel<<<T_DIM, 256>>>((const float4*)x, (uint2*)xq,
                                        (const float4*)Wks, bks);
    convw_kernel<<<4 * (NW4 / 256), 256>>>(
        (const float4*)Wq, (uint2*)wq,
        (const float4*)Wk, (uint2*)wk,
        (const float4*)Wv, (uint2*)wv,
        (const float4*)Wo, (uint2*)wo);

    gemm_qkv<<<dim3(24, 16), 256, gemm_smem>>>(
        xq,
        wq, bq, q,
        wk, bk, kh,
        wv, bv, vh);

    rank_kernel<<<16, 256>>>();
    prep_kernel<<<NGRP, 32>>>();

    attn_small_kernel<<<KSP * NHEAD, 128>>>();
    attn_group_kernel<<<dim3(NGRP, NHEAD), 512, attn_smem>>>();

    gemm_tc<<<dim3(8, 16), 256, gemm_smem>>>(atq, wo, bo, out);
}

// round 10
// speedup vs baseline: 4.7632x; 1.1273x over previous
#include <cuda_runtime.h>
#include <cuda_fp16.h>
#include <cstdint>

#define T_DIM 2048
#define C_DIM 1024
#define NHEAD 16
#define HSIZE 64
#define KSP   64
#define GQ    16
#define UMAX  128
#define NGRP  ((T_DIM - KSP) / GQ)   // 124

// ---------------- scratch (no allocations allowed) ----------------
__device__ float  g_q[T_DIM * C_DIM];
__device__ __half g_kh[T_DIM * C_DIM];
__device__ __half g_vh[T_DIM * C_DIM];
__device__ float  g_scores[T_DIM];
__device__ int    g_sorted[T_DIM];
__device__ int    g_uidx[NGRP * UMAX];
__device__ int    g_ucnt[NGRP];

// fp16 operands
__device__ __half g_xq[T_DIM * C_DIM];
__device__ __half g_wq[C_DIM * C_DIM];
__device__ __half g_wk[C_DIM * C_DIM];
__device__ __half g_wv[C_DIM * C_DIM];
__device__ __half g_wo[C_DIM * C_DIM];
__device__ __half g_atq[T_DIM * C_DIM];

// ---------------- helpers ----------------
__device__ __forceinline__ uint32_t smem_to_u32(const void* p) {
    uint32_t a;
    asm("{ .reg .u64 t; cvta.to.shared.u64 t, %1; cvt.u32.u64 %0, t; }" : "=r"(a) : "l"(p));
    return a;
}
#define SW128(off) ((off) ^ (((off) >> 3) & 0x70))

__device__ __forceinline__ void cp16(uint32_t dst, const void* src) {
    asm volatile("cp.async.cg.shared.global [%0], [%1], 16;" :: "r"(dst), "l"(src));
}
#define CP_COMMIT() asm volatile("cp.async.commit_group;" ::: "memory")
#define CP_WAIT(n)  asm volatile("cp.async.wait_group %0;" :: "n"(n) : "memory")

#define LDSM4(r, addr) \
    asm volatile("ldmatrix.sync.aligned.m8n8.x4.shared.b16 {%0,%1,%2,%3}, [%4];" \
        : "=r"((r)[0]), "=r"((r)[1]), "=r"((r)[2]), "=r"((r)[3]) : "r"(addr))

__device__ __forceinline__ void mma16816(float* d, const uint32_t* a, const uint32_t* b) {
    asm volatile("mma.sync.aligned.m16n8k16.row.col.f32.f16.f16.f32 "
        "{%0,%1,%2,%3}, {%4,%5,%6,%7}, {%8,%9}, {%0,%1,%2,%3};"
        : "+f"(d[0]), "+f"(d[1]), "+f"(d[2]), "+f"(d[3])
        : "r"(a[0]), "r"(a[1]), "r"(a[2]), "r"(a[3]), "r"(b[0]), "r"(b[1]));
}

// ---------------------------------------------------------------------------
// Fused: x -> fp16 convert + key_scores = x . Wks + bks
// ---------------------------------------------------------------------------
__global__ __launch_bounds__(256) void splitx_score_kernel(
    const float4* __restrict__ x4, uint2* __restrict__ xq,
    const float4* __restrict__ wks4, const float* __restrict__ bks)
{
    const int tid = threadIdx.x;
    const int i = blockIdx.x * 256 + tid;
    float4 v = x4[i];
    __half2 p0 = __floats2half2_rn(v.x, v.y);
    __half2 p1 = __floats2half2_rn(v.z, v.w);
    xq[i] = make_uint2(*reinterpret_cast<uint32_t*>(&p0), *reinterpret_cast<uint32_t*>(&p1));

    float4 wk = wks4[tid];
    float s = v.x * wk.x + v.y * wk.y + v.z * wk.z + v.w * wk.w;
#pragma unroll
    for (int o = 16; o; o >>= 1) s += __shfl_down_sync(0xffffffffu, s, o);
    __shared__ float red[8];
    if ((tid & 31) == 0) red[tid >> 5] = s;
    __syncthreads();
    if (tid == 0) {
        float tot = 0.f;
#pragma unroll
        for (int j = 0; j < 8; j++) tot += red[j];
        g_scores[blockIdx.x] = tot + bks[0];
    }
}

// ---------------------------------------------------------------------------
// All-4-weights fp32 -> fp16 convert in one launch
// ---------------------------------------------------------------------------
#define NW4 (C_DIM * C_DIM / 4)   // 262144 float4 per weight

__global__ __launch_bounds__(256) void convw_kernel(
    const float4* __restrict__ w0, uint2* __restrict__ d0,
    const float4* __restrict__ w1, uint2* __restrict__ d1,
    const float4* __restrict__ w2, uint2* __restrict__ d2,
    const float4* __restrict__ w3, uint2* __restrict__ d3)
{
    const int nblk = NW4 / 256;   // 1024
    int which = blockIdx.x / nblk;
    int i = (blockIdx.x % nblk) * 256 + threadIdx.x;
    const float4* src = (which == 0) ? w0 : (which == 1) ? w1 : (which == 2) ? w2 : w3;
    uint2* dst = (which == 0) ? d0 : (which == 1) ? d1 : (which == 2) ? d2 : d3;
    float4 v = src[i];
    __half2 a = __floats2half2_rn(v.x, v.y);
    __half2 b = __floats2half2_rn(v.z, v.w);
    dst[i] = make_uint2(*reinterpret_cast<uint32_t*>(&a), *reinterpret_cast<uint32_t*>(&b));
}

// ---------------------------------------------------------------------------
// HMMA GEMM core, fp16: D = Ax*B + bias. 3-stage pipeline, 2 CTAs/SM.
// ---------------------------------------------------------------------------
#define NCHUNK  (C_DIM / 64)   // 16
#define TILE_B  16384
#define STAGE_B 32768
#define NSTAGE  3
#define RU      (C_DIM / 8)

template <bool HALF_OUT>
__device__ __forceinline__ void gemm_core(
    const __half* Ax, const __half* B,
    const float* bias, void* outp, int bm, int bn, char* smem)
{
    const uint32_t sb = smem_to_u32(smem);
    const int tid = threadIdx.x;
    const int wid = tid >> 5;
    const int lane = tid & 31;
    const int warp_m = wid & 3;
    const int warp_n = wid >> 2;

    float acc[2][8][4];
#pragma unroll
    for (int i = 0; i < 2; i++)
#pragma unroll
        for (int j = 0; j < 8; j++)
#pragma unroll
            for (int q = 0; q < 4; q++) acc[i][j][q] = 0.f;

    const uint4* srcs[2] = {
        reinterpret_cast<const uint4*>(Ax) + (size_t)bm * RU,
        reinterpret_cast<const uint4*>(B)  + (size_t)bn * RU };

    const int lrow = tid >> 3;
    const int lch  = tid & 7;

    auto issue = [&](int s, int c) {
        const int kq = c * 8;
        const uint32_t sbase = sb + s * STAGE_B;
#pragma unroll
        for (int t2 = 0; t2 < 2; t2++) {
            const uint4* srow = srcs[t2] + kq;
            const uint32_t dbase = sbase + t2 * TILE_B;
#pragma unroll
            for (int p = 0; p < 4; p++) {
                int row = lrow + p * 32;
                cp16(dbase + SW128(row * 128 + lch * 16),
                     srow + (size_t)row * RU + lch);
            }
        }
        CP_COMMIT();
    };

    issue(0, 0);
    issue(1, 1);
    issue(2, 2);

    const int a_row  = warp_m * 32 + (lane & 15);
    const int a_koff = (lane >> 4) * 16;
    const int b_row  = warp_n * 64 + (lane & 7) + ((lane >> 4) & 1) * 8;
    const int b_koff = ((lane >> 3) & 1) * 16;

    for (int c = 0; c < NCHUNK; c++) {
        const int s = c % NSTAGE;
        if (c < NCHUNK - 2)       { CP_WAIT(2); }
        else if (c == NCHUNK - 2) { CP_WAIT(1); }
        else                      { CP_WAIT(0); }
        __syncthreads();

        const uint32_t aX = sb + s * STAGE_B;
        const uint32_t bB = aX + TILE_B;

#pragma unroll
        for (int ks = 0; ks < 4; ks++) {
            const int akb = ks * 32 + a_koff;
            const int bkb = ks * 32 + b_koff;
            uint32_t ax[2][4], bb[4][4];
#pragma unroll
            for (int mi = 0; mi < 2; mi++) {
                int off = (a_row + mi * 16) * 128 + akb;
                LDSM4(ax[mi], aX + SW128(off));
            }
#pragma unroll
            for (int ni2 = 0; ni2 < 4; ni2++) {
                int off = (b_row + ni2 * 16) * 128 + bkb;
                LDSM4(bb[ni2], bB + SW128(off));
            }
#pragma unroll
            for (int mi = 0; mi < 2; mi++)
#pragma unroll
                for (int ni = 0; ni < 8; ni++)
                    mma16816(acc[mi][ni], ax[mi], &bb[ni >> 1][(ni & 1) * 2]);
        }
        __syncthreads();
        if (c + NSTAGE < NCHUNK) issue(s, c + NSTAGE);
    }

    const int g  = lane >> 2;
    const int tg = lane & 3;
#pragma unroll
    for (int mi = 0; mi < 2; mi++) {
        const int row = bm + warp_m * 32 + mi * 16 + g;
#pragma unroll
        for (int ni = 0; ni < 8; ni++) {
            const int col = bn + warp_n * 64 + ni * 8 + tg * 2;
            float2 bv = *reinterpret_cast<const float2*>(bias + col);
            float o00 = acc[mi][ni][0] + bv.x, o01 = acc[mi][ni][1] + bv.y;
            float o10 = acc[mi][ni][2] + bv.x, o11 = acc[mi][ni][3] + bv.y;
            if (HALF_OUT) {
                __half* out = (__half*)outp;
                __half2 h0 = __floats2half2_rn(o00, o01);
                __half2 h1 = __floats2half2_rn(o10, o11);
                *reinterpret_cast<__half2*>(out + (size_t)row * C_DIM + col) = h0;
                *reinterpret_cast<__half2*>(out + (size_t)(row + 8) * C_DIM + col) = h1;
            } else {
                float* out = (float*)outp;
                *reinterpret_cast<float2*>(out + (size_t)row * C_DIM + col) = make_float2(o00, o01);
                *reinterpret_cast<float2*>(out + (size_t)(row + 8) * C_DIM + col) = make_float2(o10, o11);
            }
        }
    }
}

__global__ __launch_bounds__(256, 2) void gemm_qkv(
    const __half* Ax,
    const __half* B0, const float* bias0, float* out0,
    const __half* B1, const float* bias1, __half* out1,
    const __half* B2, const float* bias2, __half* out2)
{
    extern __shared__ char smem[];
    const int nb = blockIdx.x;
    const int which = nb >> 3;
    const int bn = (nb & 7) << 7;
    const int bm = blockIdx.y << 7;
    if (which == 0) {
        gemm_core<false>(Ax, B0, bias0, out0, bm, bn, smem);
    } else if (which == 1) {
        gemm_core<true>(Ax, B1, bias1, out1, bm, bn, smem);
    } else {
        gemm_core<true>(Ax, B2, bias2, out2, bm, bn, smem);
    }
}

__global__ __launch_bounds__(256, 2) void gemm_tc(
    const __half* Ax, const __half* B, const float* bias, float* out)
{
    extern __shared__ char smem[];
    gemm_core<false>(Ax, B, bias, out, blockIdx.y << 7, blockIdx.x << 7, smem);
}

// ---------------------------------------------------------------------------
// Rank sort, wide decomposition: grid 128 x 256 thr.
// 16 tokens/block, 16 threads/token, each scans 128 scores (32 float4).
// rank = #tokens with higher (score, -idx) priority; g_sorted[rank] = tok.
// ---------------------------------------------------------------------------
__global__ __launch_bounds__(256) void rank_kernel()
{
    __shared__ __align__(16) float ss[T_DIM];
    const int tid = threadIdx.x;
    for (int i = tid; i < T_DIM; i += 256) ss[i] = g_scores[i];
    __syncthreads();

    const int grpl = tid >> 4;          // 0..15: token within block
    const int sub  = tid & 15;          // 0..15: slice within token
    const int tok = blockIdx.x * 16 + grpl;
    const float si = ss[tok];

    const float4* s4 = reinterpret_cast<const float4*>(ss);
    int cnt = 0;
    const int j0 = sub * 32;
#pragma unroll 8
    for (int j4 = j0; j4 < j0 + 32; j4++) {
        float4 v = s4[j4];
        int j = j4 << 2;
        cnt += (v.x > si) || (v.x == si && (j + 0) < tok);
        cnt += (v.y > si) || (v.y == si && (j + 1) < tok);
        cnt += (v.z > si) || (v.z == si && (j + 2) < tok);
        cnt += (v.w > si) || (v.w == si && (j + 3) < tok);
    }
#pragma unroll
    for (int o = 8; o; o >>= 1) cnt += __shfl_down_sync(0xffffffffu, cnt, o, 16);
    if (sub == 0) g_sorted[cnt] = tok;
}

// ---------------------------------------------------------------------------
// Per-group candidate union (one warp per group)
// ---------------------------------------------------------------------------
__global__ void prep_kernel()
{
    int g = blockIdx.x;
    int lane = threadIdx.x;
    int tmin = KSP + g * GQ;
    int tmax = tmin + GQ - 1;
    unsigned lt = (1u << lane) - 1;

    int cmin = 0, kept = 0;
    for (int base = 0; base < T_DIM && cmin < 64; base += 32) {
        int sidx = g_sorted[base + lane];
        bool vmax = (sidx <= tmax);
        unsigned m = __ballot_sync(0xffffffffu, vmax);
        int before = __popc(m & lt);
        if (vmax) g_uidx[g * UMAX + kept + before] = sidx;
        kept += __popc(m);
        cmin += __popc(__ballot_sync(0xffffffffu, sidx <= tmin));
    }
    if (lane == 0) g_ucnt[g] = kept;
}

// ---------------------------------------------------------------------------
// Grouped sparse attention: K/V staged as half2 in SMEM, fp32 accumulation.
// ---------------------------------------------------------------------------
struct AttnSmem {
    __half2 Kc[UMAX][33];   // 32 used + 1 pad (row stride 132B)
    __half2 Vc[UMAX][32];   // row stride 128B, 16B-aligned rows
    float   qs[GQ][64];
    float   lg[GQ][64];
    int     uidx[UMAX];
    short   sel[GQ][64];
    int     ucnt;
};

__global__ __launch_bounds__(512) void attn_group_kernel()
{
    extern __shared__ char sm_raw[];
    AttnSmem& S = *reinterpret_cast<AttnSmem*>(sm_raw);

    const int grp = blockIdx.x;
    const int h   = blockIdx.y;
    const int t0  = KSP + grp * GQ;
    const int base = h * HSIZE;
    const int tid = threadIdx.x;

    if (tid == 0) S.ucnt = g_ucnt[grp];
    if (tid < UMAX) S.uidx[tid] = g_uidx[grp * UMAX + tid];
    __syncthreads();
    const int ucnt = S.ucnt;

    // stage union rows: 8 threads/row, each copies 8 halves of K and V
    for (int r = tid >> 3; r < ucnt; r += 64) {
        int tok = S.uidx[r];
        int c8 = tid & 7;
        uint4 kk = *((const uint4*)(g_kh + (size_t)tok * C_DIM + base) + c8);
        uint4 vv = *((const uint4*)(g_vh + (size_t)tok * C_DIM + base) + c8);
        uint32_t* kd = reinterpret_cast<uint32_t*>(&S.Kc[r][c8 * 4]);
        kd[0] = kk.x; kd[1] = kk.y; kd[2] = kk.z; kd[3] = kk.w;
        *reinterpret_cast<uint4*>(&S.Vc[r][c8 * 4]) = vv;
    }
    for (int i = tid; i < GQ * 64; i += 512)
        S.qs[i >> 6][i & 63] = g_q[(size_t)(t0 + (i >> 6)) * C_DIM + base + (i & 63)];
    __syncthreads();

    const int w = tid >> 5;
    const int lane = tid & 31;
    const int t = t0 + w;
    const unsigned ltm = (1u << lane) - 1;

    int count = 0;
    for (int b2 = 0; b2 < ucnt && count < 64; b2 += 32) {
        int i = b2 + lane;
        bool f = (i < ucnt) && (S.uidx[i] <= t);
        unsigned m = __ballot_sync(0xffffffffu, f);
        int before = __popc(m & ltm);
        if (f && count + before < 64) S.sel[w][count + before] = (short)i;
        count += __popc(m);
    }
    __syncwarp();

    // logits: lane handles selected keys (lane, lane+32)
    const int s0 = S.sel[w][lane];
    const int s1 = S.sel[w][lane + 32];
    float lo0 = 0.f, lo1 = 0.f;
#pragma unroll 8
    for (int d2 = 0; d2 < 32; d2++) {
        float2 k0 = __half22float2(S.Kc[s0][d2]);
        float2 k1 = __half22float2(S.Kc[s1][d2]);
        float q0 = S.qs[w][2 * d2];
        float q1 = S.qs[w][2 * d2 + 1];
        lo0 += q0 * k0.x + q1 * k0.y;
        lo1 += q0 * k1.x + q1 * k1.y;
    }
    lo0 *= 0.125f; lo1 *= 0.125f;

    float m = fmaxf(lo0, lo1);
#pragma unroll
    for (int o = 16; o; o >>= 1) m = fmaxf(m, __shfl_xor_sync(0xffffffffu, m, o));
    float e0 = expf(lo0 - m), e1 = expf(lo1 - m);
    float sum = e0 + e1;
#pragma unroll
    for (int o = 16; o; o >>= 1) sum += __shfl_xor_sync(0xffffffffu, sum, o);
    float inv = 1.f / sum;
    S.lg[w][lane] = e0 * inv;
    S.lg[w][lane + 32] = e1 * inv;
    __syncwarp();

    // PV: lane owns d = 2*lane, 2*lane+1  (Vc[s][lane] conflict-free)
    float a0 = 0.f, a1 = 0.f;
#pragma unroll 8
    for (int j = 0; j < 64; j++) {
        float p = S.lg[w][j];
        float2 vf = __half22float2(S.Vc[S.sel[w][j]][lane]);
        a0 += p * vf.x;
        a1 += p * vf.y;
    }

    size_t off = (size_t)t * C_DIM + base + 2 * lane;
    *reinterpret_cast<__half2*>(g_atq + off) = __floats2half2_rn(a0, a1);
}

// ---------------------------------------------------------------------------
// Small-t attention (t < 64)
// ---------------------------------------------------------------------------
__global__ __launch_bounds__(128) void attn_small_kernel()
{
    const int bid = blockIdx.x;
    const int h = bid & (NHEAD - 1);
    const int t = bid >> 4;
    const int tid = threadIdx.x;
    const int lane = tid & 31;
    const int w = tid >> 5;
    const int base = h * HSIZE;

    __shared__ float qs[HSIZE];
    __shared__ float lg[KSP];
    __shared__ float part[2][HSIZE];

    if (tid < 64) qs[tid] = g_q[(size_t)t * C_DIM + base + tid];
    __syncthreads();

#pragma unroll 1
    for (int j = w * 16; j < w * 16 + 16; j++) {
        int kidx = min(j, t);
        const __half* kr = g_kh + (size_t)kidx * C_DIM + base;
        float p = __half2float(kr[lane]) * qs[lane]
                + __half2float(kr[lane + 32]) * qs[lane + 32];
#pragma unroll
        for (int o = 16; o; o >>= 1) p += __shfl_down_sync(0xffffffffu, p, o);
        if (lane == 0) lg[j] = p * 0.125f;
    }
    __syncthreads();

    if (w == 0) {
        float a = lg[lane], b = lg[lane + 32];
        float m = fmaxf(a, b);
#pragma unroll
        for (int o = 16; o; o >>= 1) m = fmaxf(m, __shfl_xor_sync(0xffffffffu, m, o));
        float e0 = expf(a - m), e1 = expf(b - m);
        float s = e0 + e1;
#pragma unroll
        for (int o = 16; o; o >>= 1) s += __shfl_xor_sync(0xffffffffu, s, o);
        float inv = 1.f / s;
        lg[lane] = e0 * inv;
        lg[lane + 32] = e1 * inv;
    }
    __syncthreads();

    const int half = tid >> 6;
    const int d = tid & 63;
    float acc = 0.f;
#pragma unroll 1
    for (int j = half * 32; j < half * 32 + 32; j++)
        acc += lg[j] * __half2float(g_vh[(size_t)min(j, t) * C_DIM + base + d]);
    part[half][d] = acc;
    __syncthreads();

    if (tid < 64)
        g_atq[(size_t)t * C_DIM + base + tid] =
            __float2half_rn(part[0][tid] + part[1][tid]);
}

// ---------------------------------------------------------------------------
extern "C" void kernel_launch(void* const* d_in, const int* in_sizes, int n_in,
                              void* d_out, int out_size)
{
    const float* x   = (const float*)d_in[0];
    const float* Wq  = (const float*)d_in[1];
    const float* bq  = (const float*)d_in[2];
    const float* Wk  = (const float*)d_in[3];
    const float* bk  = (const float*)d_in[4];
    const float* Wv  = (const float*)d_in[5];
    const float* bv  = (const float*)d_in[6];
    const float* Wo  = (const float*)d_in[7];
    const float* bo  = (const float*)d_in[8];
    const float* Wks = (const float*)d_in[9];
    const float* bks = (const float*)d_in[10];
    float* out = (float*)d_out;

    float* q;
    __half *kh, *vh;
    cudaGetSymbolAddress((void**)&q,  g_q);
    cudaGetSymbolAddress((void**)&kh, g_kh);
    cudaGetSymbolAddress((void**)&vh, g_vh);

    __half *xq, *wq, *wk, *wv, *wo, *atq;
    cudaGetSymbolAddress((void**)&xq,  g_xq);
    cudaGetSymbolAddress((void**)&wq,  g_wq);
    cudaGetSymbolAddress((void**)&wk,  g_wk);
    cudaGetSymbolAddress((void**)&wv,  g_wv);
    cudaGetSymbolAddress((void**)&wo,  g_wo);
    cudaGetSymbolAddress((void**)&atq, g_atq);

    const int gemm_smem = NSTAGE * STAGE_B;            // 98304
    const int attn_smem = (int)sizeof(AttnSmem);
    static bool attr_done = false;
    if (!attr_done) {
        cudaFuncSetAttribute(gemm_qkv, cudaFuncAttributeMaxDynamicSharedMemorySize, gemm_smem);
        cudaFuncSetAttribute(gemm_tc,  cudaFuncAttributeMaxDynamicSharedMemorySize, gemm_smem);
        cudaFuncSetAttribute(attn_group_kernel, cudaFuncAttributeMaxDynamicSharedMemorySize, attn_smem);
        attr_done = true;
    }

    splitx_score_kernel<<<T_DIM, 256>>>((const float4*)x, (uint2*)xq,
                                        (const float4*)Wks, bks);
    convw_kernel<<<4 * (NW4 / 256), 256>>>(
        (const float4*)Wq, (uint2*)wq,
        (const float4*)Wk, (uint2*)wk,
        (const float4*)Wv, (uint2*)wv,
        (const float4*)Wo, (uint2*)wo);

    gemm_qkv<<<dim3(24, 16), 256, gemm_smem>>>(
        xq,
        wq, bq, q,
        wk, bk, kh,
        wv, bv, vh);

    rank_kernel<<<T_DIM / 16, 256>>>();
    prep_kernel<<<NGRP, 32>>>();

    attn_small_kernel<<<KSP * NHEAD, 128>>>();
    attn_group_kernel<<<dim3(NGRP, NHEAD), 512, attn_smem>>>();

    gemm_tc<<<dim3(8, 16), 256, gemm_smem>>>(atq, wo, bo, out);
}

// round 11
// speedup vs baseline: 5.2619x; 1.1047x over previous
#include <cuda_runtime.h>
#include <cuda_fp16.h>
#include <cstdint>

#define T_DIM 2048
#define C_DIM 1024
#define NHEAD 16
#define HSIZE 64
#define KSP   64
#define GQ    16
#define UMAX  128
#define NGRP  ((T_DIM - KSP) / GQ)   // 124

// ---------------- scratch (no allocations allowed) ----------------
__device__ float  g_q[T_DIM * C_DIM];
__device__ __half g_kh[T_DIM * C_DIM];
__device__ __half g_vh[T_DIM * C_DIM];
__device__ float  g_scores[T_DIM];
__device__ int    g_sorted[T_DIM];
__device__ int    g_uidx[NGRP * UMAX];
__device__ int    g_ucnt[NGRP];

// fp16 operands
__device__ __half g_xq[T_DIM * C_DIM];
__device__ __half g_wq[C_DIM * C_DIM];
__device__ __half g_wk[C_DIM * C_DIM];
__device__ __half g_wv[C_DIM * C_DIM];
__device__ __half g_wo[C_DIM * C_DIM];
__device__ __half g_atq[T_DIM * C_DIM];

// ---------------- helpers ----------------
__device__ __forceinline__ uint32_t smem_to_u32(const void* p) {
    uint32_t a;
    asm("{ .reg .u64 t; cvta.to.shared.u64 t, %1; cvt.u32.u64 %0, t; }" : "=r"(a) : "l"(p));
    return a;
}
#define SW128(off) ((off) ^ (((off) >> 3) & 0x70))

__device__ __forceinline__ void cp16(uint32_t dst, const void* src) {
    asm volatile("cp.async.cg.shared.global [%0], [%1], 16;" :: "r"(dst), "l"(src));
}
#define CP_COMMIT() asm volatile("cp.async.commit_group;" ::: "memory")
#define CP_WAIT(n)  asm volatile("cp.async.wait_group %0;" :: "n"(n) : "memory")

#define LDSM4(r, addr) \
    asm volatile("ldmatrix.sync.aligned.m8n8.x4.shared.b16 {%0,%1,%2,%3}, [%4];" \
        : "=r"((r)[0]), "=r"((r)[1]), "=r"((r)[2]), "=r"((r)[3]) : "r"(addr))

__device__ __forceinline__ void mma16816(float* d, const uint32_t* a, const uint32_t* b) {
    asm volatile("mma.sync.aligned.m16n8k16.row.col.f32.f16.f16.f32 "
        "{%0,%1,%2,%3}, {%4,%5,%6,%7}, {%8,%9}, {%0,%1,%2,%3};"
        : "+f"(d[0]), "+f"(d[1]), "+f"(d[2]), "+f"(d[3])
        : "r"(a[0]), "r"(a[1]), "r"(a[2]), "r"(a[3]), "r"(b[0]), "r"(b[1]));
}

// ---------------------------------------------------------------------------
// Fused input prep: blocks [0, 2048) do x->fp16 + key scores (one block/row);
// blocks [2048, 6144) convert the 4 weights to fp16.
// ---------------------------------------------------------------------------
#define NW4 (C_DIM * C_DIM / 4)   // 262144 float4 per weight
#define WBLK (NW4 / 256)          // 1024 blocks per weight

__global__ __launch_bounds__(256) void prep_inputs(
    const float4* __restrict__ x4, uint2* __restrict__ xq,
    const float4* __restrict__ wks4, const float* __restrict__ bks,
    const float4* __restrict__ w0, uint2* __restrict__ d0,
    const float4* __restrict__ w1, uint2* __restrict__ d1,
    const float4* __restrict__ w2, uint2* __restrict__ d2,
    const float4* __restrict__ w3, uint2* __restrict__ d3)
{
    const int tid = threadIdx.x;
    const int bx = blockIdx.x;

    if (bx < T_DIM) {
        // splitx + score path
        const int i = bx * 256 + tid;
        float4 v = x4[i];
        __half2 p0 = __floats2half2_rn(v.x, v.y);
        __half2 p1 = __floats2half2_rn(v.z, v.w);
        xq[i] = make_uint2(*reinterpret_cast<uint32_t*>(&p0), *reinterpret_cast<uint32_t*>(&p1));

        float4 wk = wks4[tid];
        float s = v.x * wk.x + v.y * wk.y + v.z * wk.z + v.w * wk.w;
#pragma unroll
        for (int o = 16; o; o >>= 1) s += __shfl_down_sync(0xffffffffu, s, o);
        __shared__ float red[8];
        if ((tid & 31) == 0) red[tid >> 5] = s;
        __syncthreads();
        if (tid == 0) {
            float tot = 0.f;
#pragma unroll
            for (int j = 0; j < 8; j++) tot += red[j];
            g_scores[bx] = tot + bks[0];
        }
    } else {
        // weight convert path
        const int idx = bx - T_DIM;
        const int which = idx / WBLK;
        const int i = (idx % WBLK) * 256 + tid;
        const float4* src = (which == 0) ? w0 : (which == 1) ? w1 : (which == 2) ? w2 : w3;
        uint2* dst = (which == 0) ? d0 : (which == 1) ? d1 : (which == 2) ? d2 : d3;
        float4 v = src[i];
        __half2 a = __floats2half2_rn(v.x, v.y);
        __half2 b = __floats2half2_rn(v.z, v.w);
        dst[i] = make_uint2(*reinterpret_cast<uint32_t*>(&a), *reinterpret_cast<uint32_t*>(&b));
    }
}

// ---------------------------------------------------------------------------
// Rank-sort body (runs inside gemm_qkv's grid on spare blocks).
// 16 tokens/block, 16 threads/token, each scans 128 scores from SMEM.
// ---------------------------------------------------------------------------
__device__ __forceinline__ void rank_body(char* smem, int rb)
{
    float* ss = reinterpret_cast<float*>(smem);
    const int tid = threadIdx.x;
    for (int i = tid; i < T_DIM; i += 256) ss[i] = g_scores[i];
    __syncthreads();

    const int grpl = tid >> 4;
    const int sub  = tid & 15;
    const int tok = rb * 16 + grpl;
    const float si = ss[tok];

    const float4* s4 = reinterpret_cast<const float4*>(ss);
    int cnt = 0;
    const int j0 = sub * 32;
#pragma unroll 8
    for (int j4 = j0; j4 < j0 + 32; j4++) {
        float4 v = s4[j4];
        int j = j4 << 2;
        cnt += (v.x > si) || (v.x == si && (j + 0) < tok);
        cnt += (v.y > si) || (v.y == si && (j + 1) < tok);
        cnt += (v.z > si) || (v.z == si && (j + 2) < tok);
        cnt += (v.w > si) || (v.w == si && (j + 3) < tok);
    }
#pragma unroll
    for (int o = 8; o; o >>= 1) cnt += __shfl_down_sync(0xffffffffu, cnt, o, 16);
    if (sub == 0) g_sorted[cnt] = tok;
}

// ---------------------------------------------------------------------------
// HMMA GEMM core, fp16: D = Ax*B + bias. 3-stage pipeline, 2 CTAs/SM.
// ---------------------------------------------------------------------------
#define NCHUNK  (C_DIM / 64)   // 16
#define TILE_B  16384
#define STAGE_B 32768
#define NSTAGE  3
#define RU      (C_DIM / 8)

template <bool HALF_OUT>
__device__ __forceinline__ void gemm_core(
    const __half* Ax, const __half* B,
    const float* bias, void* outp, int bm, int bn, char* smem)
{
    const uint32_t sb = smem_to_u32(smem);
    const int tid = threadIdx.x;
    const int wid = tid >> 5;
    const int lane = tid & 31;
    const int warp_m = wid & 3;
    const int warp_n = wid >> 2;

    float acc[2][8][4];
#pragma unroll
    for (int i = 0; i < 2; i++)
#pragma unroll
        for (int j = 0; j < 8; j++)
#pragma unroll
            for (int q = 0; q < 4; q++) acc[i][j][q] = 0.f;

    const uint4* srcs[2] = {
        reinterpret_cast<const uint4*>(Ax) + (size_t)bm * RU,
        reinterpret_cast<const uint4*>(B)  + (size_t)bn * RU };

    const int lrow = tid >> 3;
    const int lch  = tid & 7;

    auto issue = [&](int s, int c) {
        const int kq = c * 8;
        const uint32_t sbase = sb + s * STAGE_B;
#pragma unroll
        for (int t2 = 0; t2 < 2; t2++) {
            const uint4* srow = srcs[t2] + kq;
            const uint32_t dbase = sbase + t2 * TILE_B;
#pragma unroll
            for (int p = 0; p < 4; p++) {
                int row = lrow + p * 32;
                cp16(dbase + SW128(row * 128 + lch * 16),
                     srow + (size_t)row * RU + lch);
            }
        }
        CP_COMMIT();
    };

    issue(0, 0);
    issue(1, 1);
    issue(2, 2);

    const int a_row  = warp_m * 32 + (lane & 15);
    const int a_koff = (lane >> 4) * 16;
    const int b_row  = warp_n * 64 + (lane & 7) + ((lane >> 4) & 1) * 8;
    const int b_koff = ((lane >> 3) & 1) * 16;

    for (int c = 0; c < NCHUNK; c++) {
        const int s = c % NSTAGE;
        if (c < NCHUNK - 2)       { CP_WAIT(2); }
        else if (c == NCHUNK - 2) { CP_WAIT(1); }
        else                      { CP_WAIT(0); }
        __syncthreads();

        const uint32_t aX = sb + s * STAGE_B;
        const uint32_t bB = aX + TILE_B;

#pragma unroll
        for (int ks = 0; ks < 4; ks++) {
            const int akb = ks * 32 + a_koff;
            const int bkb = ks * 32 + b_koff;
            uint32_t ax[2][4], bb[4][4];
#pragma unroll
            for (int mi = 0; mi < 2; mi++) {
                int off = (a_row + mi * 16) * 128 + akb;
                LDSM4(ax[mi], aX + SW128(off));
            }
#pragma unroll
            for (int ni2 = 0; ni2 < 4; ni2++) {
                int off = (b_row + ni2 * 16) * 128 + bkb;
                LDSM4(bb[ni2], bB + SW128(off));
            }
#pragma unroll
            for (int mi = 0; mi < 2; mi++)
#pragma unroll
                for (int ni = 0; ni < 8; ni++)
                    mma16816(acc[mi][ni], ax[mi], &bb[ni >> 1][(ni & 1) * 2]);
        }
        __syncthreads();
        if (c + NSTAGE < NCHUNK) issue(s, c + NSTAGE);
    }

    const int g  = lane >> 2;
    const int tg = lane & 3;
#pragma unroll
    for (int mi = 0; mi < 2; mi++) {
        const int row = bm + warp_m * 32 + mi * 16 + g;
#pragma unroll
        for (int ni = 0; ni < 8; ni++) {
            const int col = bn + warp_n * 64 + ni * 8 + tg * 2;
            float2 bv = *reinterpret_cast<const float2*>(bias + col);
            float o00 = acc[mi][ni][0] + bv.x, o01 = acc[mi][ni][1] + bv.y;
            float o10 = acc[mi][ni][2] + bv.x, o11 = acc[mi][ni][3] + bv.y;
            if (HALF_OUT) {
                __half* out = (__half*)outp;
                __half2 h0 = __floats2half2_rn(o00, o01);
                __half2 h1 = __floats2half2_rn(o10, o11);
                *reinterpret_cast<__half2*>(out + (size_t)row * C_DIM + col) = h0;
                *reinterpret_cast<__half2*>(out + (size_t)(row + 8) * C_DIM + col) = h1;
            } else {
                float* out = (float*)outp;
                *reinterpret_cast<float2*>(out + (size_t)row * C_DIM + col) = make_float2(o00, o01);
                *reinterpret_cast<float2*>(out + (size_t)(row + 8) * C_DIM + col) = make_float2(o10, o11);
            }
        }
    }
}

// Fused QKV + rank: grid (32, 16). nb<24: GEMM tiles; nb>=24: rank blocks.
__global__ __launch_bounds__(256, 2) void gemm_qkv(
    const __half* Ax,
    const __half* B0, const float* bias0, float* out0,
    const __half* B1, const float* bias1, __half* out1,
    const __half* B2, const float* bias2, __half* out2)
{
    extern __shared__ char smem[];
    const int nb = blockIdx.x;
    if (nb >= 24) {
        rank_body(smem, (nb - 24) + blockIdx.y * 8);   // 128 rank blocks
        return;
    }
    const int which = nb >> 3;
    const int bn = (nb & 7) << 7;
    const int bm = blockIdx.y << 7;
    if (which == 0) {
        gemm_core<false>(Ax, B0, bias0, out0, bm, bn, smem);
    } else if (which == 1) {
        gemm_core<true>(Ax, B1, bias1, out1, bm, bn, smem);
    } else {
        gemm_core<true>(Ax, B2, bias2, out2, bm, bn, smem);
    }
}

__global__ __launch_bounds__(256, 2) void gemm_tc(
    const __half* Ax, const __half* B, const float* bias, float* out)
{
    extern __shared__ char smem[];
    gemm_core<false>(Ax, B, bias, out, blockIdx.y << 7, blockIdx.x << 7, smem);
}

// ---------------------------------------------------------------------------
// Per-group candidate union (one warp per group)
// ---------------------------------------------------------------------------
__global__ void prep_kernel()
{
    int g = blockIdx.x;
    int lane = threadIdx.x;
    int tmin = KSP + g * GQ;
    int tmax = tmin + GQ - 1;
    unsigned lt = (1u << lane) - 1;

    int cmin = 0, kept = 0;
    for (int base = 0; base < T_DIM && cmin < 64; base += 32) {
        int sidx = g_sorted[base + lane];
        bool vmax = (sidx <= tmax);
        unsigned m = __ballot_sync(0xffffffffu, vmax);
        int before = __popc(m & lt);
        if (vmax) g_uidx[g * UMAX + kept + before] = sidx;
        kept += __popc(m);
        cmin += __popc(__ballot_sync(0xffffffffu, sidx <= tmin));
    }
    if (lane == 0) g_ucnt[g] = kept;
}

// ---------------------------------------------------------------------------
// Grouped sparse attention (now also covers t < 64 via groups >= NGRP).
// K/V staged as half2 in SMEM, fp32 accumulation.
// ---------------------------------------------------------------------------
struct AttnSmem {
    __half2 Kc[UMAX][33];
    __half2 Vc[UMAX][32];
    float   qs[GQ][64];
    float   lg[GQ][64];
    int     uidx[UMAX];
    short   sel[GQ][64];
    int     ucnt;
};

__global__ __launch_bounds__(512) void attn_group_kernel()
{
    extern __shared__ char sm_raw[];
    AttnSmem& S = *reinterpret_cast<AttnSmem*>(sm_raw);

    const int grp = blockIdx.x;
    const int h   = blockIdx.y;
    const bool small = (grp >= NGRP);
    const int t0  = small ? (grp - NGRP) * GQ : KSP + grp * GQ;
    const int base = h * HSIZE;
    const int tid = threadIdx.x;

    if (small) {
        if (tid == 0) S.ucnt = 64;
        if (tid < 64) S.uidx[tid] = tid;
    } else {
        if (tid == 0) S.ucnt = g_ucnt[grp];
        if (tid < UMAX) S.uidx[tid] = g_uidx[grp * UMAX + tid];
    }
    __syncthreads();
    const int ucnt = S.ucnt;

    // stage union rows: 8 threads/row, each copies 8 halves of K and V
    for (int r = tid >> 3; r < ucnt; r += 64) {
        int tok = S.uidx[r];
        int c8 = tid & 7;
        uint4 kk = *((const uint4*)(g_kh + (size_t)tok * C_DIM + base) + c8);
        uint4 vv = *((const uint4*)(g_vh + (size_t)tok * C_DIM + base) + c8);
        uint32_t* kd = reinterpret_cast<uint32_t*>(&S.Kc[r][c8 * 4]);
        kd[0] = kk.x; kd[1] = kk.y; kd[2] = kk.z; kd[3] = kk.w;
        *reinterpret_cast<uint4*>(&S.Vc[r][c8 * 4]) = vv;
    }
    for (int i = tid; i < GQ * 64; i += 512)
        S.qs[i >> 6][i & 63] = g_q[(size_t)(t0 + (i >> 6)) * C_DIM + base + (i & 63)];
    __syncthreads();

    const int w = tid >> 5;
    const int lane = tid & 31;
    const int t = t0 + w;
    const unsigned ltm = (1u << lane) - 1;

    if (small) {
        S.sel[w][lane]      = (short)min(lane, t);
        S.sel[w][lane + 32] = (short)min(lane + 32, t);
    } else {
        int count = 0;
        for (int b2 = 0; b2 < ucnt && count < 64; b2 += 32) {
            int i = b2 + lane;
            bool f = (i < ucnt) && (S.uidx[i] <= t);
            unsigned m = __ballot_sync(0xffffffffu, f);
            int before = __popc(m & ltm);
            if (f && count + before < 64) S.sel[w][count + before] = (short)i;
            count += __popc(m);
        }
    }
    __syncwarp();

    // logits: lane handles selected keys (lane, lane+32)
    const int s0 = S.sel[w][lane];
    const int s1 = S.sel[w][lane + 32];
    float lo0 = 0.f, lo1 = 0.f;
#pragma unroll 8
    for (int d2 = 0; d2 < 32; d2++) {
        float2 k0 = __half22float2(S.Kc[s0][d2]);
        float2 k1 = __half22float2(S.Kc[s1][d2]);
        float q0 = S.qs[w][2 * d2];
        float q1 = S.qs[w][2 * d2 + 1];
        lo0 += q0 * k0.x + q1 * k0.y;
        lo1 += q0 * k1.x + q1 * k1.y;
    }
    lo0 *= 0.125f; lo1 *= 0.125f;

    float m = fmaxf(lo0, lo1);
#pragma unroll
    for (int o = 16; o; o >>= 1) m = fmaxf(m, __shfl_xor_sync(0xffffffffu, m, o));
    float e0 = expf(lo0 - m), e1 = expf(lo1 - m);
    float sum = e0 + e1;
#pragma unroll
    for (int o = 16; o; o >>= 1) sum += __shfl_xor_sync(0xffffffffu, sum, o);
    float inv = 1.f / sum;
    S.lg[w][lane] = e0 * inv;
    S.lg[w][lane + 32] = e1 * inv;
    __syncwarp();

    // PV: lane owns d = 2*lane, 2*lane+1
    float a0 = 0.f, a1 = 0.f;
#pragma unroll 8
    for (int j = 0; j < 64; j++) {
        float p = S.lg[w][j];
        float2 vf = __half22float2(S.Vc[S.sel[w][j]][lane]);
        a0 += p * vf.x;
        a1 += p * vf.y;
    }

    size_t off = (size_t)t * C_DIM + base + 2 * lane;
    *reinterpret_cast<__half2*>(g_atq + off) = __floats2half2_rn(a0, a1);
}

// ---------------------------------------------------------------------------
extern "C" void kernel_launch(void* const* d_in, const int* in_sizes, int n_in,
                              void* d_out, int out_size)
{
    const float* x   = (const float*)d_in[0];
    const float* Wq  = (const float*)d_in[1];
    const float* bq  = (const float*)d_in[2];
    const float* Wk  = (const float*)d_in[3];
    const float* bk  = (const float*)d_in[4];
    const float* Wv  = (const float*)d_in[5];
    const float* bv  = (const float*)d_in[6];
    const float* Wo  = (const float*)d_in[7];
    const float* bo  = (const float*)d_in[8];
    const float* Wks = (const float*)d_in[9];
    const float* bks = (const float*)d_in[10];
    float* out = (float*)d_out;

    float* q;
    __half *kh, *vh;
    cudaGetSymbolAddress((void**)&q,  g_q);
    cudaGetSymbolAddress((void**)&kh, g_kh);
    cudaGetSymbolAddress((void**)&vh, g_vh);

    __half *xq, *wq, *wk, *wv, *wo, *atq;
    cudaGetSymbolAddress((void**)&xq,  g_xq);
    cudaGetSymbolAddress((void**)&wq,  g_wq);
    cudaGetSymbolAddress((void**)&wk,  g_wk);
    cudaGetSymbolAddress((void**)&wv,  g_wv);
    cudaGetSymbolAddress((void**)&wo,  g_wo);
    cudaGetSymbolAddress((void**)&atq, g_atq);

    const int gemm_smem = NSTAGE * STAGE_B;            // 98304
    const int attn_smem = (int)sizeof(AttnSmem);
    static bool attr_done = false;
    if (!attr_done) {
        cudaFuncSetAttribute(gemm_qkv, cudaFuncAttributeMaxDynamicSharedMemorySize, gemm_smem);
        cudaFuncSetAttribute(gemm_tc,  cudaFuncAttributeMaxDynamicSharedMemorySize, gemm_smem);
        cudaFuncSetAttribute(attn_group_kernel, cudaFuncAttributeMaxDynamicSharedMemorySize, attn_smem);
        attr_done = true;
    }

    // fused x-convert + key scores + all weight converts (one launch)
    prep_inputs<<<T_DIM + 4 * WBLK, 256>>>(
        (const float4*)x, (uint2*)xq, (const float4*)Wks, bks,
        (const float4*)Wq, (uint2*)wq,
        (const float4*)Wk, (uint2*)wk,
        (const float4*)Wv, (uint2*)wv,
        (const float4*)Wo, (uint2*)wo);

    // fused QKV GEMM + rank sort (rank blocks ride along in the same grid)
    gemm_qkv<<<dim3(32, 16), 256, gemm_smem>>>(
        xq,
        wq, bq, q,
        wk, bk, kh,
        wv, bv, vh);

    prep_kernel<<<NGRP, 32>>>();

    // grouped attention covers all t (groups >= NGRP handle t < 64)
    attn_group_kernel<<<dim3(NGRP + KSP / GQ, NHEAD), 512, attn_smem>>>();

    gemm_tc<<<dim3(8, 16), 256, gemm_smem>>>(atq, wo, bo, out);
}

// round 12
// speedup vs baseline: 6.5698x; 1.2486x over previous
#include <cuda_runtime.h>
#include <cuda_fp16.h>
#include <cstdint>

#define T_DIM 2048
#define C_DIM 1024
#define NHEAD 16
#define HSIZE 64
#define KSP   64
#define GQ    16
#define UMAX  128
#define NGRP  ((T_DIM - KSP) / GQ)   // 124

// ---------------- scratch (no allocations allowed) ----------------
__device__ __half   g_qh[T_DIM * C_DIM];   // Q in fp16, pre-scaled by 0.125
__device__ __half   g_kh[T_DIM * C_DIM];
__device__ __half   g_vh[T_DIM * C_DIM];
__device__ float    g_scores[T_DIM];
__device__ int      g_sorted[T_DIM];
__device__ int      g_uidx[NGRP * UMAX];
__device__ int      g_ucnt[NGRP];
__device__ uint32_t g_mask[NGRP * GQ * 4];

__device__ __half g_xq[T_DIM * C_DIM];
__device__ __half g_wq[C_DIM * C_DIM];
__device__ __half g_wk[C_DIM * C_DIM];
__device__ __half g_wv[C_DIM * C_DIM];
__device__ __half g_wo[C_DIM * C_DIM];
__device__ __half g_atq[T_DIM * C_DIM];

// ---------------- helpers ----------------
__device__ __forceinline__ uint32_t smem_to_u32(const void* p) {
    uint32_t a;
    asm("{ .reg .u64 t; cvta.to.shared.u64 t, %1; cvt.u32.u64 %0, t; }" : "=r"(a) : "l"(p));
    return a;
}
#define SW128(off) ((off) ^ (((off) >> 3) & 0x70))
#define SW256(off) ((off) ^ (((off) >> 4) & 0x70))

__device__ __forceinline__ void cp16(uint32_t dst, const void* src) {
    asm volatile("cp.async.cg.shared.global [%0], [%1], 16;" :: "r"(dst), "l"(src));
}
#define CP_COMMIT() asm volatile("cp.async.commit_group;" ::: "memory")
#define CP_WAIT(n)  asm volatile("cp.async.wait_group %0;" :: "n"(n) : "memory")

#define LDSM4(r, addr) \
    asm volatile("ldmatrix.sync.aligned.m8n8.x4.shared.b16 {%0,%1,%2,%3}, [%4];" \
        : "=r"((r)[0]), "=r"((r)[1]), "=r"((r)[2]), "=r"((r)[3]) : "r"(addr))
#define LDSM4_T(r, addr) \
    asm volatile("ldmatrix.sync.aligned.m8n8.x4.trans.shared.b16 {%0,%1,%2,%3}, [%4];" \
        : "=r"((r)[0]), "=r"((r)[1]), "=r"((r)[2]), "=r"((r)[3]) : "r"(addr))

__device__ __forceinline__ void mma16816(float* d, const uint32_t* a, const uint32_t* b) {
    asm volatile("mma.sync.aligned.m16n8k16.row.col.f32.f16.f16.f32 "
        "{%0,%1,%2,%3}, {%4,%5,%6,%7}, {%8,%9}, {%0,%1,%2,%3};"
        : "+f"(d[0]), "+f"(d[1]), "+f"(d[2]), "+f"(d[3])
        : "r"(a[0]), "r"(a[1]), "r"(a[2]), "r"(a[3]), "r"(b[0]), "r"(b[1]));
}

// ---------------------------------------------------------------------------
// Fused input prep: blocks [0, 2048): x->fp16 + key scores; rest: weights.
// ---------------------------------------------------------------------------
#define NW4 (C_DIM * C_DIM / 4)
#define WBLK (NW4 / 256)

__global__ __launch_bounds__(256) void prep_inputs(
    const float4* __restrict__ x4, uint2* __restrict__ xq,
    const float4* __restrict__ wks4, const float* __restrict__ bks,
    const float4* __restrict__ w0, uint2* __restrict__ d0,
    const float4* __restrict__ w1, uint2* __restrict__ d1,
    const float4* __restrict__ w2, uint2* __restrict__ d2,
    const float4* __restrict__ w3, uint2* __restrict__ d3)
{
    const int tid = threadIdx.x;
    const int bx = blockIdx.x;

    if (bx < T_DIM) {
        const int i = bx * 256 + tid;
        float4 v = x4[i];
        __half2 p0 = __floats2half2_rn(v.x, v.y);
        __half2 p1 = __floats2half2_rn(v.z, v.w);
        xq[i] = make_uint2(*reinterpret_cast<uint32_t*>(&p0), *reinterpret_cast<uint32_t*>(&p1));

        float4 wk = wks4[tid];
        float s = v.x * wk.x + v.y * wk.y + v.z * wk.z + v.w * wk.w;
#pragma unroll
        for (int o = 16; o; o >>= 1) s += __shfl_down_sync(0xffffffffu, s, o);
        __shared__ float red[8];
        if ((tid & 31) == 0) red[tid >> 5] = s;
        __syncthreads();
        if (tid == 0) {
            float tot = 0.f;
#pragma unroll
            for (int j = 0; j < 8; j++) tot += red[j];
            g_scores[bx] = tot + bks[0];
        }
    } else {
        const int idx = bx - T_DIM;
        const int which = idx / WBLK;
        const int i = (idx % WBLK) * 256 + tid;
        const float4* src = (which == 0) ? w0 : (which == 1) ? w1 : (which == 2) ? w2 : w3;
        uint2* dst = (which == 0) ? d0 : (which == 1) ? d1 : (which == 2) ? d2 : d3;
        float4 v = src[i];
        __half2 a = __floats2half2_rn(v.x, v.y);
        __half2 b = __floats2half2_rn(v.z, v.w);
        dst[i] = make_uint2(*reinterpret_cast<uint32_t*>(&a), *reinterpret_cast<uint32_t*>(&b));
    }
}

// ---------------------------------------------------------------------------
// Rank-sort body (rides inside gemm_qkv's grid)
// ---------------------------------------------------------------------------
__device__ __forceinline__ void rank_body(char* smem, int rb)
{
    float* ss = reinterpret_cast<float*>(smem);
    const int tid = threadIdx.x;
    for (int i = tid; i < T_DIM; i += 256) ss[i] = g_scores[i];
    __syncthreads();

    const int grpl = tid >> 4;
    const int sub  = tid & 15;
    const int tok = rb * 16 + grpl;
    const float si = ss[tok];

    const float4* s4 = reinterpret_cast<const float4*>(ss);
    int cnt = 0;
    const int j0 = sub * 32;
#pragma unroll 8
    for (int j4 = j0; j4 < j0 + 32; j4++) {
        float4 v = s4[j4];
        int j = j4 << 2;
        cnt += (v.x > si) || (v.x == si && (j + 0) < tok);
        cnt += (v.y > si) || (v.y == si && (j + 1) < tok);
        cnt += (v.z > si) || (v.z == si && (j + 2) < tok);
        cnt += (v.w > si) || (v.w == si && (j + 3) < tok);
    }
#pragma unroll
    for (int o = 8; o; o >>= 1) cnt += __shfl_down_sync(0xffffffffu, cnt, o, 16);
    if (sub == 0) g_sorted[cnt] = tok;
}

// ---------------------------------------------------------------------------
// HMMA GEMM core: D = (Ax*B + bias) * scale. 3-stage, 2 CTAs/SM.
// ---------------------------------------------------------------------------
#define NCHUNK  (C_DIM / 64)
#define TILE_B  16384
#define STAGE_B 32768
#define NSTAGE  3
#define RU      (C_DIM / 8)

template <bool HALF_OUT>
__device__ __forceinline__ void gemm_core(
    const __half* Ax, const __half* B,
    const float* bias, void* outp, int bm, int bn, char* smem, float scale)
{
    const uint32_t sb = smem_to_u32(smem);
    const int tid = threadIdx.x;
    const int wid = tid >> 5;
    const int lane = tid & 31;
    const int warp_m = wid & 3;
    const int warp_n = wid >> 2;

    float acc[2][8][4];
#pragma unroll
    for (int i = 0; i < 2; i++)
#pragma unroll
        for (int j = 0; j < 8; j++)
#pragma unroll
            for (int q = 0; q < 4; q++) acc[i][j][q] = 0.f;

    const uint4* srcs[2] = {
        reinterpret_cast<const uint4*>(Ax) + (size_t)bm * RU,
        reinterpret_cast<const uint4*>(B)  + (size_t)bn * RU };

    const int lrow = tid >> 3;
    const int lch  = tid & 7;

    auto issue = [&](int s, int c) {
        const int kq = c * 8;
        const uint32_t sbase = sb + s * STAGE_B;
#pragma unroll
        for (int t2 = 0; t2 < 2; t2++) {
            const uint4* srow = srcs[t2] + kq;
            const uint32_t dbase = sbase + t2 * TILE_B;
#pragma unroll
            for (int p = 0; p < 4; p++) {
                int row = lrow + p * 32;
                cp16(dbase + SW128(row * 128 + lch * 16),
                     srow + (size_t)row * RU + lch);
            }
        }
        CP_COMMIT();
    };

    issue(0, 0);
    issue(1, 1);
    issue(2, 2);

    const int a_row  = warp_m * 32 + (lane & 15);
    const int a_koff = (lane >> 4) * 16;
    const int b_row  = warp_n * 64 + (lane & 7) + ((lane >> 4) & 1) * 8;
    const int b_koff = ((lane >> 3) & 1) * 16;

    for (int c = 0; c < NCHUNK; c++) {
        const int s = c % NSTAGE;
        if (c < NCHUNK - 2)       { CP_WAIT(2); }
        else if (c == NCHUNK - 2) { CP_WAIT(1); }
        else                      { CP_WAIT(0); }
        __syncthreads();

        const uint32_t aX = sb + s * STAGE_B;
        const uint32_t bB = aX + TILE_B;

#pragma unroll
        for (int ks = 0; ks < 4; ks++) {
            const int akb = ks * 32 + a_koff;
            const int bkb = ks * 32 + b_koff;
            uint32_t ax[2][4], bb[4][4];
#pragma unroll
            for (int mi = 0; mi < 2; mi++) {
                int off = (a_row + mi * 16) * 128 + akb;
                LDSM4(ax[mi], aX + SW128(off));
            }
#pragma unroll
            for (int ni2 = 0; ni2 < 4; ni2++) {
                int off = (b_row + ni2 * 16) * 128 + bkb;
                LDSM4(bb[ni2], bB + SW128(off));
            }
#pragma unroll
            for (int mi = 0; mi < 2; mi++)
#pragma unroll
                for (int ni = 0; ni < 8; ni++)
                    mma16816(acc[mi][ni], ax[mi], &bb[ni >> 1][(ni & 1) * 2]);
        }
        __syncthreads();
        if (c + NSTAGE < NCHUNK) issue(s, c + NSTAGE);
    }

    const int g  = lane >> 2;
    const int tg = lane & 3;
#pragma unroll
    for (int mi = 0; mi < 2; mi++) {
        const int row = bm + warp_m * 32 + mi * 16 + g;
#pragma unroll
        for (int ni = 0; ni < 8; ni++) {
            const int col = bn + warp_n * 64 + ni * 8 + tg * 2;
            float2 bv = *reinterpret_cast<const float2*>(bias + col);
            float o00 = (acc[mi][ni][0] + bv.x) * scale, o01 = (acc[mi][ni][1] + bv.y) * scale;
            float o10 = (acc[mi][ni][2] + bv.x) * scale, o11 = (acc[mi][ni][3] + bv.y) * scale;
            if (HALF_OUT) {
                __half* out = (__half*)outp;
                __half2 h0 = __floats2half2_rn(o00, o01);
                __half2 h1 = __floats2half2_rn(o10, o11);
                *reinterpret_cast<__half2*>(out + (size_t)row * C_DIM + col) = h0;
                *reinterpret_cast<__half2*>(out + (size_t)(row + 8) * C_DIM + col) = h1;
            } else {
                float* out = (float*)outp;
                *reinterpret_cast<float2*>(out + (size_t)row * C_DIM + col) = make_float2(o00, o01);
                *reinterpret_cast<float2*>(out + (size_t)(row + 8) * C_DIM + col) = make_float2(o10, o11);
            }
        }
    }
}

// Fused QKV + rank: grid (32, 16). nb<24: GEMM tiles; nb>=24: rank blocks.
__global__ __launch_bounds__(256, 2) void gemm_qkv(
    const __half* Ax,
    const __half* B0, const float* bias0, __half* out0,
    const __half* B1, const float* bias1, __half* out1,
    const __half* B2, const float* bias2, __half* out2)
{
    extern __shared__ char smem[];
    const int nb = blockIdx.x;
    if (nb >= 24) {
        rank_body(smem, (nb - 24) + blockIdx.y * 8);
        return;
    }
    const int which = nb >> 3;
    const int bn = (nb & 7) << 7;
    const int bm = blockIdx.y << 7;
    if (which == 0) {
        gemm_core<true>(Ax, B0, bias0, out0, bm, bn, smem, 0.125f);  // Q pre-scaled
    } else if (which == 1) {
        gemm_core<true>(Ax, B1, bias1, out1, bm, bn, smem, 1.0f);
    } else {
        gemm_core<true>(Ax, B2, bias2, out2, bm, bn, smem, 1.0f);
    }
}

__global__ __launch_bounds__(256, 2) void gemm_tc(
    const __half* Ax, const __half* B, const float* bias, float* out)
{
    extern __shared__ char smem[];
    gemm_core<false>(Ax, B, bias, out, blockIdx.y << 7, blockIdx.x << 7, smem, 1.0f);
}

// ---------------------------------------------------------------------------
// Per-group union + per-query 128-bit masks (one warp per group)
// ---------------------------------------------------------------------------
__global__ void prep_kernel()
{
    __shared__ int u[UMAX];
    const int g = blockIdx.x;
    const int lane = threadIdx.x;
    const int tmin = KSP + g * GQ;
    const int tmax = tmin + GQ - 1;
    const unsigned lt = (1u << lane) - 1;

    int cmin = 0, kept = 0;
    for (int base = 0; base < T_DIM && cmin < 64; base += 32) {
        int sidx = g_sorted[base + lane];
        bool vmax = (sidx <= tmax);
        unsigned m = __ballot_sync(0xffffffffu, vmax);
        int before = __popc(m & lt);
        if (vmax && kept + before < UMAX) u[kept + before] = sidx;
        kept += __popc(m);
        cmin += __popc(__ballot_sync(0xffffffffu, sidx <= tmin));
    }
    if (kept > UMAX) kept = UMAX;
    if (lane == 0) g_ucnt[g] = kept;
    __syncwarp();

    int uu[4];
#pragma unroll
    for (int c = 0; c < 4; c++) {
        int i = c * 32 + lane;
        uu[c] = (i < kept) ? u[i] : (1 << 30);
        g_uidx[g * UMAX + i] = uu[c];
    }

#pragma unroll 1
    for (int tq = 0; tq < GQ; tq++) {
        int t = tmin + tq;
        int cum = 0;
#pragma unroll
        for (int c = 0; c < 4; c++) {
            bool f = (uu[c] <= t);
            unsigned m = __ballot_sync(0xffffffffu, f);
            int before = __popc(m & lt) + cum;
            unsigned mm = __ballot_sync(0xffffffffu, f && before < 64);
            if (lane == 0) g_mask[(g * GQ + tq) * 4 + c] = mm;
            cum += __popc(m);
        }
    }
}

// ---------------------------------------------------------------------------
// MMA grouped attention: block = (group, head), 128 thr (4 warps).
// Logits 16x128 via HMMA, masked softmax, PV via HMMA (ldmatrix.trans V).
// Groups >= NGRP handle t<64 via weighted-exp (matches reference multiset).
// ---------------------------------------------------------------------------
struct AttnSmem {
    __half   Kc[128 * 64];   // 16 KB, SW128
    __half   Vc[128 * 64];   // 16 KB, SW128
    __half   Qs[16 * 64];    //  2 KB, SW128
    __half   Ps[16 * 128];   //  4 KB, SW256
    float    pmax[4][16];
    float    psum[4][16];
    int      uidx[UMAX];
    uint32_t mask[GQ][4];
    int      ucnt;
};

__global__ __launch_bounds__(128) void attn_mma_kernel()
{
    extern __shared__ char sm_raw[];
    AttnSmem& S = *reinterpret_cast<AttnSmem*>(sm_raw);

    const int grp = blockIdx.x;
    const int h   = blockIdx.y;
    const bool small = (grp >= NGRP);
    const int t0  = small ? (grp - NGRP) * GQ : KSP + grp * GQ;
    const int base = h * HSIZE;
    const int tid = threadIdx.x;
    const int w = tid >> 5;
    const int lane = tid & 31;

    if (small) {
        if (tid == 0) S.ucnt = 64;
        if (tid < 64) S.uidx[tid] = tid;
    } else {
        if (tid == 0) S.ucnt = g_ucnt[grp];
        if (tid < UMAX) S.uidx[tid] = g_uidx[grp * UMAX + tid];
        if (tid < 64)
            S.mask[tid >> 2][tid & 3] = g_mask[(grp * GQ + (tid >> 2)) * 4 + (tid & 3)];
    }
    __syncthreads();
    const int ucnt = S.ucnt;

    const uint32_t kbase = smem_to_u32(S.Kc);
    const uint32_t vbase = smem_to_u32(S.Vc);
    const uint32_t qbase = smem_to_u32(S.Qs);
    const uint32_t pbase = smem_to_u32(S.Ps);
    char* kc = reinterpret_cast<char*>(S.Kc);
    char* vc = reinterpret_cast<char*>(S.Vc);
    char* qc = reinterpret_cast<char*>(S.Qs);
    char* pc = reinterpret_cast<char*>(S.Ps);

    // stage K/V (zero-pad to 128 rows), 8 threads/row
    const int c8 = tid & 7;
    for (int r = tid >> 3; r < 128; r += 16) {
        uint4 kk = make_uint4(0, 0, 0, 0), vv = kk;
        if (r < ucnt) {
            int tok = S.uidx[r];
            kk = *((const uint4*)(g_kh + (size_t)tok * C_DIM + base) + c8);
            vv = *((const uint4*)(g_vh + (size_t)tok * C_DIM + base) + c8);
        }
        *reinterpret_cast<uint4*>(kc + SW128(r * 128 + c8 * 16)) = kk;
        *reinterpret_cast<uint4*>(vc + SW128(r * 128 + c8 * 16)) = vv;
    }
    {   // Q: 16 rows x 8 chunks
        int r = tid >> 3;
        uint4 qq = *((const uint4*)(g_qh + (size_t)(t0 + r) * C_DIM + base) + c8);
        *reinterpret_cast<uint4*>(qc + SW128(r * 128 + c8 * 16)) = qq;
    }
    __syncthreads();

    // ---- logits: warp w covers keys [w*32, w*32+32) ----
    float d[4][4];
#pragma unroll
    for (int i = 0; i < 4; i++)
#pragma unroll
        for (int j = 0; j < 4; j++) d[i][j] = 0.f;

    const int a_row = lane & 15;
    const int a_k16 = (lane >> 4) * 16;
    const int b_row = (lane & 7) + ((lane >> 4) & 1) * 8;
    const int b_k16 = ((lane >> 3) & 1) * 16;

#pragma unroll
    for (int ks = 0; ks < 4; ks++) {
        uint32_t aq[4];
        LDSM4(aq, qbase + SW128(a_row * 128 + ks * 32 + a_k16));
        uint32_t bk[2][4];
#pragma unroll
        for (int ni2 = 0; ni2 < 2; ni2++)
            LDSM4(bk[ni2], kbase + SW128((w * 32 + ni2 * 16 + b_row) * 128 + ks * 32 + b_k16));
#pragma unroll
        for (int ni = 0; ni < 4; ni++)
            mma16816(d[ni], aq, &bk[ni >> 1][(ni & 1) * 2]);
    }

    const int g  = lane >> 2;
    const int tg = lane & 3;

    // row max over this warp's 32 keys
    float m0 = -1e30f, m1 = -1e30f;
#pragma unroll
    for (int ni = 0; ni < 4; ni++) {
        m0 = fmaxf(m0, fmaxf(d[ni][0], d[ni][1]));
        m1 = fmaxf(m1, fmaxf(d[ni][2], d[ni][3]));
    }
    m0 = fmaxf(m0, __shfl_xor_sync(0xffffffffu, m0, 1));
    m0 = fmaxf(m0, __shfl_xor_sync(0xffffffffu, m0, 2));
    m1 = fmaxf(m1, __shfl_xor_sync(0xffffffffu, m1, 1));
    m1 = fmaxf(m1, __shfl_xor_sync(0xffffffffu, m1, 2));
    if (tg == 0) { S.pmax[w][g] = m0; S.pmax[w][8 + g] = m1; }
    __syncthreads();
    float gm0 = fmaxf(fmaxf(S.pmax[0][g], S.pmax[1][g]), fmaxf(S.pmax[2][g], S.pmax[3][g]));
    float gm1 = fmaxf(fmaxf(S.pmax[0][8 + g], S.pmax[1][8 + g]), fmaxf(S.pmax[2][8 + g], S.pmax[3][8 + g]));

    // weighted exp
    uint32_t mw0 = 0, mw1 = 0;
    if (!small) { mw0 = S.mask[g][w]; mw1 = S.mask[8 + g][w]; }
    const int tA = t0 + g, tB = t0 + 8 + g;
    float ws0 = 0.f, ws1 = 0.f;
#pragma unroll
    for (int ni = 0; ni < 4; ni++) {
        int colL = ni * 8 + tg * 2;
        int col  = w * 32 + colL;
        float wA0, wA1, wB0, wB1;
        if (small) {
            wA0 = (col < tA) ? 1.f : ((col == tA) ? (float)(64 - tA) : 0.f);
            wA1 = (col + 1 < tA) ? 1.f : ((col + 1 == tA) ? (float)(64 - tA) : 0.f);
            wB0 = (col < tB) ? 1.f : ((col == tB) ? (float)(64 - tB) : 0.f);
            wB1 = (col + 1 < tB) ? 1.f : ((col + 1 == tB) ? (float)(64 - tB) : 0.f);
        } else {
            wA0 = (float)((mw0 >> colL) & 1u);
            wA1 = (float)((mw0 >> (colL + 1)) & 1u);
            wB0 = (float)((mw1 >> colL) & 1u);
            wB1 = (float)((mw1 >> (colL + 1)) & 1u);
        }
        d[ni][0] = expf(d[ni][0] - gm0) * wA0;  ws0 += d[ni][0];
        d[ni][1] = expf(d[ni][1] - gm0) * wA1;  ws0 += d[ni][1];
        d[ni][2] = expf(d[ni][2] - gm1) * wB0;  ws1 += d[ni][2];
        d[ni][3] = expf(d[ni][3] - gm1) * wB1;  ws1 += d[ni][3];
    }
    ws0 += __shfl_xor_sync(0xffffffffu, ws0, 1);
    ws0 += __shfl_xor_sync(0xffffffffu, ws0, 2);
    ws1 += __shfl_xor_sync(0xffffffffu, ws1, 1);
    ws1 += __shfl_xor_sync(0xffffffffu, ws1, 2);
    if (tg == 0) { S.psum[w][g] = ws0; S.psum[w][8 + g] = ws1; }
    __syncthreads();
    float inv0 = 1.f / (S.psum[0][g] + S.psum[1][g] + S.psum[2][g] + S.psum[3][g]);
    float inv1 = 1.f / (S.psum[0][8 + g] + S.psum[1][8 + g] + S.psum[2][8 + g] + S.psum[3][8 + g]);

    // store P (fp16, SW256 rows of 256B)
#pragma unroll
    for (int ni = 0; ni < 4; ni++) {
        int col = w * 32 + ni * 8 + tg * 2;
        *reinterpret_cast<__half2*>(pc + SW256(g * 256 + col * 2)) =
            __floats2half2_rn(d[ni][0] * inv0, d[ni][1] * inv0);
        *reinterpret_cast<__half2*>(pc + SW256((8 + g) * 256 + col * 2)) =
            __floats2half2_rn(d[ni][2] * inv1, d[ni][3] * inv1);
    }
    __syncthreads();

    // ---- PV: warp w covers dims [w*16, w*16+16) ----
    float o[2][4];
#pragma unroll
    for (int i = 0; i < 2; i++)
#pragma unroll
        for (int j = 0; j < 4; j++) o[i][j] = 0.f;

    const int v_row = (lane & 7) + ((lane >> 3) & 1) * 8;
    const int v_d16 = ((lane >> 4) & 1) * 16;   // bytes within the warp's 32B dim span

#pragma unroll
    for (int ks = 0; ks < 8; ks++) {
        uint32_t ap[4];
        LDSM4(ap, pbase + SW256(a_row * 256 + ks * 32 + a_k16));
        uint32_t bv[4];
        LDSM4_T(bv, vbase + SW128((ks * 16 + v_row) * 128 + w * 32 + v_d16));
        mma16816(o[0], ap, &bv[0]);
        mma16816(o[1], ap, &bv[2]);
    }

#pragma unroll
    for (int ni = 0; ni < 2; ni++) {
        int col = w * 16 + ni * 8 + tg * 2;
        *reinterpret_cast<__half2*>(g_atq + (size_t)(t0 + g) * C_DIM + base + col) =
            __floats2half2_rn(o[ni][0], o[ni][1]);
        *reinterpret_cast<__half2*>(g_atq + (size_t)(t0 + 8 + g) * C_DIM + base + col) =
            __floats2half2_rn(o[ni][2], o[ni][3]);
    }
}

// ---------------------------------------------------------------------------
extern "C" void kernel_launch(void* const* d_in, const int* in_sizes, int n_in,
                              void* d_out, int out_size)
{
    const float* x   = (const float*)d_in[0];
    const float* Wq  = (const float*)d_in[1];
    const float* bq  = (const float*)d_in[2];
    const float* Wk  = (const float*)d_in[3];
    const float* bk  = (const float*)d_in[4];
    const float* Wv  = (const float*)d_in[5];
    const float* bv  = (const float*)d_in[6];
    const float* Wo  = (const float*)d_in[7];
    const float* bo  = (const float*)d_in[8];
    const float* Wks = (const float*)d_in[9];
    const float* bks = (const float*)d_in[10];
    float* out = (float*)d_out;

    __half *qh, *kh, *vh;
    cudaGetSymbolAddress((void**)&qh, g_qh);
    cudaGetSymbolAddress((void**)&kh, g_kh);
    cudaGetSymbolAddress((void**)&vh, g_vh);

    __half *xq, *wq, *wk, *wv, *wo, *atq;
    cudaGetSymbolAddress((void**)&xq,  g_xq);
    cudaGetSymbolAddress((void**)&wq,  g_wq);
    cudaGetSymbolAddress((void**)&wk,  g_wk);
    cudaGetSymbolAddress((void**)&wv,  g_wv);
    cudaGetSymbolAddress((void**)&wo,  g_wo);
    cudaGetSymbolAddress((void**)&atq, g_atq);

    const int gemm_smem = NSTAGE * STAGE_B;       // 98304
    const int attn_smem = (int)sizeof(AttnSmem);  // ~40KB
    static bool attr_done = false;
    if (!attr_done) {
        cudaFuncSetAttribute(gemm_qkv, cudaFuncAttributeMaxDynamicSharedMemorySize, gemm_smem);
        cudaFuncSetAttribute(gemm_tc,  cudaFuncAttributeMaxDynamicSharedMemorySize, gemm_smem);
        cudaFuncSetAttribute(attn_mma_kernel, cudaFuncAttributeMaxDynamicSharedMemorySize, attn_smem);
        attr_done = true;
    }

    prep_inputs<<<T_DIM + 4 * WBLK, 256>>>(
        (const float4*)x, (uint2*)xq, (const float4*)Wks, bks,
        (const float4*)Wq, (uint2*)wq,
        (const float4*)Wk, (uint2*)wk,
        (const float4*)Wv, (uint2*)wv,
        (const float4*)Wo, (uint2*)wo);

    gemm_qkv<<<dim3(32, 16), 256, gemm_smem>>>(
        xq,
        wq, bq, qh,
        wk, bk, kh,
        wv, bv, vh);

    prep_kernel<<<NGRP, 32>>>();

    attn_mma_kernel<<<dim3(NGRP + KSP / GQ, NHEAD), 128, attn_smem>>>();

    gemm_tc<<<dim3(8, 16), 256, gemm_smem>>>(atq, wo, bo, out);
}